// round 1
// baseline (speedup 1.0000x reference)
#include <cuda_runtime.h>
#include <cuda_bf16.h>
#include <cstdint>

// Problem constants (fixed by the reference)
#define N0 100000
#define N1 20000
#define N2 4000
#define E1 500000
#define E2 100000
#define F_IN 512
#define H 512
#define C_OUT 10

// Scratch (static device allocations are allowed)
__device__ float g_agg1[(size_t)N1 * H];   // 40 MB
__device__ float g_h   [(size_t)N1 * H];   // 40 MB
__device__ float g_agg2[(size_t)N2 * H];   // 8 MB
__device__ float g_h2  [(size_t)N2 * H];   // 8 MB
__device__ float g_tmp [(size_t)N2 * H];   // 8 MB

// ---------------------------------------------------------------------------
// Zero-fill (float4 vectorized)
// ---------------------------------------------------------------------------
__global__ void zero_f4(float4* __restrict__ p, int n4) {
    int i = blockIdx.x * blockDim.x + threadIdx.x;
    if (i < n4) p[i] = make_float4(0.f, 0.f, 0.f, 0.f);
}

// ---------------------------------------------------------------------------
// Scatter-add rows: one warp per edge; agg[dst] += x[src] (512 floats)
// ---------------------------------------------------------------------------
__global__ void scatter_add_rows(const float* __restrict__ xs,
                                 const int*   __restrict__ src,
                                 const int*   __restrict__ dst,
                                 int E, float* __restrict__ agg) {
    int edge = blockIdx.x * (blockDim.x >> 5) + (threadIdx.x >> 5);
    if (edge >= E) return;
    int lane = threadIdx.x & 31;
    const float4* xr = (const float4*)(xs + (size_t)src[edge] * 512);
    float*        ar = agg + (size_t)dst[edge] * 512;
#pragma unroll
    for (int i = 0; i < 4; ++i) {
        float4 v = xr[lane + 32 * i];
        int o = (lane + 32 * i) * 4;
        atomicAdd(ar + o + 0, v.x);
        atomicAdd(ar + o + 1, v.y);
        atomicAdd(ar + o + 2, v.z);
        atomicAdd(ar + o + 3, v.w);
    }
}

// ---------------------------------------------------------------------------
// Fused dual-source SGEMM: C = act(A1@B1 + A2@B2 + bias)
//   A1,A2: [M,K] row-major; B1,B2: [K,N] row-major; N multiple of 64, K of 8.
//   A2 == nullptr -> single GEMM.
// Tiling: BM=BN=64, BK=8, 256 threads, 4x4 per thread.
// ---------------------------------------------------------------------------
#define BM 64
#define BN 64
#define BK 8

template <bool RELU>
__global__ __launch_bounds__(256)
void gemm2_bias(const float* __restrict__ A1, const float* __restrict__ B1,
                const float* __restrict__ A2, const float* __restrict__ B2,
                const float* __restrict__ bias, float* __restrict__ Cout,
                int M, int N, int K) {
    __shared__ float As[BK][BM];
    __shared__ float Bs[BK][BN];

    const int tid = threadIdx.x;
    const int m0 = blockIdx.y * BM;
    const int n0 = blockIdx.x * BN;
    const int ty = tid >> 4;       // 0..15
    const int tx = tid & 15;       // 0..15

    float acc[4][4];
#pragma unroll
    for (int i = 0; i < 4; ++i)
#pragma unroll
        for (int j = 0; j < 4; ++j) acc[i][j] = 0.f;

#pragma unroll 1
    for (int pass = 0; pass < 2; ++pass) {
        const float* __restrict__ A = pass ? A2 : A1;
        const float* __restrict__ B = pass ? B2 : B1;
        if (A == nullptr) break;
#pragma unroll 1
        for (int k0 = 0; k0 < K; k0 += BK) {
            // A tile: 64x8 -> As[k][m]; 512 elems, 2 per thread
#pragma unroll
            for (int e = tid; e < BM * BK; e += 256) {
                int m = e >> 3, k = e & 7;
                int gm = m0 + m;
                As[k][m] = (gm < M) ? A[(size_t)gm * K + k0 + k] : 0.f;
            }
            // B tile: 8x64 -> Bs[k][n]; fully coalesced
#pragma unroll
            for (int e = tid; e < BK * BN; e += 256) {
                int k = e >> 6, n = e & 63;
                Bs[k][n] = B[(size_t)(k0 + k) * N + n0 + n];
            }
            __syncthreads();
#pragma unroll
            for (int k = 0; k < BK; ++k) {
                float4 a4 = *(const float4*)&As[k][ty * 4];
                float4 b4 = *(const float4*)&Bs[k][tx * 4];
                float av[4] = {a4.x, a4.y, a4.z, a4.w};
                float bv[4] = {b4.x, b4.y, b4.z, b4.w};
#pragma unroll
                for (int i = 0; i < 4; ++i)
#pragma unroll
                    for (int j = 0; j < 4; ++j) acc[i][j] += av[i] * bv[j];
            }
            __syncthreads();
        }
    }

    // Epilogue: bias (+ optional relu)
#pragma unroll
    for (int i = 0; i < 4; ++i) {
        int gm = m0 + ty * 4 + i;
        if (gm >= M) continue;
#pragma unroll
        for (int j = 0; j < 4; ++j) {
            int gn = n0 + tx * 4 + j;
            float v = acc[i][j] + bias[gn];
            if (RELU) v = fmaxf(v, 0.f);
            Cout[(size_t)gm * N + gn] = v;
        }
    }
}

// ---------------------------------------------------------------------------
// Head: out[r, :10] = tmp[r, :512] @ Whead[512,10] + bhead  (one warp / row)
// ---------------------------------------------------------------------------
__global__ void head_kernel(const float* __restrict__ tmp,
                            const float* __restrict__ Whead,
                            const float* __restrict__ bhead,
                            float* __restrict__ out) {
    int r = blockIdx.x;
    int lane = threadIdx.x;
    float acc[C_OUT];
#pragma unroll
    for (int c = 0; c < C_OUT; ++c) acc[c] = 0.f;
    const float* trow = tmp + (size_t)r * H;
    for (int k = lane; k < H; k += 32) {
        float t = trow[k];
        const float* w = Whead + (size_t)k * C_OUT;
#pragma unroll
        for (int c = 0; c < C_OUT; ++c) acc[c] += t * w[c];
    }
#pragma unroll
    for (int off = 16; off > 0; off >>= 1)
#pragma unroll
        for (int c = 0; c < C_OUT; ++c)
            acc[c] += __shfl_down_sync(0xFFFFFFFFu, acc[c], off);
    if (lane == 0) {
#pragma unroll
        for (int c = 0; c < C_OUT; ++c) out[(size_t)r * C_OUT + c] = acc[c] + bhead[c];
    }
}

// ---------------------------------------------------------------------------
// Launch
// ---------------------------------------------------------------------------
extern "C" void kernel_launch(void* const* d_in, const int* in_sizes, int n_in,
                              void* d_out, int out_size) {
    const float* x     = (const float*)d_in[0];
    const int*   src1  = (const int*)  d_in[1];
    const int*   dst1  = (const int*)  d_in[2];
    const int*   src2  = (const int*)  d_in[3];
    const int*   dst2  = (const int*)  d_in[4];
    const float* Wrel1 = (const float*)d_in[5];
    const float* brel1 = (const float*)d_in[6];
    const float* Wroot1= (const float*)d_in[7];
    const float* Wrel2 = (const float*)d_in[8];
    const float* brel2 = (const float*)d_in[9];
    const float* Wroot2= (const float*)d_in[10];
    const float* Wlin  = (const float*)d_in[11];
    const float* blin  = (const float*)d_in[12];
    const float* Whead = (const float*)d_in[13];
    const float* bhead = (const float*)d_in[14];
    float* out = (float*)d_out;

    float *agg1, *h, *agg2, *h2, *tmp;
    cudaGetSymbolAddress((void**)&agg1, g_agg1);
    cudaGetSymbolAddress((void**)&h,    g_h);
    cudaGetSymbolAddress((void**)&agg2, g_agg2);
    cudaGetSymbolAddress((void**)&h2,   g_h2);
    cudaGetSymbolAddress((void**)&tmp,  g_tmp);

    // ---- Layer 1 ----
    {
        int n4 = (N1 * H) / 4;
        zero_f4<<<(n4 + 255) / 256, 256>>>((float4*)agg1, n4);
    }
    {
        int warps_per_block = 8;
        int blocks = (E1 + warps_per_block - 1) / warps_per_block;
        scatter_add_rows<<<blocks, 256>>>(x, src1, dst1, E1, agg1);
    }
    {
        dim3 grid(H / BN, (N1 + BM - 1) / BM);
        gemm2_bias<true><<<grid, 256>>>(agg1, Wrel1, x, Wroot1, brel1, h,
                                        N1, H, F_IN);
    }

    // ---- Layer 2 ----
    {
        int n4 = (N2 * H) / 4;
        zero_f4<<<(n4 + 255) / 256, 256>>>((float4*)agg2, n4);
    }
    {
        int warps_per_block = 8;
        int blocks = (E2 + warps_per_block - 1) / warps_per_block;
        scatter_add_rows<<<blocks, 256>>>(h, src2, dst2, E2, agg2);
    }
    {
        dim3 grid(H / BN, (N2 + BM - 1) / BM);
        gemm2_bias<false><<<grid, 256>>>(agg2, Wrel2, h, Wroot2, brel2, h2,
                                         N2, H, H);
    }

    // ---- Dense head ----
    {
        dim3 grid(H / BN, (N2 + BM - 1) / BM);
        gemm2_bias<false><<<grid, 256>>>(h2, Wlin, nullptr, nullptr, blin, tmp,
                                         N2, H, H);
    }
    head_kernel<<<N2, 32>>>(tmp, Whead, bhead, out);

    (void)in_sizes; (void)n_in; (void)out_size;
}

// round 3
// speedup vs baseline: 1.4913x; 1.4913x over previous
#include <cuda_runtime.h>
#include <cuda_bf16.h>
#include <cstdint>

#define N0 100000
#define N1 20000
#define N2 4000
#define E1 500000
#define E2 100000
#define FH 512
#define C_OUT 10

// ---------------- scratch ---------------------------------------------------
__device__ float g_agg1[(size_t)N1 * FH];
__device__ float g_h   [(size_t)N1 * FH];
__device__ float g_agg2[(size_t)N2 * FH];
__device__ float g_h2  [(size_t)N2 * FH];

__device__ __nv_bfloat16 g_A1h[(size_t)N1 * FH], g_A1l[(size_t)N1 * FH];
__device__ __nv_bfloat16 g_A2h[(size_t)N1 * FH], g_A2l[(size_t)N1 * FH];
__device__ __nv_bfloat16 g_Hh [(size_t)N1 * FH], g_Hl [(size_t)N1 * FH];
__device__ __nv_bfloat16 g_G2h[(size_t)N2 * FH], g_G2l[(size_t)N2 * FH];
__device__ __nv_bfloat16 g_Wt[8][(size_t)FH * FH];   // 0/1 rel1 h/l, 2/3 root1, 4/5 rel2, 6/7 root2
__device__ float g_Wcomb[(size_t)FH * C_OUT];
__device__ float g_bcomb[C_OUT];

// ---------------- helpers ---------------------------------------------------
__device__ __forceinline__ uint32_t smem_u32(const void* p) {
    uint32_t a;
    asm("{ .reg .u64 t; cvta.to.shared.u64 t, %1; cvt.u32.u64 %0, t; }"
        : "=r"(a) : "l"(p));
    return a;
}
__device__ __forceinline__ void cp_async16(uint32_t dst, const void* src, int sz) {
    asm volatile("cp.async.cg.shared.global [%0], [%1], 16, %2;"
                 :: "r"(dst), "l"(src), "r"(sz) : "memory");
}
__device__ __forceinline__ void cp_commit() {
    asm volatile("cp.async.commit_group;" ::: "memory");
}
__device__ __forceinline__ void cp_wait0() {
    asm volatile("cp.async.wait_group 0;" ::: "memory");
}
__device__ __forceinline__ void split1(float v, __nv_bfloat16& h, __nv_bfloat16& l) {
    h = __float2bfloat16(v);
    l = __float2bfloat16(v - __bfloat162float(h));
}
__device__ __forceinline__ void mma16816(float* c, const uint32_t* a, const uint32_t* b) {
    asm("mma.sync.aligned.m16n8k16.row.col.f32.bf16.bf16.f32 "
        "{%0,%1,%2,%3}, {%4,%5,%6,%7}, {%8,%9}, {%0,%1,%2,%3};"
        : "+f"(c[0]), "+f"(c[1]), "+f"(c[2]), "+f"(c[3])
        : "r"(a[0]), "r"(a[1]), "r"(a[2]), "r"(a[3]), "r"(b[0]), "r"(b[1]));
}

// ---------------- zero / scatter --------------------------------------------
__global__ void zero_f4(float4* __restrict__ p, int n4) {
    int i = blockIdx.x * blockDim.x + threadIdx.x;
    if (i < n4) p[i] = make_float4(0.f, 0.f, 0.f, 0.f);
}

__global__ void scatter_add_rows(const float* __restrict__ xs,
                                 const int* __restrict__ src,
                                 const int* __restrict__ dst,
                                 int E, float* __restrict__ agg) {
    int edge = blockIdx.x * (blockDim.x >> 5) + (threadIdx.x >> 5);
    if (edge >= E) return;
    int lane = threadIdx.x & 31;
    const float4* xr = (const float4*)(xs + (size_t)src[edge] * FH);
    float*        ar = agg + (size_t)dst[edge] * FH;
#pragma unroll
    for (int i = 0; i < 4; ++i) {
        float4 v = xr[lane + 32 * i];
        int o = (lane + 32 * i) * 4;
        atomicAdd(ar + o + 0, v.x);
        atomicAdd(ar + o + 1, v.y);
        atomicAdd(ar + o + 2, v.z);
        atomicAdd(ar + o + 3, v.w);
    }
}

// ---------------- fp32 -> bf16 hi/lo split ----------------------------------
__global__ void split_f32(const float4* __restrict__ in,
                          uint2* __restrict__ hi, uint2* __restrict__ lo, int n4) {
    int i = blockIdx.x * blockDim.x + threadIdx.x;
    if (i >= n4) return;
    float4 v = in[i];
    __nv_bfloat16 h0, h1, h2, h3, l0, l1, l2, l3;
    split1(v.x, h0, l0); split1(v.y, h1, l1);
    split1(v.z, h2, l2); split1(v.w, h3, l3);
    uint2 H, L;
    H.x = (uint32_t)__bfloat16_as_ushort(h0) | ((uint32_t)__bfloat16_as_ushort(h1) << 16);
    H.y = (uint32_t)__bfloat16_as_ushort(h2) | ((uint32_t)__bfloat16_as_ushort(h3) << 16);
    L.x = (uint32_t)__bfloat16_as_ushort(l0) | ((uint32_t)__bfloat16_as_ushort(l1) << 16);
    L.y = (uint32_t)__bfloat16_as_ushort(l2) | ((uint32_t)__bfloat16_as_ushort(l3) << 16);
    hi[i] = H; lo[i] = L;
}

// ---------------- weight transpose + split ----------------------------------
__global__ void transpose_split(const float* __restrict__ W,
                                __nv_bfloat16* __restrict__ Bh,
                                __nv_bfloat16* __restrict__ Bl) {
    __shared__ float t[32][33];
    int n0 = blockIdx.x * 32, k0 = blockIdx.y * 32;
    int tx = threadIdx.x, ty = threadIdx.y;
    for (int yy = ty; yy < 32; yy += 8)
        t[yy][tx] = W[(size_t)(k0 + yy) * FH + n0 + tx];
    __syncthreads();
    for (int yy = ty; yy < 32; yy += 8) {
        float v = t[tx][yy];
        size_t o = (size_t)(n0 + yy) * FH + k0 + tx;
        __nv_bfloat16 h, l;
        split1(v, h, l);
        Bh[o] = h; Bl[o] = l;
    }
}

// ---------------- head fold + head ------------------------------------------
__global__ void wcomb_kernel(const float* __restrict__ Wlin,
                             const float* __restrict__ Whead,
                             const float* __restrict__ blin,
                             const float* __restrict__ bhead,
                             float* __restrict__ Wcomb, float* __restrict__ bcomb) {
    int k = blockIdx.x;
    int lane = threadIdx.x;
    const float* rowv = (k < FH) ? (Wlin + (size_t)k * FH) : blin;
    float acc[C_OUT];
#pragma unroll
    for (int c = 0; c < C_OUT; ++c) acc[c] = 0.f;
    for (int j = lane; j < FH; j += 32) {
        float v = rowv[j];
        const float* w = Whead + (size_t)j * C_OUT;
#pragma unroll
        for (int c = 0; c < C_OUT; ++c) acc[c] += v * w[c];
    }
#pragma unroll
    for (int off = 16; off > 0; off >>= 1)
#pragma unroll
        for (int c = 0; c < C_OUT; ++c)
            acc[c] += __shfl_down_sync(0xFFFFFFFFu, acc[c], off);
    if (lane == 0) {
        if (k < FH) {
#pragma unroll
            for (int c = 0; c < C_OUT; ++c) Wcomb[(size_t)k * C_OUT + c] = acc[c];
        } else {
#pragma unroll
            for (int c = 0; c < C_OUT; ++c) bcomb[c] = acc[c] + bhead[c];
        }
    }
}

__global__ void head_kernel(const float* __restrict__ h2,
                            const float* __restrict__ Wcomb,
                            const float* __restrict__ bcomb,
                            float* __restrict__ out) {
    int r = blockIdx.x;
    int lane = threadIdx.x;
    float acc[C_OUT];
#pragma unroll
    for (int c = 0; c < C_OUT; ++c) acc[c] = 0.f;
    const float* trow = h2 + (size_t)r * FH;
    for (int k = lane; k < FH; k += 32) {
        float t = trow[k];
        const float* w = Wcomb + (size_t)k * C_OUT;
#pragma unroll
        for (int c = 0; c < C_OUT; ++c) acc[c] += t * w[c];
    }
#pragma unroll
    for (int off = 16; off > 0; off >>= 1)
#pragma unroll
        for (int c = 0; c < C_OUT; ++c)
            acc[c] += __shfl_down_sync(0xFFFFFFFFu, acc[c], off);
    if (lane == 0) {
#pragma unroll
        for (int c = 0; c < C_OUT; ++c) out[(size_t)r * C_OUT + c] = acc[c] + bcomb[c];
    }
}

// ---------------- HMMA bf16-split dual-source GEMM --------------------------
// C[M,512] = relu?( A0@W0 + A1@W1 + bias ), A in hi/lo bf16, W transposed hi/lo.
// CTA 128x128, BK=32, 8 warps (warp tile 32x64), cp.async double buffer.
#define SA 40   // smem row stride (bf16 elems): 80B, conflict-free & 16B aligned

template <bool RELU, bool SPLIT>
__global__ __launch_bounds__(256) void gemm_mma(
    const __nv_bfloat16* __restrict__ A0h, const __nv_bfloat16* __restrict__ A0l,
    const __nv_bfloat16* __restrict__ A1h, const __nv_bfloat16* __restrict__ A1l,
    const __nv_bfloat16* __restrict__ B0h, const __nv_bfloat16* __restrict__ B0l,
    const __nv_bfloat16* __restrict__ B1h, const __nv_bfloat16* __restrict__ B1l,
    const float* __restrict__ bias, float* __restrict__ Cout,
    __nv_bfloat16* __restrict__ Ch, __nv_bfloat16* __restrict__ Cl, int M) {
    __shared__ __nv_bfloat16 As[2][128][SA];
    __shared__ __nv_bfloat16 Bs[2][128][SA];

    const int tid = threadIdx.x;
    const int lane = tid & 31;
    const int wid = tid >> 5;
    const int wm = wid & 3;          // 4 warps in M
    const int wn = wid >> 2;         // 2 warps in N
    const int m0 = blockIdx.y * 128;
    const int n0 = blockIdx.x * 128;

    const __nv_bfloat16* Ap[6] = {A0h, A0l, A0h, A1h, A1l, A1h};
    const __nv_bfloat16* Bp[6] = {B0h, B0h, B0l, B1h, B1h, B1l};
    constexpr int NCH = 96;          // 6 passes x 16 k-chunks of 32

    float acc[2][8][4];
#pragma unroll
    for (int i = 0; i < 2; ++i)
#pragma unroll
        for (int j = 0; j < 8; ++j)
#pragma unroll
            for (int q = 0; q < 4; ++q) acc[i][j][q] = 0.f;

    // per-thread load coords (2 uint4 per tile per thread)
    const int r0 = tid >> 2;             // 0..63
    const int c8 = (tid & 3) * 8;        // 0,8,16,24

    auto issue = [&](int buf, int chunk) {
        const int sel = chunk >> 4;
        const int k0 = (chunk & 15) * 32;
        const __nv_bfloat16* A = Ap[sel];
        const __nv_bfloat16* B = Bp[sel];
#pragma unroll
        for (int i = 0; i < 2; ++i) {
            int row = r0 + i * 64;
            int gm = m0 + row;
            cp_async16(smem_u32(&As[buf][row][c8]),
                       A + (size_t)gm * FH + k0 + c8, gm < M ? 16 : 0);
            cp_async16(smem_u32(&Bs[buf][row][c8]),
                       B + (size_t)(n0 + row) * FH + k0 + c8, 16);
        }
        cp_commit();
    };

    issue(0, 0);

    const int fr = lane >> 2;            // fragment row 0..7
    const int fc = (lane & 3) * 2;       // fragment col pair

#pragma unroll 1
    for (int c = 0; c < NCH; ++c) {
        cp_wait0();
        __syncthreads();
        if (c + 1 < NCH) issue((c + 1) & 1, c + 1);
        const int buf = c & 1;
#pragma unroll
        for (int kk = 0; kk < 32; kk += 16) {
            uint32_t a[2][4];
#pragma unroll
            for (int mi = 0; mi < 2; ++mi) {
                int rb = wm * 32 + mi * 16;
                a[mi][0] = *(const uint32_t*)&As[buf][rb + fr][kk + fc];
                a[mi][1] = *(const uint32_t*)&As[buf][rb + fr + 8][kk + fc];
                a[mi][2] = *(const uint32_t*)&As[buf][rb + fr][kk + fc + 8];
                a[mi][3] = *(const uint32_t*)&As[buf][rb + fr + 8][kk + fc + 8];
            }
#pragma unroll
            for (int ni = 0; ni < 8; ++ni) {
                int nb = wn * 64 + ni * 8;
                uint32_t b[2];
                b[0] = *(const uint32_t*)&Bs[buf][nb + fr][kk + fc];
                b[1] = *(const uint32_t*)&Bs[buf][nb + fr][kk + fc + 8];
                mma16816(acc[0][ni], a[0], b);
                mma16816(acc[1][ni], a[1], b);
            }
        }
        __syncthreads();
    }

    // -------- epilogue --------
#pragma unroll
    for (int mi = 0; mi < 2; ++mi) {
#pragma unroll
        for (int half = 0; half < 2; ++half) {
            int row = m0 + wm * 32 + mi * 16 + fr + half * 8;
            if (row >= M) continue;
#pragma unroll
            for (int ni = 0; ni < 8; ++ni) {
                int col = n0 + wn * 64 + ni * 8 + fc;
                float v0 = acc[mi][ni][half * 2 + 0] + bias[col];
                float v1 = acc[mi][ni][half * 2 + 1] + bias[col + 1];
                if (RELU) { v0 = fmaxf(v0, 0.f); v1 = fmaxf(v1, 0.f); }
                float2* dst = (float2*)(Cout + (size_t)row * FH + col);
                *dst = make_float2(v0, v1);
                if (SPLIT) {
                    __nv_bfloat16 h0, h1, l0, l1;
                    split1(v0, h0, l0); split1(v1, h1, l1);
                    *(uint32_t*)(Ch + (size_t)row * FH + col) =
                        (uint32_t)__bfloat16_as_ushort(h0) |
                        ((uint32_t)__bfloat16_as_ushort(h1) << 16);
                    *(uint32_t*)(Cl + (size_t)row * FH + col) =
                        (uint32_t)__bfloat16_as_ushort(l0) |
                        ((uint32_t)__bfloat16_as_ushort(l1) << 16);
                }
            }
        }
    }
}

// ---------------------------------------------------------------------------
extern "C" void kernel_launch(void* const* d_in, const int* in_sizes, int n_in,
                              void* d_out, int out_size) {
    const float* x     = (const float*)d_in[0];
    const int*   src1  = (const int*)  d_in[1];
    const int*   dst1  = (const int*)  d_in[2];
    const int*   src2  = (const int*)  d_in[3];
    const int*   dst2  = (const int*)  d_in[4];
    const float* Wrel1 = (const float*)d_in[5];
    const float* brel1 = (const float*)d_in[6];
    const float* Wroot1= (const float*)d_in[7];
    const float* Wrel2 = (const float*)d_in[8];
    const float* brel2 = (const float*)d_in[9];
    const float* Wroot2= (const float*)d_in[10];
    const float* Wlin  = (const float*)d_in[11];
    const float* blin  = (const float*)d_in[12];
    const float* Whead = (const float*)d_in[13];
    const float* bhead = (const float*)d_in[14];
    float* out = (float*)d_out;

    float *agg1, *h, *agg2, *h2, *Wcomb, *bcomb;
    __nv_bfloat16 *A1h, *A1l, *A2h, *A2l, *Hh, *Hl, *G2h, *G2l, *Wt;
    cudaGetSymbolAddress((void**)&agg1, g_agg1);
    cudaGetSymbolAddress((void**)&h,    g_h);
    cudaGetSymbolAddress((void**)&agg2, g_agg2);
    cudaGetSymbolAddress((void**)&h2,   g_h2);
    cudaGetSymbolAddress((void**)&A1h,  g_A1h);
    cudaGetSymbolAddress((void**)&A1l,  g_A1l);
    cudaGetSymbolAddress((void**)&A2h,  g_A2h);
    cudaGetSymbolAddress((void**)&A2l,  g_A2l);
    cudaGetSymbolAddress((void**)&Hh,   g_Hh);
    cudaGetSymbolAddress((void**)&Hl,   g_Hl);
    cudaGetSymbolAddress((void**)&G2h,  g_G2h);
    cudaGetSymbolAddress((void**)&G2l,  g_G2l);
    cudaGetSymbolAddress((void**)&Wt,   g_Wt);
    cudaGetSymbolAddress((void**)&Wcomb, g_Wcomb);
    cudaGetSymbolAddress((void**)&bcomb, g_bcomb);
    __nv_bfloat16* WtP[8];
    for (int i = 0; i < 8; ++i) WtP[i] = Wt + (size_t)i * FH * FH;

    // zero agg buffers
    {
        int n4 = (N1 * FH) / 4;
        zero_f4<<<(n4 + 255) / 256, 256>>>((float4*)agg1, n4);
        int m4 = (N2 * FH) / 4;
        zero_f4<<<(m4 + 255) / 256, 256>>>((float4*)agg2, m4);
    }
    // scatter layer 1
    scatter_add_rows<<<(E1 + 7) / 8, 256>>>(x, src1, dst1, E1, agg1);
    // splits for layer-1 GEMM
    {
        int n4 = (N1 * FH) / 4;
        split_f32<<<(n4 + 255) / 256, 256>>>((const float4*)agg1, (uint2*)A1h, (uint2*)A1l, n4);
        split_f32<<<(n4 + 255) / 256, 256>>>((const float4*)x,    (uint2*)A2h, (uint2*)A2l, n4);
    }
    // weight transposes + head fold
    {
        dim3 g(16, 16), b(32, 8);
        transpose_split<<<g, b>>>(Wrel1,  WtP[0], WtP[1]);
        transpose_split<<<g, b>>>(Wroot1, WtP[2], WtP[3]);
        transpose_split<<<g, b>>>(Wrel2,  WtP[4], WtP[5]);
        transpose_split<<<g, b>>>(Wroot2, WtP[6], WtP[7]);
        wcomb_kernel<<<FH + 1, 32>>>(Wlin, Whead, blin, bhead, Wcomb, bcomb);
    }
    // layer 1: h = relu(agg1@Wrel1 + x@Wroot1 + brel1), emit bf16 split of h
    {
        dim3 grid(FH / 128, (N1 + 127) / 128);
        gemm_mma<true, true><<<grid, 256>>>(
            A1h, A1l, A2h, A2l, WtP[0], WtP[1], WtP[2], WtP[3],
            brel1, h, Hh, Hl, N1);
    }
    // scatter layer 2 + split
    scatter_add_rows<<<(E2 + 7) / 8, 256>>>(h, src2, dst2, E2, agg2);
    {
        int n4 = (N2 * FH) / 4;
        split_f32<<<(n4 + 255) / 256, 256>>>((const float4*)agg2, (uint2*)G2h, (uint2*)G2l, n4);
    }
    // layer 2: h2 = agg2@Wrel2 + h[:N2]@Wroot2 + brel2
    {
        dim3 grid(FH / 128, (N2 + 127) / 128);
        gemm_mma<false, false><<<grid, 256>>>(
            G2h, G2l, Hh, Hl, WtP[4], WtP[5], WtP[6], WtP[7],
            brel2, h2, nullptr, nullptr, N2);
    }
    // head
    head_kernel<<<N2, 32>>>(h2, Wcomb, bcomb, out);

    (void)in_sizes; (void)n_in; (void)out_size;
}

// round 4
// speedup vs baseline: 2.7262x; 1.8281x over previous
#include <cuda_runtime.h>
#include <cuda_bf16.h>
#include <cstdint>

#define N0 100000
#define N1 20000
#define N2 4000
#define E1 500000
#define E2 100000
#define FH 512
#define C_OUT 10

// ---------------- scratch ---------------------------------------------------
__device__ float g_h [(size_t)N1 * FH];
__device__ float g_h2[(size_t)N2 * FH];

__device__ __nv_bfloat16 g_A1h[(size_t)N1 * FH], g_A1l[(size_t)N1 * FH]; // agg1 split
__device__ __nv_bfloat16 g_A2h[(size_t)N1 * FH], g_A2l[(size_t)N1 * FH]; // x[:N1] split
__device__ __nv_bfloat16 g_Hh [(size_t)N1 * FH], g_Hl [(size_t)N1 * FH]; // h split
__device__ __nv_bfloat16 g_G2h[(size_t)N2 * FH], g_G2l[(size_t)N2 * FH]; // agg2 split
__device__ __nv_bfloat16 g_Wt[8][(size_t)FH * FH];
__device__ float g_Wcomb[(size_t)FH * C_OUT];
__device__ float g_bcomb[C_OUT];

// CSR scratch
__device__ int g_cnt1[N1], g_rp1[N1 + 1], g_pos1[N1], g_eidx1[E1];
__device__ int g_cnt2[N2], g_rp2[N2 + 1], g_pos2[N2], g_eidx2[E2];

// ---------------- helpers ---------------------------------------------------
__device__ __forceinline__ uint32_t smem_u32(const void* p) {
    uint32_t a;
    asm("{ .reg .u64 t; cvta.to.shared.u64 t, %1; cvt.u32.u64 %0, t; }"
        : "=r"(a) : "l"(p));
    return a;
}
__device__ __forceinline__ void cp_async16(uint32_t dst, const void* src, int sz) {
    asm volatile("cp.async.cg.shared.global [%0], [%1], 16, %2;"
                 :: "r"(dst), "l"(src), "r"(sz) : "memory");
}
__device__ __forceinline__ void cp_commit() {
    asm volatile("cp.async.commit_group;" ::: "memory");
}
__device__ __forceinline__ void cp_wait0() {
    asm volatile("cp.async.wait_group 0;" ::: "memory");
}
__device__ __forceinline__ void split1(float v, __nv_bfloat16& h, __nv_bfloat16& l) {
    h = __float2bfloat16(v);
    l = __float2bfloat16(v - __bfloat162float(h));
}
__device__ __forceinline__ uint32_t pack2(__nv_bfloat16 a, __nv_bfloat16 b) {
    return (uint32_t)__bfloat16_as_ushort(a) | ((uint32_t)__bfloat16_as_ushort(b) << 16);
}
__device__ __forceinline__ void mma16816(float* c, const uint32_t* a, const uint32_t* b) {
    asm("mma.sync.aligned.m16n8k16.row.col.f32.bf16.bf16.f32 "
        "{%0,%1,%2,%3}, {%4,%5,%6,%7}, {%8,%9}, {%0,%1,%2,%3};"
        : "+f"(c[0]), "+f"(c[1]), "+f"(c[2]), "+f"(c[3])
        : "r"(a[0]), "r"(a[1]), "r"(a[2]), "r"(a[3]), "r"(b[0]), "r"(b[1]));
}

// ---------------- CSR build --------------------------------------------------
__global__ void zero_i(int* __restrict__ p, int n) {
    int i = blockIdx.x * blockDim.x + threadIdx.x;
    if (i < n) p[i] = 0;
}
__global__ void hist_k(const int* __restrict__ dst, int E, int* __restrict__ cnt) {
    int e = blockIdx.x * blockDim.x + threadIdx.x;
    if (e < E) atomicAdd(&cnt[dst[e]], 1);
}
// single-block exclusive scan (n <= 1024*20)
__global__ __launch_bounds__(1024) void scan_k(const int* __restrict__ cnt, int n,
                                               int* __restrict__ rowptr,
                                               int* __restrict__ pos) {
    __shared__ int ts[1024];
    const int t = threadIdx.x;
    const int C = (n + 1023) >> 10;      // <= 20
    int local[20];
    int s = 0;
    for (int j = 0; j < C; ++j) {
        int idx = t * C + j;
        int v = (idx < n) ? cnt[idx] : 0;
        local[j] = s; s += v;
    }
    ts[t] = s;
    __syncthreads();
    for (int off = 1; off < 1024; off <<= 1) {
        int v = (t >= off) ? ts[t - off] : 0;
        __syncthreads();
        ts[t] += v;
        __syncthreads();
    }
    int base = (t > 0) ? ts[t - 1] : 0;
    for (int j = 0; j < C; ++j) {
        int idx = t * C + j;
        if (idx < n) { int r = base + local[j]; rowptr[idx] = r; pos[idx] = r; }
    }
    if (t == 1023) rowptr[n] = ts[1023];
}
__global__ void fill_k(const int* __restrict__ dst, int E,
                       int* __restrict__ pos, int* __restrict__ eidx) {
    int e = blockIdx.x * blockDim.x + threadIdx.x;
    if (e < E) {
        int p = atomicAdd(&pos[dst[e]], 1);
        eidx[p] = e;
    }
}

// ---------------- gather-aggregate + bf16 split (one warp per row) -----------
__global__ void gather_split(const float* __restrict__ X,
                             const int* __restrict__ src,
                             const int* __restrict__ eidx,
                             const int* __restrict__ rowptr, int nrows,
                             __nv_bfloat16* __restrict__ Ah,
                             __nv_bfloat16* __restrict__ Al) {
    int row = blockIdx.x * (blockDim.x >> 5) + (threadIdx.x >> 5);
    if (row >= nrows) return;
    const int lane = threadIdx.x & 31;
    const int beg = rowptr[row], end = rowptr[row + 1];
    float4 a0 = make_float4(0.f, 0.f, 0.f, 0.f), a1 = a0, a2 = a0, a3 = a0;
    for (int i = beg; i < end; ++i) {
        const float4* xr = (const float4*)(X + (size_t)__ldg(&src[__ldg(&eidx[i])]) * FH);
        float4 v0 = xr[lane], v1 = xr[lane + 32], v2 = xr[lane + 64], v3 = xr[lane + 96];
        a0.x += v0.x; a0.y += v0.y; a0.z += v0.z; a0.w += v0.w;
        a1.x += v1.x; a1.y += v1.y; a1.z += v1.z; a1.w += v1.w;
        a2.x += v2.x; a2.y += v2.y; a2.z += v2.z; a2.w += v2.w;
        a3.x += v3.x; a3.y += v3.y; a3.z += v3.z; a3.w += v3.w;
    }
    float4 acc[4] = {a0, a1, a2, a3};
#pragma unroll
    for (int q = 0; q < 4; ++q) {
        __nv_bfloat16 h0, h1, h2, h3, l0, l1, l2, l3;
        split1(acc[q].x, h0, l0); split1(acc[q].y, h1, l1);
        split1(acc[q].z, h2, l2); split1(acc[q].w, h3, l3);
        size_t o = (size_t)row * FH + 4 * (lane + 32 * q);
        *(uint2*)(Ah + o) = make_uint2(pack2(h0, h1), pack2(h2, h3));
        *(uint2*)(Al + o) = make_uint2(pack2(l0, l1), pack2(l2, l3));
    }
}

// ---------------- fp32 -> bf16 hi/lo split ----------------------------------
__global__ void split_f32(const float4* __restrict__ in,
                          uint2* __restrict__ hi, uint2* __restrict__ lo, int n4) {
    int i = blockIdx.x * blockDim.x + threadIdx.x;
    if (i >= n4) return;
    float4 v = in[i];
    __nv_bfloat16 h0, h1, h2, h3, l0, l1, l2, l3;
    split1(v.x, h0, l0); split1(v.y, h1, l1);
    split1(v.z, h2, l2); split1(v.w, h3, l3);
    hi[i] = make_uint2(pack2(h0, h1), pack2(h2, h3));
    lo[i] = make_uint2(pack2(l0, l1), pack2(l2, l3));
}

// ---------------- weight transpose + split ----------------------------------
__global__ void transpose_split(const float* __restrict__ W,
                                __nv_bfloat16* __restrict__ Bh,
                                __nv_bfloat16* __restrict__ Bl) {
    __shared__ float t[32][33];
    int n0 = blockIdx.x * 32, k0 = blockIdx.y * 32;
    int tx = threadIdx.x, ty = threadIdx.y;
    for (int yy = ty; yy < 32; yy += 8)
        t[yy][tx] = W[(size_t)(k0 + yy) * FH + n0 + tx];
    __syncthreads();
    for (int yy = ty; yy < 32; yy += 8) {
        float v = t[tx][yy];
        size_t o = (size_t)(n0 + yy) * FH + k0 + tx;
        __nv_bfloat16 h, l;
        split1(v, h, l);
        Bh[o] = h; Bl[o] = l;
    }
}

// ---------------- head fold + head ------------------------------------------
__global__ void wcomb_kernel(const float* __restrict__ Wlin,
                             const float* __restrict__ Whead,
                             const float* __restrict__ blin,
                             const float* __restrict__ bhead,
                             float* __restrict__ Wcomb, float* __restrict__ bcomb) {
    int k = blockIdx.x;
    int lane = threadIdx.x;
    const float* rowv = (k < FH) ? (Wlin + (size_t)k * FH) : blin;
    float acc[C_OUT];
#pragma unroll
    for (int c = 0; c < C_OUT; ++c) acc[c] = 0.f;
    for (int j = lane; j < FH; j += 32) {
        float v = rowv[j];
        const float* w = Whead + (size_t)j * C_OUT;
#pragma unroll
        for (int c = 0; c < C_OUT; ++c) acc[c] += v * w[c];
    }
#pragma unroll
    for (int off = 16; off > 0; off >>= 1)
#pragma unroll
        for (int c = 0; c < C_OUT; ++c)
            acc[c] += __shfl_down_sync(0xFFFFFFFFu, acc[c], off);
    if (lane == 0) {
        if (k < FH) {
#pragma unroll
            for (int c = 0; c < C_OUT; ++c) Wcomb[(size_t)k * C_OUT + c] = acc[c];
        } else {
#pragma unroll
            for (int c = 0; c < C_OUT; ++c) bcomb[c] = acc[c] + bhead[c];
        }
    }
}

__global__ void head_kernel(const float* __restrict__ h2,
                            const float* __restrict__ Wcomb,
                            const float* __restrict__ bcomb,
                            float* __restrict__ out) {
    int r = blockIdx.x;
    int lane = threadIdx.x;
    float acc[C_OUT];
#pragma unroll
    for (int c = 0; c < C_OUT; ++c) acc[c] = 0.f;
    const float* trow = h2 + (size_t)r * FH;
    for (int k = lane; k < FH; k += 32) {
        float t = trow[k];
        const float* w = Wcomb + (size_t)k * C_OUT;
#pragma unroll
        for (int c = 0; c < C_OUT; ++c) acc[c] += t * w[c];
    }
#pragma unroll
    for (int off = 16; off > 0; off >>= 1)
#pragma unroll
        for (int c = 0; c < C_OUT; ++c)
            acc[c] += __shfl_down_sync(0xFFFFFFFFu, acc[c], off);
    if (lane == 0) {
#pragma unroll
        for (int c = 0; c < C_OUT; ++c) out[(size_t)r * C_OUT + c] = acc[c] + bcomb[c];
    }
}

// ---------------- HMMA bf16-split dual-source GEMM --------------------------
#define SA 40

template <bool RELU, bool SPLIT>
__global__ __launch_bounds__(256) void gemm_mma(
    const __nv_bfloat16* __restrict__ A0h, const __nv_bfloat16* __restrict__ A0l,
    const __nv_bfloat16* __restrict__ A1h, const __nv_bfloat16* __restrict__ A1l,
    const __nv_bfloat16* __restrict__ B0h, const __nv_bfloat16* __restrict__ B0l,
    const __nv_bfloat16* __restrict__ B1h, const __nv_bfloat16* __restrict__ B1l,
    const float* __restrict__ bias, float* __restrict__ Cout,
    __nv_bfloat16* __restrict__ Ch, __nv_bfloat16* __restrict__ Cl, int M) {
    __shared__ __nv_bfloat16 As[2][128][SA];
    __shared__ __nv_bfloat16 Bs[2][128][SA];

    const int tid = threadIdx.x;
    const int lane = tid & 31;
    const int wid = tid >> 5;
    const int wm = wid & 3;
    const int wn = wid >> 2;
    const int m0 = blockIdx.y * 128;
    const int n0 = blockIdx.x * 128;

    const __nv_bfloat16* Ap[6] = {A0h, A0l, A0h, A1h, A1l, A1h};
    const __nv_bfloat16* Bp[6] = {B0h, B0h, B0l, B1h, B1h, B1l};
    constexpr int NCH = 96;

    float acc[2][8][4];
#pragma unroll
    for (int i = 0; i < 2; ++i)
#pragma unroll
        for (int j = 0; j < 8; ++j)
#pragma unroll
            for (int q = 0; q < 4; ++q) acc[i][j][q] = 0.f;

    const int r0 = tid >> 2;
    const int c8 = (tid & 3) * 8;

    auto issue = [&](int buf, int chunk) {
        const int sel = chunk >> 4;
        const int k0 = (chunk & 15) * 32;
        const __nv_bfloat16* A = Ap[sel];
        const __nv_bfloat16* B = Bp[sel];
#pragma unroll
        for (int i = 0; i < 2; ++i) {
            int row = r0 + i * 64;
            int gm = m0 + row;
            cp_async16(smem_u32(&As[buf][row][c8]),
                       A + (size_t)gm * FH + k0 + c8, gm < M ? 16 : 0);
            cp_async16(smem_u32(&Bs[buf][row][c8]),
                       B + (size_t)(n0 + row) * FH + k0 + c8, 16);
        }
        cp_commit();
    };

    issue(0, 0);

    const int fr = lane >> 2;
    const int fc = (lane & 3) * 2;

#pragma unroll 1
    for (int c = 0; c < NCH; ++c) {
        cp_wait0();
        __syncthreads();
        if (c + 1 < NCH) issue((c + 1) & 1, c + 1);
        const int buf = c & 1;
#pragma unroll
        for (int kk = 0; kk < 32; kk += 16) {
            uint32_t a[2][4];
#pragma unroll
            for (int mi = 0; mi < 2; ++mi) {
                int rb = wm * 32 + mi * 16;
                a[mi][0] = *(const uint32_t*)&As[buf][rb + fr][kk + fc];
                a[mi][1] = *(const uint32_t*)&As[buf][rb + fr + 8][kk + fc];
                a[mi][2] = *(const uint32_t*)&As[buf][rb + fr][kk + fc + 8];
                a[mi][3] = *(const uint32_t*)&As[buf][rb + fr + 8][kk + fc + 8];
            }
#pragma unroll
            for (int ni = 0; ni < 8; ++ni) {
                int nb = wn * 64 + ni * 8;
                uint32_t b[2];
                b[0] = *(const uint32_t*)&Bs[buf][nb + fr][kk + fc];
                b[1] = *(const uint32_t*)&Bs[buf][nb + fr][kk + fc + 8];
                mma16816(acc[0][ni], a[0], b);
                mma16816(acc[1][ni], a[1], b);
            }
        }
        __syncthreads();
    }

#pragma unroll
    for (int mi = 0; mi < 2; ++mi) {
#pragma unroll
        for (int half = 0; half < 2; ++half) {
            int row = m0 + wm * 32 + mi * 16 + fr + half * 8;
            if (row >= M) continue;
#pragma unroll
            for (int ni = 0; ni < 8; ++ni) {
                int col = n0 + wn * 64 + ni * 8 + fc;
                float v0 = acc[mi][ni][half * 2 + 0] + bias[col];
                float v1 = acc[mi][ni][half * 2 + 1] + bias[col + 1];
                if (RELU) { v0 = fmaxf(v0, 0.f); v1 = fmaxf(v1, 0.f); }
                *(float2*)(Cout + (size_t)row * FH + col) = make_float2(v0, v1);
                if (SPLIT) {
                    __nv_bfloat16 h0, h1, l0, l1;
                    split1(v0, h0, l0); split1(v1, h1, l1);
                    *(uint32_t*)(Ch + (size_t)row * FH + col) = pack2(h0, h1);
                    *(uint32_t*)(Cl + (size_t)row * FH + col) = pack2(l0, l1);
                }
            }
        }
    }
}

// ---------------------------------------------------------------------------
extern "C" void kernel_launch(void* const* d_in, const int* in_sizes, int n_in,
                              void* d_out, int out_size) {
    const float* x     = (const float*)d_in[0];
    const int*   src1  = (const int*)  d_in[1];
    const int*   dst1  = (const int*)  d_in[2];
    const int*   src2  = (const int*)  d_in[3];
    const int*   dst2  = (const int*)  d_in[4];
    const float* Wrel1 = (const float*)d_in[5];
    const float* brel1 = (const float*)d_in[6];
    const float* Wroot1= (const float*)d_in[7];
    const float* Wrel2 = (const float*)d_in[8];
    const float* brel2 = (const float*)d_in[9];
    const float* Wroot2= (const float*)d_in[10];
    const float* Wlin  = (const float*)d_in[11];
    const float* blin  = (const float*)d_in[12];
    const float* Whead = (const float*)d_in[13];
    const float* bhead = (const float*)d_in[14];
    float* out = (float*)d_out;

    float *h, *h2, *Wcomb, *bcomb;
    __nv_bfloat16 *A1h, *A1l, *A2h, *A2l, *Hh, *Hl, *G2h, *G2l, *Wt;
    int *cnt1, *rp1, *pos1, *eidx1, *cnt2, *rp2, *pos2, *eidx2;
    cudaGetSymbolAddress((void**)&h,    g_h);
    cudaGetSymbolAddress((void**)&h2,   g_h2);
    cudaGetSymbolAddress((void**)&A1h,  g_A1h);
    cudaGetSymbolAddress((void**)&A1l,  g_A1l);
    cudaGetSymbolAddress((void**)&A2h,  g_A2h);
    cudaGetSymbolAddress((void**)&A2l,  g_A2l);
    cudaGetSymbolAddress((void**)&Hh,   g_Hh);
    cudaGetSymbolAddress((void**)&Hl,   g_Hl);
    cudaGetSymbolAddress((void**)&G2h,  g_G2h);
    cudaGetSymbolAddress((void**)&G2l,  g_G2l);
    cudaGetSymbolAddress((void**)&Wt,   g_Wt);
    cudaGetSymbolAddress((void**)&Wcomb, g_Wcomb);
    cudaGetSymbolAddress((void**)&bcomb, g_bcomb);
    cudaGetSymbolAddress((void**)&cnt1, g_cnt1);
    cudaGetSymbolAddress((void**)&rp1,  g_rp1);
    cudaGetSymbolAddress((void**)&pos1, g_pos1);
    cudaGetSymbolAddress((void**)&eidx1, g_eidx1);
    cudaGetSymbolAddress((void**)&cnt2, g_cnt2);
    cudaGetSymbolAddress((void**)&rp2,  g_rp2);
    cudaGetSymbolAddress((void**)&pos2, g_pos2);
    cudaGetSymbolAddress((void**)&eidx2, g_eidx2);
    __nv_bfloat16* WtP[8];
    for (int i = 0; i < 8; ++i) WtP[i] = Wt + (size_t)i * FH * FH;

    // ---- CSR build (both layers; independent of features) ----
    zero_i<<<(N1 + 255) / 256, 256>>>(cnt1, N1);
    zero_i<<<(N2 + 255) / 256, 256>>>(cnt2, N2);
    hist_k<<<(E1 + 255) / 256, 256>>>(dst1, E1, cnt1);
    hist_k<<<(E2 + 255) / 256, 256>>>(dst2, E2, cnt2);
    scan_k<<<1, 1024>>>(cnt1, N1, rp1, pos1);
    scan_k<<<1, 1024>>>(cnt2, N2, rp2, pos2);
    fill_k<<<(E1 + 255) / 256, 256>>>(dst1, E1, pos1, eidx1);
    fill_k<<<(E2 + 255) / 256, 256>>>(dst2, E2, pos2, eidx2);

    // ---- splits / weight prep (independent) ----
    {
        int n4 = (N1 * FH) / 4;
        split_f32<<<(n4 + 255) / 256, 256>>>((const float4*)x, (uint2*)A2h, (uint2*)A2l, n4);
        dim3 g(16, 16), b(32, 8);
        transpose_split<<<g, b>>>(Wrel1,  WtP[0], WtP[1]);
        transpose_split<<<g, b>>>(Wroot1, WtP[2], WtP[3]);
        transpose_split<<<g, b>>>(Wrel2,  WtP[4], WtP[5]);
        transpose_split<<<g, b>>>(Wroot2, WtP[6], WtP[7]);
        wcomb_kernel<<<FH + 1, 32>>>(Wlin, Whead, blin, bhead, Wcomb, bcomb);
    }

    // ---- layer 1 aggregation (gather, no atomics) + split ----
    gather_split<<<(N1 + 7) / 8, 256>>>(x, src1, eidx1, rp1, N1, A1h, A1l);

    // ---- layer 1 GEMM ----
    {
        dim3 grid(FH / 128, (N1 + 127) / 128);
        gemm_mma<true, true><<<grid, 256>>>(
            A1h, A1l, A2h, A2l, WtP[0], WtP[1], WtP[2], WtP[3],
            brel1, h, Hh, Hl, N1);
    }

    // ---- layer 2 aggregation + GEMM ----
    gather_split<<<(N2 + 7) / 8, 256>>>(h, src2, eidx2, rp2, N2, G2h, G2l);
    {
        dim3 grid(FH / 128, (N2 + 127) / 128);
        gemm_mma<false, false><<<grid, 256>>>(
            G2h, G2l, Hh, Hl, WtP[4], WtP[5], WtP[6], WtP[7],
            brel2, h2, nullptr, nullptr, N2);
    }

    // ---- head ----
    head_kernel<<<N2, 32>>>(h2, Wcomb, bcomb, out);

    (void)in_sizes; (void)n_in; (void)out_size;
}

// round 5
// speedup vs baseline: 3.0943x; 1.1350x over previous
#include <cuda_runtime.h>
#include <cuda_bf16.h>
#include <cstdint>

#define N0 100000
#define N1 20000
#define N2 4000
#define E1 500000
#define E2 100000
#define FH 512
#define C_OUT 10

// ---------------- scratch ---------------------------------------------------
__device__ float g_h [(size_t)N1 * FH];
__device__ float g_h2[(size_t)N2 * FH];

__device__ __nv_bfloat16 g_A1h[(size_t)N1 * FH], g_A1l[(size_t)N1 * FH];
__device__ __nv_bfloat16 g_A2h[(size_t)N1 * FH], g_A2l[(size_t)N1 * FH];
__device__ __nv_bfloat16 g_Hh [(size_t)N1 * FH], g_Hl [(size_t)N1 * FH];
__device__ __nv_bfloat16 g_G2h[(size_t)N2 * FH], g_G2l[(size_t)N2 * FH];
__device__ __nv_bfloat16 g_Wt[8][(size_t)FH * FH];
__device__ float g_Wcomb[(size_t)FH * C_OUT];
__device__ float g_bcomb[C_OUT];

// CSR scratch (esrc holds src node id per sorted edge slot)
__device__ int g_cnt1[N1], g_rp1[N1 + 1], g_pos1[N1], g_esrc1[E1];
__device__ int g_cnt2[N2], g_rp2[N2 + 1], g_pos2[N2], g_esrc2[E2];

// ---------------- helpers ---------------------------------------------------
__device__ __forceinline__ uint32_t smem_u32(const void* p) {
    uint32_t a;
    asm("{ .reg .u64 t; cvta.to.shared.u64 t, %1; cvt.u32.u64 %0, t; }"
        : "=r"(a) : "l"(p));
    return a;
}
__device__ __forceinline__ void cp_async16(uint32_t dst, const void* src, int sz) {
    asm volatile("cp.async.cg.shared.global [%0], [%1], 16, %2;"
                 :: "r"(dst), "l"(src), "r"(sz) : "memory");
}
__device__ __forceinline__ void cp_commit() {
    asm volatile("cp.async.commit_group;" ::: "memory");
}
__device__ __forceinline__ void cp_wait0() {
    asm volatile("cp.async.wait_group 0;" ::: "memory");
}
__device__ __forceinline__ void split1(float v, __nv_bfloat16& h, __nv_bfloat16& l) {
    h = __float2bfloat16(v);
    l = __float2bfloat16(v - __bfloat162float(h));
}
__device__ __forceinline__ uint32_t pack2(__nv_bfloat16 a, __nv_bfloat16 b) {
    return (uint32_t)__bfloat16_as_ushort(a) | ((uint32_t)__bfloat16_as_ushort(b) << 16);
}
__device__ __forceinline__ void mma16816(float* c, const uint32_t* a,
                                         uint32_t b0, uint32_t b1) {
    asm("mma.sync.aligned.m16n8k16.row.col.f32.bf16.bf16.f32 "
        "{%0,%1,%2,%3}, {%4,%5,%6,%7}, {%8,%9}, {%0,%1,%2,%3};"
        : "+f"(c[0]), "+f"(c[1]), "+f"(c[2]), "+f"(c[3])
        : "r"(a[0]), "r"(a[1]), "r"(a[2]), "r"(a[3]), "r"(b0), "r"(b1));
}
#define LDX4(r, addr) \
    asm volatile("ldmatrix.sync.aligned.m8n8.x4.shared.b16 {%0,%1,%2,%3}, [%4];" \
                 : "=r"((r)[0]), "=r"((r)[1]), "=r"((r)[2]), "=r"((r)[3])        \
                 : "r"(addr))

// ---------------- CSR build --------------------------------------------------
__global__ void zero_i(int* __restrict__ p, int n) {
    int i = blockIdx.x * blockDim.x + threadIdx.x;
    if (i < n) p[i] = 0;
}
__global__ void hist_k(const int* __restrict__ dst, int E, int* __restrict__ cnt) {
    int e = blockIdx.x * blockDim.x + threadIdx.x;
    if (e < E) atomicAdd(&cnt[dst[e]], 1);
}
__global__ __launch_bounds__(1024) void scan_k(const int* __restrict__ cnt, int n,
                                               int* __restrict__ rowptr,
                                               int* __restrict__ pos) {
    __shared__ int ts[1024];
    const int t = threadIdx.x;
    const int C = (n + 1023) >> 10;
    int local[20];
    int s = 0;
    for (int j = 0; j < C; ++j) {
        int idx = t * C + j;
        int v = (idx < n) ? cnt[idx] : 0;
        local[j] = s; s += v;
    }
    ts[t] = s;
    __syncthreads();
    for (int off = 1; off < 1024; off <<= 1) {
        int v = (t >= off) ? ts[t - off] : 0;
        __syncthreads();
        ts[t] += v;
        __syncthreads();
    }
    int base = (t > 0) ? ts[t - 1] : 0;
    for (int j = 0; j < C; ++j) {
        int idx = t * C + j;
        if (idx < n) { int r = base + local[j]; rowptr[idx] = r; pos[idx] = r; }
    }
    if (t == 1023) rowptr[n] = ts[1023];
}
__global__ void fill_k(const int* __restrict__ dst, const int* __restrict__ src,
                       int E, int* __restrict__ pos, int* __restrict__ esrc) {
    int e = blockIdx.x * blockDim.x + threadIdx.x;
    if (e < E) {
        int p = atomicAdd(&pos[dst[e]], 1);
        esrc[p] = src[e];
    }
}

// ---------------- gather-aggregate + bf16 split (one warp per row) -----------
__global__ void gather_split(const float* __restrict__ X,
                             const int* __restrict__ esrc,
                             const int* __restrict__ rowptr, int nrows,
                             __nv_bfloat16* __restrict__ Ah,
                             __nv_bfloat16* __restrict__ Al) {
    int row = blockIdx.x * (blockDim.x >> 5) + (threadIdx.x >> 5);
    if (row >= nrows) return;
    const int lane = threadIdx.x & 31;
    const int beg = rowptr[row], end = rowptr[row + 1];
    float4 a0 = make_float4(0.f, 0.f, 0.f, 0.f), a1 = a0, a2 = a0, a3 = a0;
    for (int i = beg; i < end; ++i) {
        const float4* xr = (const float4*)(X + (size_t)__ldg(&esrc[i]) * FH);
        float4 v0 = xr[lane], v1 = xr[lane + 32], v2 = xr[lane + 64], v3 = xr[lane + 96];
        a0.x += v0.x; a0.y += v0.y; a0.z += v0.z; a0.w += v0.w;
        a1.x += v1.x; a1.y += v1.y; a1.z += v1.z; a1.w += v1.w;
        a2.x += v2.x; a2.y += v2.y; a2.z += v2.z; a2.w += v2.w;
        a3.x += v3.x; a3.y += v3.y; a3.z += v3.z; a3.w += v3.w;
    }
    float4 acc[4] = {a0, a1, a2, a3};
#pragma unroll
    for (int q = 0; q < 4; ++q) {
        __nv_bfloat16 h0, h1, h2, h3, l0, l1, l2, l3;
        split1(acc[q].x, h0, l0); split1(acc[q].y, h1, l1);
        split1(acc[q].z, h2, l2); split1(acc[q].w, h3, l3);
        size_t o = (size_t)row * FH + 4 * (lane + 32 * q);
        *(uint2*)(Ah + o) = make_uint2(pack2(h0, h1), pack2(h2, h3));
        *(uint2*)(Al + o) = make_uint2(pack2(l0, l1), pack2(l2, l3));
    }
}

// ---------------- fp32 -> bf16 hi/lo split ----------------------------------
__global__ void split_f32(const float4* __restrict__ in,
                          uint2* __restrict__ hi, uint2* __restrict__ lo, int n4) {
    int i = blockIdx.x * blockDim.x + threadIdx.x;
    if (i >= n4) return;
    float4 v = in[i];
    __nv_bfloat16 h0, h1, h2, h3, l0, l1, l2, l3;
    split1(v.x, h0, l0); split1(v.y, h1, l1);
    split1(v.z, h2, l2); split1(v.w, h3, l3);
    hi[i] = make_uint2(pack2(h0, h1), pack2(h2, h3));
    lo[i] = make_uint2(pack2(l0, l1), pack2(l2, l3));
}

// ---------------- weight transpose + split ----------------------------------
__global__ void transpose_split(const float* __restrict__ W,
                                __nv_bfloat16* __restrict__ Bh,
                                __nv_bfloat16* __restrict__ Bl) {
    __shared__ float t[32][33];
    int n0 = blockIdx.x * 32, k0 = blockIdx.y * 32;
    int tx = threadIdx.x, ty = threadIdx.y;
    for (int yy = ty; yy < 32; yy += 8)
        t[yy][tx] = W[(size_t)(k0 + yy) * FH + n0 + tx];
    __syncthreads();
    for (int yy = ty; yy < 32; yy += 8) {
        float v = t[tx][yy];
        size_t o = (size_t)(n0 + yy) * FH + k0 + tx;
        __nv_bfloat16 h, l;
        split1(v, h, l);
        Bh[o] = h; Bl[o] = l;
    }
}

// ---------------- head fold + head ------------------------------------------
__global__ void wcomb_kernel(const float* __restrict__ Wlin,
                             const float* __restrict__ Whead,
                             const float* __restrict__ blin,
                             const float* __restrict__ bhead,
                             float* __restrict__ Wcomb, float* __restrict__ bcomb) {
    int k = blockIdx.x;
    int lane = threadIdx.x;
    const float* rowv = (k < FH) ? (Wlin + (size_t)k * FH) : blin;
    float acc[C_OUT];
#pragma unroll
    for (int c = 0; c < C_OUT; ++c) acc[c] = 0.f;
    for (int j = lane; j < FH; j += 32) {
        float v = rowv[j];
        const float* w = Whead + (size_t)j * C_OUT;
#pragma unroll
        for (int c = 0; c < C_OUT; ++c) acc[c] += v * w[c];
    }
#pragma unroll
    for (int off = 16; off > 0; off >>= 1)
#pragma unroll
        for (int c = 0; c < C_OUT; ++c)
            acc[c] += __shfl_down_sync(0xFFFFFFFFu, acc[c], off);
    if (lane == 0) {
        if (k < FH) {
#pragma unroll
            for (int c = 0; c < C_OUT; ++c) Wcomb[(size_t)k * C_OUT + c] = acc[c];
        } else {
#pragma unroll
            for (int c = 0; c < C_OUT; ++c) bcomb[c] = acc[c] + bhead[c];
        }
    }
}

__global__ void head_kernel(const float* __restrict__ h2,
                            const float* __restrict__ Wcomb,
                            const float* __restrict__ bcomb,
                            float* __restrict__ out) {
    int r = blockIdx.x;
    int lane = threadIdx.x;
    float acc[C_OUT];
#pragma unroll
    for (int c = 0; c < C_OUT; ++c) acc[c] = 0.f;
    const float* trow = h2 + (size_t)r * FH;
    for (int k = lane; k < FH; k += 32) {
        float t = trow[k];
        const float* w = Wcomb + (size_t)k * C_OUT;
#pragma unroll
        for (int c = 0; c < C_OUT; ++c) acc[c] += t * w[c];
    }
#pragma unroll
    for (int off = 16; off > 0; off >>= 1)
#pragma unroll
        for (int c = 0; c < C_OUT; ++c)
            acc[c] += __shfl_down_sync(0xFFFFFFFFu, acc[c], off);
    if (lane == 0) {
#pragma unroll
        for (int c = 0; c < C_OUT; ++c) out[(size_t)r * C_OUT + c] = acc[c] + bcomb[c];
    }
}

// ---------------- HMMA bf16-split dual-source GEMM (tile-reuse, ldmatrix) ----
// Stage = (source, k0[32-wide]): loads Ah, Al, Bh, Bl tiles once; computes the
// 3 split combos AhBh + AlBh + AhBl. 32 stages, double buffered.
#define SA 40   // smem row stride in bf16 (80B): conflict-free for ldmatrix

template <bool RELU, bool SPLIT>
__global__ __launch_bounds__(256) void gemm_mma(
    const __nv_bfloat16* __restrict__ A0h, const __nv_bfloat16* __restrict__ A0l,
    const __nv_bfloat16* __restrict__ A1h, const __nv_bfloat16* __restrict__ A1l,
    const __nv_bfloat16* __restrict__ B0h, const __nv_bfloat16* __restrict__ B0l,
    const __nv_bfloat16* __restrict__ B1h, const __nv_bfloat16* __restrict__ B1l,
    const float* __restrict__ bias, float* __restrict__ Cout,
    __nv_bfloat16* __restrict__ Ch, __nv_bfloat16* __restrict__ Cl, int M) {
    extern __shared__ __nv_bfloat16 sm[];
    // layout: sm[buf][tile][row][SA]; tile: 0=Ah 1=Al 2=Bh 3=Bl
    const int tid = threadIdx.x;
    const int lane = tid & 31;
    const int wid = tid >> 5;
    const int wm = wid & 3;          // 4 warps in M (32 rows each)
    const int wn = wid >> 2;         // 2 warps in N (64 cols each)
    const int m0 = blockIdx.y * 128;
    const int n0 = blockIdx.x * 128;

    const __nv_bfloat16* APs[2][2] = {{A0h, A0l}, {A1h, A1l}};
    const __nv_bfloat16* BPs[2][2] = {{B0h, B0l}, {B1h, B1l}};

    float acc[2][8][4];
#pragma unroll
    for (int i = 0; i < 2; ++i)
#pragma unroll
        for (int j = 0; j < 8; ++j)
#pragma unroll
            for (int q = 0; q < 4; ++q) acc[i][j][q] = 0.f;

    const int r0 = tid >> 2;             // 0..63
    const int c8 = (tid & 3) * 8;        // bf16 element offset (16B chunks)

    auto tile_off = [&](int buf, int t, int row, int col) -> uint32_t {
        return (uint32_t)((((buf * 4 + t) * 128 + row) * SA + col) * 2);
    };
    const uint32_t smb = smem_u32(sm);

    constexpr int NST = 32;
    auto issue = [&](int buf, int s) {
        const int src = s >> 4;
        const int k0 = (s & 15) * 32;
#pragma unroll
        for (int t = 0; t < 4; ++t) {
            const __nv_bfloat16* P = (t < 2) ? APs[src][t] : BPs[src][t - 2];
#pragma unroll
            for (int i = 0; i < 2; ++i) {
                int row = r0 + i * 64;
                int sz = 16;
                int gr;
                if (t < 2) { gr = m0 + row; if (gr >= M) sz = 0; }
                else       { gr = n0 + row; }
                cp_async16(smb + tile_off(buf, t, row, c8),
                           P + (size_t)gr * FH + k0 + c8, sz);
            }
        }
        cp_commit();
    };

    issue(0, 0);

    const int lrow = lane & 15;                 // ldmatrix row within 16
    const int lcol = (lane >> 4) << 3;          // +8 cols for upper half lanes
    const int fr = lane >> 2;
    const int fc = (lane & 3) * 2;

#pragma unroll 1
    for (int s = 0; s < NST; ++s) {
        cp_wait0();
        __syncthreads();
        if (s + 1 < NST) issue((s + 1) & 1, s + 1);
        const int buf = s & 1;
#pragma unroll
        for (int kk = 0; kk < 32; kk += 16) {
            uint32_t ah[2][4], al[2][4], bb[4][4];
#pragma unroll
            for (int mi = 0; mi < 2; ++mi) {
                int rb = wm * 32 + mi * 16 + lrow;
                LDX4(ah[mi], smb + tile_off(buf, 0, rb, kk + lcol));
                LDX4(al[mi], smb + tile_off(buf, 1, rb, kk + lcol));
            }
#pragma unroll
            for (int np = 0; np < 4; ++np) {
                int nb = wn * 64 + np * 16 + lrow;
                LDX4(bb[np], smb + tile_off(buf, 2, nb, kk + lcol));
            }
            // AhBh + AlBh
#pragma unroll
            for (int np = 0; np < 4; ++np) {
#pragma unroll
                for (int mi = 0; mi < 2; ++mi) {
                    mma16816(acc[mi][2 * np],     ah[mi], bb[np][0], bb[np][2]);
                    mma16816(acc[mi][2 * np + 1], ah[mi], bb[np][1], bb[np][3]);
                    mma16816(acc[mi][2 * np],     al[mi], bb[np][0], bb[np][2]);
                    mma16816(acc[mi][2 * np + 1], al[mi], bb[np][1], bb[np][3]);
                }
            }
            // AhBl
#pragma unroll
            for (int np = 0; np < 4; ++np) {
                int nb = wn * 64 + np * 16 + lrow;
                LDX4(bb[np], smb + tile_off(buf, 3, nb, kk + lcol));
            }
#pragma unroll
            for (int np = 0; np < 4; ++np) {
#pragma unroll
                for (int mi = 0; mi < 2; ++mi) {
                    mma16816(acc[mi][2 * np],     ah[mi], bb[np][0], bb[np][2]);
                    mma16816(acc[mi][2 * np + 1], ah[mi], bb[np][1], bb[np][3]);
                }
            }
        }
        __syncthreads();
    }

    // -------- epilogue --------
#pragma unroll
    for (int mi = 0; mi < 2; ++mi) {
#pragma unroll
        for (int half = 0; half < 2; ++half) {
            int row = m0 + wm * 32 + mi * 16 + fr + half * 8;
            if (row >= M) continue;
#pragma unroll
            for (int ni = 0; ni < 8; ++ni) {
                int col = n0 + wn * 64 + ni * 8 + fc;
                float v0 = acc[mi][ni][half * 2 + 0] + bias[col];
                float v1 = acc[mi][ni][half * 2 + 1] + bias[col + 1];
                if (RELU) { v0 = fmaxf(v0, 0.f); v1 = fmaxf(v1, 0.f); }
                *(float2*)(Cout + (size_t)row * FH + col) = make_float2(v0, v1);
                if (SPLIT) {
                    __nv_bfloat16 h0, h1, l0, l1;
                    split1(v0, h0, l0); split1(v1, h1, l1);
                    *(uint32_t*)(Ch + (size_t)row * FH + col) = pack2(h0, h1);
                    *(uint32_t*)(Cl + (size_t)row * FH + col) = pack2(l0, l1);
                }
            }
        }
    }
}

// ---------------------------------------------------------------------------
extern "C" void kernel_launch(void* const* d_in, const int* in_sizes, int n_in,
                              void* d_out, int out_size) {
    const float* x     = (const float*)d_in[0];
    const int*   src1  = (const int*)  d_in[1];
    const int*   dst1  = (const int*)  d_in[2];
    const int*   src2  = (const int*)  d_in[3];
    const int*   dst2  = (const int*)  d_in[4];
    const float* Wrel1 = (const float*)d_in[5];
    const float* brel1 = (const float*)d_in[6];
    const float* Wroot1= (const float*)d_in[7];
    const float* Wrel2 = (const float*)d_in[8];
    const float* brel2 = (const float*)d_in[9];
    const float* Wroot2= (const float*)d_in[10];
    const float* Wlin  = (const float*)d_in[11];
    const float* blin  = (const float*)d_in[12];
    const float* Whead = (const float*)d_in[13];
    const float* bhead = (const float*)d_in[14];
    float* out = (float*)d_out;

    float *h, *h2, *Wcomb, *bcomb;
    __nv_bfloat16 *A1h, *A1l, *A2h, *A2l, *Hh, *Hl, *G2h, *G2l, *Wt;
    int *cnt1, *rp1, *pos1, *esrc1, *cnt2, *rp2, *pos2, *esrc2;
    cudaGetSymbolAddress((void**)&h,    g_h);
    cudaGetSymbolAddress((void**)&h2,   g_h2);
    cudaGetSymbolAddress((void**)&A1h,  g_A1h);
    cudaGetSymbolAddress((void**)&A1l,  g_A1l);
    cudaGetSymbolAddress((void**)&A2h,  g_A2h);
    cudaGetSymbolAddress((void**)&A2l,  g_A2l);
    cudaGetSymbolAddress((void**)&Hh,   g_Hh);
    cudaGetSymbolAddress((void**)&Hl,   g_Hl);
    cudaGetSymbolAddress((void**)&G2h,  g_G2h);
    cudaGetSymbolAddress((void**)&G2l,  g_G2l);
    cudaGetSymbolAddress((void**)&Wt,   g_Wt);
    cudaGetSymbolAddress((void**)&Wcomb, g_Wcomb);
    cudaGetSymbolAddress((void**)&bcomb, g_bcomb);
    cudaGetSymbolAddress((void**)&cnt1, g_cnt1);
    cudaGetSymbolAddress((void**)&rp1,  g_rp1);
    cudaGetSymbolAddress((void**)&pos1, g_pos1);
    cudaGetSymbolAddress((void**)&esrc1, g_esrc1);
    cudaGetSymbolAddress((void**)&cnt2, g_cnt2);
    cudaGetSymbolAddress((void**)&rp2,  g_rp2);
    cudaGetSymbolAddress((void**)&pos2, g_pos2);
    cudaGetSymbolAddress((void**)&esrc2, g_esrc2);
    __nv_bfloat16* WtP[8];
    for (int i = 0; i < 8; ++i) WtP[i] = Wt + (size_t)i * FH * FH;

    constexpr int GSMEM = 2 * 4 * 128 * SA * 2;  // 81920 B
    cudaFuncSetAttribute(gemm_mma<true, true>,
                         cudaFuncAttributeMaxDynamicSharedMemorySize, GSMEM);
    cudaFuncSetAttribute(gemm_mma<false, false>,
                         cudaFuncAttributeMaxDynamicSharedMemorySize, GSMEM);

    // ---- CSR build ----
    zero_i<<<(N1 + 255) / 256, 256>>>(cnt1, N1);
    zero_i<<<(N2 + 255) / 256, 256>>>(cnt2, N2);
    hist_k<<<(E1 + 255) / 256, 256>>>(dst1, E1, cnt1);
    hist_k<<<(E2 + 255) / 256, 256>>>(dst2, E2, cnt2);
    scan_k<<<1, 1024>>>(cnt1, N1, rp1, pos1);
    scan_k<<<1, 1024>>>(cnt2, N2, rp2, pos2);
    fill_k<<<(E1 + 255) / 256, 256>>>(dst1, src1, E1, pos1, esrc1);
    fill_k<<<(E2 + 255) / 256, 256>>>(dst2, src2, E2, pos2, esrc2);

    // ---- splits / weight prep ----
    {
        int n4 = (N1 * FH) / 4;
        split_f32<<<(n4 + 255) / 256, 256>>>((const float4*)x, (uint2*)A2h, (uint2*)A2l, n4);
        dim3 g(16, 16), b(32, 8);
        transpose_split<<<g, b>>>(Wrel1,  WtP[0], WtP[1]);
        transpose_split<<<g, b>>>(Wroot1, WtP[2], WtP[3]);
        transpose_split<<<g, b>>>(Wrel2,  WtP[4], WtP[5]);
        transpose_split<<<g, b>>>(Wroot2, WtP[6], WtP[7]);
        wcomb_kernel<<<FH + 1, 32>>>(Wlin, Whead, blin, bhead, Wcomb, bcomb);
    }

    // ---- layer 1 ----
    gather_split<<<(N1 + 7) / 8, 256>>>(x, esrc1, rp1, N1, A1h, A1l);
    {
        dim3 grid(FH / 128, (N1 + 127) / 128);
        gemm_mma<true, true><<<grid, 256, GSMEM>>>(
            A1h, A1l, A2h, A2l, WtP[0], WtP[1], WtP[2], WtP[3],
            brel1, h, Hh, Hl, N1);
    }

    // ---- layer 2 ----
    gather_split<<<(N2 + 7) / 8, 256>>>(h, esrc2, rp2, N2, G2h, G2l);
    {
        dim3 grid(FH / 128, (N2 + 127) / 128);
        gemm_mma<false, false><<<grid, 256, GSMEM>>>(
            G2h, G2l, Hh, Hl, WtP[4], WtP[5], WtP[6], WtP[7],
            brel2, h2, nullptr, nullptr, N2);
    }

    // ---- head ----
    head_kernel<<<N2, 32>>>(h2, Wcomb, bcomb, out);

    (void)in_sizes; (void)n_in; (void)out_size;
}

// round 6
// speedup vs baseline: 3.1288x; 1.0112x over previous
#include <cuda_runtime.h>
#include <cuda_bf16.h>
#include <cstdint>

#define N0 100000
#define N1 20000
#define N2 4000
#define E1 500000
#define E2 100000
#define FH 512
#define C_OUT 10

// ---------------- scratch ---------------------------------------------------
__device__ float g_h2[(size_t)N2 * FH];

__device__ __nv_bfloat16 g_A1h[(size_t)N1 * FH], g_A1l[(size_t)N1 * FH];
__device__ __nv_bfloat16 g_A2h[(size_t)N1 * FH], g_A2l[(size_t)N1 * FH];
__device__ __nv_bfloat16 g_Hh [(size_t)N1 * FH], g_Hl [(size_t)N1 * FH];
__device__ __nv_bfloat16 g_G2h[(size_t)N2 * FH], g_G2l[(size_t)N2 * FH];
__device__ __nv_bfloat16 g_Wt[8][(size_t)FH * FH];
__device__ float g_Wcomb[(size_t)FH * C_OUT];
__device__ float g_bcomb[C_OUT];

// CSR scratch
__device__ int g_cnt1[N1], g_rp1[N1 + 1], g_pos1[N1], g_esrc1[E1];
__device__ int g_cnt2[N2], g_rp2[N2 + 1], g_pos2[N2], g_esrc2[E2];

// ---------------- helpers ---------------------------------------------------
__device__ __forceinline__ uint32_t smem_u32(const void* p) {
    uint32_t a;
    asm("{ .reg .u64 t; cvta.to.shared.u64 t, %1; cvt.u32.u64 %0, t; }"
        : "=r"(a) : "l"(p));
    return a;
}
__device__ __forceinline__ void cp_async16(uint32_t dst, const void* src, int sz) {
    asm volatile("cp.async.cg.shared.global [%0], [%1], 16, %2;"
                 :: "r"(dst), "l"(src), "r"(sz) : "memory");
}
__device__ __forceinline__ void cp_commit() {
    asm volatile("cp.async.commit_group;" ::: "memory");
}
__device__ __forceinline__ void cp_wait0() {
    asm volatile("cp.async.wait_group 0;" ::: "memory");
}
__device__ __forceinline__ void split1(float v, __nv_bfloat16& h, __nv_bfloat16& l) {
    h = __float2bfloat16(v);
    l = __float2bfloat16(v - __bfloat162float(h));
}
__device__ __forceinline__ uint32_t pack2(__nv_bfloat16 a, __nv_bfloat16 b) {
    return (uint32_t)__bfloat16_as_ushort(a) | ((uint32_t)__bfloat16_as_ushort(b) << 16);
}
__device__ __forceinline__ float bf_lo(uint32_t w) {
    return __uint_as_float(w << 16);
}
__device__ __forceinline__ float bf_hi(uint32_t w) {
    return __uint_as_float(w & 0xFFFF0000u);
}
__device__ __forceinline__ void mma16816(float* c, const uint32_t* a,
                                         uint32_t b0, uint32_t b1) {
    asm("mma.sync.aligned.m16n8k16.row.col.f32.bf16.bf16.f32 "
        "{%0,%1,%2,%3}, {%4,%5,%6,%7}, {%8,%9}, {%0,%1,%2,%3};"
        : "+f"(c[0]), "+f"(c[1]), "+f"(c[2]), "+f"(c[3])
        : "r"(a[0]), "r"(a[1]), "r"(a[2]), "r"(a[3]), "r"(b0), "r"(b1));
}
#define LDX4(r, addr) \
    asm volatile("ldmatrix.sync.aligned.m8n8.x4.shared.b16 {%0,%1,%2,%3}, [%4];" \
                 : "=r"((r)[0]), "=r"((r)[1]), "=r"((r)[2]), "=r"((r)[3])        \
                 : "r"(addr))

// ---------------- CSR build --------------------------------------------------
__global__ void zero_i(int* __restrict__ p, int n) {
    int i = blockIdx.x * blockDim.x + threadIdx.x;
    if (i < n) p[i] = 0;
}
__global__ void hist_k(const int* __restrict__ dst, int E, int* __restrict__ cnt) {
    int e = blockIdx.x * blockDim.x + threadIdx.x;
    if (e < E) atomicAdd(&cnt[dst[e]], 1);
}
__global__ __launch_bounds__(1024) void scan_k(const int* __restrict__ cnt, int n,
                                               int* __restrict__ rowptr,
                                               int* __restrict__ pos) {
    __shared__ int ts[1024];
    const int t = threadIdx.x;
    const int C = (n + 1023) >> 10;
    int local[20];
    int s = 0;
    for (int j = 0; j < C; ++j) {
        int idx = t * C + j;
        int v = (idx < n) ? cnt[idx] : 0;
        local[j] = s; s += v;
    }
    ts[t] = s;
    __syncthreads();
    for (int off = 1; off < 1024; off <<= 1) {
        int v = (t >= off) ? ts[t - off] : 0;
        __syncthreads();
        ts[t] += v;
        __syncthreads();
    }
    int base = (t > 0) ? ts[t - 1] : 0;
    for (int j = 0; j < C; ++j) {
        int idx = t * C + j;
        if (idx < n) { int r = base + local[j]; rowptr[idx] = r; pos[idx] = r; }
    }
    if (t == 1023) rowptr[n] = ts[1023];
}
__global__ void fill_k(const int* __restrict__ dst, const int* __restrict__ src,
                       int E, int* __restrict__ pos, int* __restrict__ esrc) {
    int e = blockIdx.x * blockDim.x + threadIdx.x;
    if (e < E) {
        int p = atomicAdd(&pos[dst[e]], 1);
        esrc[p] = src[e];
    }
}

// ---------------- gather (fp32 source) + bf16 split, 2-edge unrolled ---------
__global__ void gather_split(const float* __restrict__ X,
                             const int* __restrict__ esrc,
                             const int* __restrict__ rowptr, int nrows,
                             __nv_bfloat16* __restrict__ Ah,
                             __nv_bfloat16* __restrict__ Al) {
    int row = blockIdx.x * (blockDim.x >> 5) + (threadIdx.x >> 5);
    if (row >= nrows) return;
    const int lane = threadIdx.x & 31;
    const int beg = rowptr[row], end = rowptr[row + 1];
    float4 a0 = make_float4(0.f, 0.f, 0.f, 0.f), a1 = a0, a2 = a0, a3 = a0;
    float4 b0 = a0, b1 = a0, b2 = a0, b3 = a0;
    int i = beg;
    for (; i + 2 <= end; i += 2) {
        const float4* r0 = (const float4*)(X + (size_t)__ldg(&esrc[i]) * FH);
        const float4* r1 = (const float4*)(X + (size_t)__ldg(&esrc[i + 1]) * FH);
        float4 u0 = r0[lane], u1 = r0[lane + 32], u2 = r0[lane + 64], u3 = r0[lane + 96];
        float4 w0 = r1[lane], w1 = r1[lane + 32], w2 = r1[lane + 64], w3 = r1[lane + 96];
        a0.x += u0.x; a0.y += u0.y; a0.z += u0.z; a0.w += u0.w;
        a1.x += u1.x; a1.y += u1.y; a1.z += u1.z; a1.w += u1.w;
        a2.x += u2.x; a2.y += u2.y; a2.z += u2.z; a2.w += u2.w;
        a3.x += u3.x; a3.y += u3.y; a3.z += u3.z; a3.w += u3.w;
        b0.x += w0.x; b0.y += w0.y; b0.z += w0.z; b0.w += w0.w;
        b1.x += w1.x; b1.y += w1.y; b1.z += w1.z; b1.w += w1.w;
        b2.x += w2.x; b2.y += w2.y; b2.z += w2.z; b2.w += w2.w;
        b3.x += w3.x; b3.y += w3.y; b3.z += w3.z; b3.w += w3.w;
    }
    if (i < end) {
        const float4* r0 = (const float4*)(X + (size_t)__ldg(&esrc[i]) * FH);
        float4 u0 = r0[lane], u1 = r0[lane + 32], u2 = r0[lane + 64], u3 = r0[lane + 96];
        a0.x += u0.x; a0.y += u0.y; a0.z += u0.z; a0.w += u0.w;
        a1.x += u1.x; a1.y += u1.y; a1.z += u1.z; a1.w += u1.w;
        a2.x += u2.x; a2.y += u2.y; a2.z += u2.z; a2.w += u2.w;
        a3.x += u3.x; a3.y += u3.y; a3.z += u3.z; a3.w += u3.w;
    }
    a0.x += b0.x; a0.y += b0.y; a0.z += b0.z; a0.w += b0.w;
    a1.x += b1.x; a1.y += b1.y; a1.z += b1.z; a1.w += b1.w;
    a2.x += b2.x; a2.y += b2.y; a2.z += b2.z; a2.w += b2.w;
    a3.x += b3.x; a3.y += b3.y; a3.z += b3.z; a3.w += b3.w;
    float4 acc[4] = {a0, a1, a2, a3};
#pragma unroll
    for (int q = 0; q < 4; ++q) {
        __nv_bfloat16 h0, h1, h2, h3, l0, l1, l2, l3;
        split1(acc[q].x, h0, l0); split1(acc[q].y, h1, l1);
        split1(acc[q].z, h2, l2); split1(acc[q].w, h3, l3);
        size_t o = (size_t)row * FH + 4 * (lane + 32 * q);
        *(uint2*)(Ah + o) = make_uint2(pack2(h0, h1), pack2(h2, h3));
        *(uint2*)(Al + o) = make_uint2(pack2(l0, l1), pack2(l2, l3));
    }
}

// ---------------- gather (bf16 hi/lo source) + bf16 split --------------------
// Reconstructs v = hi + lo per element; lane handles 16 contiguous elements.
__global__ void gather_bf16_split(const __nv_bfloat16* __restrict__ Xh,
                                  const __nv_bfloat16* __restrict__ Xl,
                                  const int* __restrict__ esrc,
                                  const int* __restrict__ rowptr, int nrows,
                                  __nv_bfloat16* __restrict__ Ah,
                                  __nv_bfloat16* __restrict__ Al) {
    int row = blockIdx.x * (blockDim.x >> 5) + (threadIdx.x >> 5);
    if (row >= nrows) return;
    const int lane = threadIdx.x & 31;
    const int beg = rowptr[row], end = rowptr[row + 1];
    float acc[16];
#pragma unroll
    for (int j = 0; j < 16; ++j) acc[j] = 0.f;

    for (int i = beg; i < end; ++i) {
        size_t base = (size_t)__ldg(&esrc[i]) * FH + lane * 16;
        uint4 H0 = *(const uint4*)(Xh + base);
        uint4 H1 = *(const uint4*)(Xh + base + 8);
        uint4 L0 = *(const uint4*)(Xl + base);
        uint4 L1 = *(const uint4*)(Xl + base + 8);
        uint32_t hw[8] = {H0.x, H0.y, H0.z, H0.w, H1.x, H1.y, H1.z, H1.w};
        uint32_t lw[8] = {L0.x, L0.y, L0.z, L0.w, L1.x, L1.y, L1.z, L1.w};
#pragma unroll
        for (int j = 0; j < 8; ++j) {
            acc[2 * j]     += bf_lo(hw[j]) + bf_lo(lw[j]);
            acc[2 * j + 1] += bf_hi(hw[j]) + bf_hi(lw[j]);
        }
    }
    uint32_t hp[8], lp[8];
#pragma unroll
    for (int j = 0; j < 8; ++j) {
        __nv_bfloat16 h0, h1, l0, l1;
        split1(acc[2 * j], h0, l0);
        split1(acc[2 * j + 1], h1, l1);
        hp[j] = pack2(h0, h1);
        lp[j] = pack2(l0, l1);
    }
    size_t o = (size_t)row * FH + lane * 16;
    *(uint4*)(Ah + o)     = make_uint4(hp[0], hp[1], hp[2], hp[3]);
    *(uint4*)(Ah + o + 8) = make_uint4(hp[4], hp[5], hp[6], hp[7]);
    *(uint4*)(Al + o)     = make_uint4(lp[0], lp[1], lp[2], lp[3]);
    *(uint4*)(Al + o + 8) = make_uint4(lp[4], lp[5], lp[6], lp[7]);
}

// ---------------- fp32 -> bf16 hi/lo split ----------------------------------
__global__ void split_f32(const float4* __restrict__ in,
                          uint2* __restrict__ hi, uint2* __restrict__ lo, int n4) {
    int i = blockIdx.x * blockDim.x + threadIdx.x;
    if (i >= n4) return;
    float4 v = in[i];
    __nv_bfloat16 h0, h1, h2, h3, l0, l1, l2, l3;
    split1(v.x, h0, l0); split1(v.y, h1, l1);
    split1(v.z, h2, l2); split1(v.w, h3, l3);
    hi[i] = make_uint2(pack2(h0, h1), pack2(h2, h3));
    lo[i] = make_uint2(pack2(l0, l1), pack2(l2, l3));
}

// ---------------- weight transpose + split ----------------------------------
__global__ void transpose_split(const float* __restrict__ W,
                                __nv_bfloat16* __restrict__ Bh,
                                __nv_bfloat16* __restrict__ Bl) {
    __shared__ float t[32][33];
    int n0 = blockIdx.x * 32, k0 = blockIdx.y * 32;
    int tx = threadIdx.x, ty = threadIdx.y;
    for (int yy = ty; yy < 32; yy += 8)
        t[yy][tx] = W[(size_t)(k0 + yy) * FH + n0 + tx];
    __syncthreads();
    for (int yy = ty; yy < 32; yy += 8) {
        float v = t[tx][yy];
        size_t o = (size_t)(n0 + yy) * FH + k0 + tx;
        __nv_bfloat16 h, l;
        split1(v, h, l);
        Bh[o] = h; Bl[o] = l;
    }
}

// ---------------- head fold + head ------------------------------------------
__global__ void wcomb_kernel(const float* __restrict__ Wlin,
                             const float* __restrict__ Whead,
                             const float* __restrict__ blin,
                             const float* __restrict__ bhead,
                             float* __restrict__ Wcomb, float* __restrict__ bcomb) {
    int k = blockIdx.x;
    int lane = threadIdx.x;
    const float* rowv = (k < FH) ? (Wlin + (size_t)k * FH) : blin;
    float acc[C_OUT];
#pragma unroll
    for (int c = 0; c < C_OUT; ++c) acc[c] = 0.f;
    for (int j = lane; j < FH; j += 32) {
        float v = rowv[j];
        const float* w = Whead + (size_t)j * C_OUT;
#pragma unroll
        for (int c = 0; c < C_OUT; ++c) acc[c] += v * w[c];
    }
#pragma unroll
    for (int off = 16; off > 0; off >>= 1)
#pragma unroll
        for (int c = 0; c < C_OUT; ++c)
            acc[c] += __shfl_down_sync(0xFFFFFFFFu, acc[c], off);
    if (lane == 0) {
        if (k < FH) {
#pragma unroll
            for (int c = 0; c < C_OUT; ++c) Wcomb[(size_t)k * C_OUT + c] = acc[c];
        } else {
#pragma unroll
            for (int c = 0; c < C_OUT; ++c) bcomb[c] = acc[c] + bhead[c];
        }
    }
}

__global__ void head_kernel(const float* __restrict__ h2,
                            const float* __restrict__ Wcomb,
                            const float* __restrict__ bcomb,
                            float* __restrict__ out) {
    int r = blockIdx.x;
    int lane = threadIdx.x;
    float acc[C_OUT];
#pragma unroll
    for (int c = 0; c < C_OUT; ++c) acc[c] = 0.f;
    const float* trow = h2 + (size_t)r * FH;
    for (int k = lane; k < FH; k += 32) {
        float t = trow[k];
        const float* w = Wcomb + (size_t)k * C_OUT;
#pragma unroll
        for (int c = 0; c < C_OUT; ++c) acc[c] += t * w[c];
    }
#pragma unroll
    for (int off = 16; off > 0; off >>= 1)
#pragma unroll
        for (int c = 0; c < C_OUT; ++c)
            acc[c] += __shfl_down_sync(0xFFFFFFFFu, acc[c], off);
    if (lane == 0) {
#pragma unroll
        for (int c = 0; c < C_OUT; ++c) out[(size_t)r * C_OUT + c] = acc[c] + bcomb[c];
    }
}

// ---------------- HMMA bf16-split dual-source GEMM (tile-reuse, ldmatrix) ----
#define SA 40

template <bool RELU, bool SPLIT, bool WF32>
__global__ __launch_bounds__(256) void gemm_mma(
    const __nv_bfloat16* __restrict__ A0h, const __nv_bfloat16* __restrict__ A0l,
    const __nv_bfloat16* __restrict__ A1h, const __nv_bfloat16* __restrict__ A1l,
    const __nv_bfloat16* __restrict__ B0h, const __nv_bfloat16* __restrict__ B0l,
    const __nv_bfloat16* __restrict__ B1h, const __nv_bfloat16* __restrict__ B1l,
    const float* __restrict__ bias, float* __restrict__ Cout,
    __nv_bfloat16* __restrict__ Ch, __nv_bfloat16* __restrict__ Cl, int M) {
    extern __shared__ __nv_bfloat16 sm[];
    const int tid = threadIdx.x;
    const int lane = tid & 31;
    const int wid = tid >> 5;
    const int wm = wid & 3;
    const int wn = wid >> 2;
    const int m0 = blockIdx.y * 128;
    const int n0 = blockIdx.x * 128;

    const __nv_bfloat16* APs[2][2] = {{A0h, A0l}, {A1h, A1l}};
    const __nv_bfloat16* BPs[2][2] = {{B0h, B0l}, {B1h, B1l}};

    float acc[2][8][4];
#pragma unroll
    for (int i = 0; i < 2; ++i)
#pragma unroll
        for (int j = 0; j < 8; ++j)
#pragma unroll
            for (int q = 0; q < 4; ++q) acc[i][j][q] = 0.f;

    const int r0 = tid >> 2;
    const int c8 = (tid & 3) * 8;

    auto tile_off = [&](int buf, int t, int row, int col) -> uint32_t {
        return (uint32_t)((((buf * 4 + t) * 128 + row) * SA + col) * 2);
    };
    const uint32_t smb = smem_u32(sm);

    constexpr int NST = 32;
    auto issue = [&](int buf, int s) {
        const int src = s >> 4;
        const int k0 = (s & 15) * 32;
#pragma unroll
        for (int t = 0; t < 4; ++t) {
            const __nv_bfloat16* P = (t < 2) ? APs[src][t] : BPs[src][t - 2];
#pragma unroll
            for (int i = 0; i < 2; ++i) {
                int row = r0 + i * 64;
                int sz = 16;
                int gr;
                if (t < 2) { gr = m0 + row; if (gr >= M) sz = 0; }
                else       { gr = n0 + row; }
                cp_async16(smb + tile_off(buf, t, row, c8),
                           P + (size_t)gr * FH + k0 + c8, sz);
            }
        }
        cp_commit();
    };

    issue(0, 0);

    const int lrow = lane & 15;
    const int lcol = (lane >> 4) << 3;
    const int fr = lane >> 2;
    const int fc = (lane & 3) * 2;

#pragma unroll 1
    for (int s = 0; s < NST; ++s) {
        cp_wait0();
        __syncthreads();
        if (s + 1 < NST) issue((s + 1) & 1, s + 1);
        const int buf = s & 1;
#pragma unroll
        for (int kk = 0; kk < 32; kk += 16) {
            uint32_t ah[2][4], al[2][4], bb[4][4];
#pragma unroll
            for (int mi = 0; mi < 2; ++mi) {
                int rb = wm * 32 + mi * 16 + lrow;
                LDX4(ah[mi], smb + tile_off(buf, 0, rb, kk + lcol));
                LDX4(al[mi], smb + tile_off(buf, 1, rb, kk + lcol));
            }
#pragma unroll
            for (int np = 0; np < 4; ++np) {
                int nb = wn * 64 + np * 16 + lrow;
                LDX4(bb[np], smb + tile_off(buf, 2, nb, kk + lcol));
            }
#pragma unroll
            for (int np = 0; np < 4; ++np) {
#pragma unroll
                for (int mi = 0; mi < 2; ++mi) {
                    mma16816(acc[mi][2 * np],     ah[mi], bb[np][0], bb[np][2]);
                    mma16816(acc[mi][2 * np + 1], ah[mi], bb[np][1], bb[np][3]);
                    mma16816(acc[mi][2 * np],     al[mi], bb[np][0], bb[np][2]);
                    mma16816(acc[mi][2 * np + 1], al[mi], bb[np][1], bb[np][3]);
                }
            }
#pragma unroll
            for (int np = 0; np < 4; ++np) {
                int nb = wn * 64 + np * 16 + lrow;
                LDX4(bb[np], smb + tile_off(buf, 3, nb, kk + lcol));
            }
#pragma unroll
            for (int np = 0; np < 4; ++np) {
#pragma unroll
                for (int mi = 0; mi < 2; ++mi) {
                    mma16816(acc[mi][2 * np],     ah[mi], bb[np][0], bb[np][2]);
                    mma16816(acc[mi][2 * np + 1], ah[mi], bb[np][1], bb[np][3]);
                }
            }
        }
        __syncthreads();
    }

    // -------- epilogue --------
#pragma unroll
    for (int mi = 0; mi < 2; ++mi) {
#pragma unroll
        for (int half = 0; half < 2; ++half) {
            int row = m0 + wm * 32 + mi * 16 + fr + half * 8;
            if (row >= M) continue;
#pragma unroll
            for (int ni = 0; ni < 8; ++ni) {
                int col = n0 + wn * 64 + ni * 8 + fc;
                float v0 = acc[mi][ni][half * 2 + 0] + bias[col];
                float v1 = acc[mi][ni][half * 2 + 1] + bias[col + 1];
                if (RELU) { v0 = fmaxf(v0, 0.f); v1 = fmaxf(v1, 0.f); }
                if (WF32)
                    *(float2*)(Cout + (size_t)row * FH + col) = make_float2(v0, v1);
                if (SPLIT) {
                    __nv_bfloat16 h0, h1, l0, l1;
                    split1(v0, h0, l0); split1(v1, h1, l1);
                    *(uint32_t*)(Ch + (size_t)row * FH + col) = pack2(h0, h1);
                    *(uint32_t*)(Cl + (size_t)row * FH + col) = pack2(l0, l1);
                }
            }
        }
    }
}

// ---------------------------------------------------------------------------
extern "C" void kernel_launch(void* const* d_in, const int* in_sizes, int n_in,
                              void* d_out, int out_size) {
    const float* x     = (const float*)d_in[0];
    const int*   src1  = (const int*)  d_in[1];
    const int*   dst1  = (const int*)  d_in[2];
    const int*   src2  = (const int*)  d_in[3];
    const int*   dst2  = (const int*)  d_in[4];
    const float* Wrel1 = (const float*)d_in[5];
    const float* brel1 = (const float*)d_in[6];
    const float* Wroot1= (const float*)d_in[7];
    const float* Wrel2 = (const float*)d_in[8];
    const float* brel2 = (const float*)d_in[9];
    const float* Wroot2= (const float*)d_in[10];
    const float* Wlin  = (const float*)d_in[11];
    const float* blin  = (const float*)d_in[12];
    const float* Whead = (const float*)d_in[13];
    const float* bhead = (const float*)d_in[14];
    float* out = (float*)d_out;

    float *h2, *Wcomb, *bcomb;
    __nv_bfloat16 *A1h, *A1l, *A2h, *A2l, *Hh, *Hl, *G2h, *G2l, *Wt;
    int *cnt1, *rp1, *pos1, *esrc1, *cnt2, *rp2, *pos2, *esrc2;
    cudaGetSymbolAddress((void**)&h2,   g_h2);
    cudaGetSymbolAddress((void**)&A1h,  g_A1h);
    cudaGetSymbolAddress((void**)&A1l,  g_A1l);
    cudaGetSymbolAddress((void**)&A2h,  g_A2h);
    cudaGetSymbolAddress((void**)&A2l,  g_A2l);
    cudaGetSymbolAddress((void**)&Hh,   g_Hh);
    cudaGetSymbolAddress((void**)&Hl,   g_Hl);
    cudaGetSymbolAddress((void**)&G2h,  g_G2h);
    cudaGetSymbolAddress((void**)&G2l,  g_G2l);
    cudaGetSymbolAddress((void**)&Wt,   g_Wt);
    cudaGetSymbolAddress((void**)&Wcomb, g_Wcomb);
    cudaGetSymbolAddress((void**)&bcomb, g_bcomb);
    cudaGetSymbolAddress((void**)&cnt1, g_cnt1);
    cudaGetSymbolAddress((void**)&rp1,  g_rp1);
    cudaGetSymbolAddress((void**)&pos1, g_pos1);
    cudaGetSymbolAddress((void**)&esrc1, g_esrc1);
    cudaGetSymbolAddress((void**)&cnt2, g_cnt2);
    cudaGetSymbolAddress((void**)&rp2,  g_rp2);
    cudaGetSymbolAddress((void**)&pos2, g_pos2);
    cudaGetSymbolAddress((void**)&esrc2, g_esrc2);
    __nv_bfloat16* WtP[8];
    for (int i = 0; i < 8; ++i) WtP[i] = Wt + (size_t)i * FH * FH;

    constexpr int GSMEM = 2 * 4 * 128 * SA * 2;  // 81920 B
    cudaFuncSetAttribute(gemm_mma<true, true, false>,
                         cudaFuncAttributeMaxDynamicSharedMemorySize, GSMEM);
    cudaFuncSetAttribute(gemm_mma<false, false, true>,
                         cudaFuncAttributeMaxDynamicSharedMemorySize, GSMEM);

    // ---- CSR build ----
    zero_i<<<(N1 + 255) / 256, 256>>>(cnt1, N1);
    zero_i<<<(N2 + 255) / 256, 256>>>(cnt2, N2);
    hist_k<<<(E1 + 255) / 256, 256>>>(dst1, E1, cnt1);
    hist_k<<<(E2 + 255) / 256, 256>>>(dst2, E2, cnt2);
    scan_k<<<1, 1024>>>(cnt1, N1, rp1, pos1);
    scan_k<<<1, 1024>>>(cnt2, N2, rp2, pos2);
    fill_k<<<(E1 + 255) / 256, 256>>>(dst1, src1, E1, pos1, esrc1);
    fill_k<<<(E2 + 255) / 256, 256>>>(dst2, src2, E2, pos2, esrc2);

    // ---- splits / weight prep ----
    {
        int n4 = (N1 * FH) / 4;
        split_f32<<<(n4 + 255) / 256, 256>>>((const float4*)x, (uint2*)A2h, (uint2*)A2l, n4);
        dim3 g(16, 16), b(32, 8);
        transpose_split<<<g, b>>>(Wrel1,  WtP[0], WtP[1]);
        transpose_split<<<g, b>>>(Wroot1, WtP[2], WtP[3]);
        transpose_split<<<g, b>>>(Wrel2,  WtP[4], WtP[5]);
        transpose_split<<<g, b>>>(Wroot2, WtP[6], WtP[7]);
        wcomb_kernel<<<FH + 1, 32>>>(Wlin, Whead, blin, bhead, Wcomb, bcomb);
    }

    // ---- layer 1 ----
    gather_split<<<(N1 + 7) / 8, 256>>>(x, esrc1, rp1, N1, A1h, A1l);
    {
        dim3 grid(FH / 128, (N1 + 127) / 128);
        gemm_mma<true, true, false><<<grid, 256, GSMEM>>>(
            A1h, A1l, A2h, A2l, WtP[0], WtP[1], WtP[2], WtP[3],
            brel1, nullptr, Hh, Hl, N1);
    }

    // ---- layer 2 ----
    gather_bf16_split<<<(N2 + 7) / 8, 256>>>(Hh, Hl, esrc2, rp2, N2, G2h, G2l);
    {
        dim3 grid(FH / 128, (N2 + 127) / 128);
        gemm_mma<false, false, true><<<grid, 256, GSMEM>>>(
            G2h, G2l, Hh, Hl, WtP[4], WtP[5], WtP[6], WtP[7],
            brel2, h2, nullptr, nullptr, N2);
    }

    // ---- head ----
    head_kernel<<<N2, 32>>>(h2, Wcomb, bcomb, out);

    (void)in_sizes; (void)n_in; (void)out_size;
}

// round 7
// speedup vs baseline: 3.5761x; 1.1430x over previous
#include <cuda_runtime.h>
#include <cuda_fp16.h>
#include <cstdint>

#define N0 100000
#define N1 20000
#define N2 4000
#define E1 500000
#define E2 100000
#define FH 512
#define C_OUT 10

// ---------------- scratch ---------------------------------------------------
__device__ float g_h2[(size_t)N2 * FH];

__device__ __half g_A1h[(size_t)N1 * FH], g_A1l[(size_t)N1 * FH]; // agg1 split
__device__ __half g_A2h[(size_t)N1 * FH], g_A2l[(size_t)N1 * FH]; // x[:N1] split
__device__ __half g_Hh [(size_t)N1 * FH], g_Hl [(size_t)N1 * FH]; // h split
__device__ __half g_G2h[(size_t)N2 * FH], g_G2l[(size_t)N2 * FH]; // agg2 split
__device__ __half g_Wt[8][(size_t)FH * FH]; // 0/1 rel1 h/l, 2/3 root1, 4/5 rel2, 6/7 root2
__device__ float g_Wcomb[(size_t)FH * C_OUT];
__device__ float g_bcomb[C_OUT];

// CSR scratch
__device__ int g_cnt1[N1], g_rp1[N1 + 1], g_pos1[N1], g_esrc1[E1];
__device__ int g_cnt2[N2], g_rp2[N2 + 1], g_pos2[N2], g_esrc2[E2];

// ---------------- helpers ---------------------------------------------------
__device__ __forceinline__ uint32_t smem_u32(const void* p) {
    uint32_t a;
    asm("{ .reg .u64 t; cvta.to.shared.u64 t, %1; cvt.u32.u64 %0, t; }"
        : "=r"(a) : "l"(p));
    return a;
}
__device__ __forceinline__ void cp_async16(uint32_t dst, const void* src, int sz) {
    asm volatile("cp.async.cg.shared.global [%0], [%1], 16, %2;"
                 :: "r"(dst), "l"(src), "r"(sz) : "memory");
}
__device__ __forceinline__ void cp_commit() {
    asm volatile("cp.async.commit_group;" ::: "memory");
}
__device__ __forceinline__ void cp_wait0() {
    asm volatile("cp.async.wait_group 0;" ::: "memory");
}
__device__ __forceinline__ void split1(float v, __half& h, __half& l) {
    h = __float2half_rn(v);
    l = __float2half_rn(v - __half2float(h));
}
__device__ __forceinline__ uint32_t pack2(__half a, __half b) {
    __half2 t = __halves2half2(a, b);
    return *reinterpret_cast<uint32_t*>(&t);
}
__device__ __forceinline__ float2 h2f(uint32_t w) {
    __half2 t = *reinterpret_cast<__half2*>(&w);
    return __half22float2(t);
}
__device__ __forceinline__ void mma16816(float* c, const uint32_t* a,
                                         uint32_t b0, uint32_t b1) {
    asm("mma.sync.aligned.m16n8k16.row.col.f32.f16.f16.f32 "
        "{%0,%1,%2,%3}, {%4,%5,%6,%7}, {%8,%9}, {%0,%1,%2,%3};"
        : "+f"(c[0]), "+f"(c[1]), "+f"(c[2]), "+f"(c[3])
        : "r"(a[0]), "r"(a[1]), "r"(a[2]), "r"(a[3]), "r"(b0), "r"(b1));
}
#define LDX4(r, addr) \
    asm volatile("ldmatrix.sync.aligned.m8n8.x4.shared.b16 {%0,%1,%2,%3}, [%4];" \
                 : "=r"((r)[0]), "=r"((r)[1]), "=r"((r)[2]), "=r"((r)[3])        \
                 : "r"(addr))

// ---------------- CSR build (fused across both layers) -----------------------
__global__ void zero_both(int* __restrict__ c1, int* __restrict__ c2) {
    int i = blockIdx.x * blockDim.x + threadIdx.x;
    if (i < N1) c1[i] = 0;
    else if (i < N1 + N2) c2[i - N1] = 0;
}
__global__ void hist_both(const int* __restrict__ d1, const int* __restrict__ d2,
                          int* __restrict__ c1, int* __restrict__ c2) {
    int e = blockIdx.x * blockDim.x + threadIdx.x;
    if (e < E1) atomicAdd(&c1[d1[e]], 1);
    else if (e < E1 + E2) atomicAdd(&c2[d2[e - E1]], 1);
}
__global__ __launch_bounds__(1024) void scan_both(
    const int* __restrict__ c1, int* __restrict__ r1, int* __restrict__ p1,
    const int* __restrict__ c2, int* __restrict__ r2, int* __restrict__ p2) {
    const int n = blockIdx.x ? N2 : N1;
    const int* cnt = blockIdx.x ? c2 : c1;
    int* rowptr = blockIdx.x ? r2 : r1;
    int* pos    = blockIdx.x ? p2 : p1;
    __shared__ int ts[1024];
    const int t = threadIdx.x;
    const int C = (n + 1023) >> 10;
    int local[20];
    int s = 0;
    for (int j = 0; j < C; ++j) {
        int idx = t * C + j;
        int v = (idx < n) ? cnt[idx] : 0;
        local[j] = s; s += v;
    }
    ts[t] = s;
    __syncthreads();
    for (int off = 1; off < 1024; off <<= 1) {
        int v = (t >= off) ? ts[t - off] : 0;
        __syncthreads();
        ts[t] += v;
        __syncthreads();
    }
    int base = (t > 0) ? ts[t - 1] : 0;
    for (int j = 0; j < C; ++j) {
        int idx = t * C + j;
        if (idx < n) { int r = base + local[j]; rowptr[idx] = r; pos[idx] = r; }
    }
    if (t == 1023) rowptr[n] = ts[1023];
}
__global__ void fill_both(const int* __restrict__ d1, const int* __restrict__ s1,
                          int* __restrict__ p1, int* __restrict__ e1,
                          const int* __restrict__ d2, const int* __restrict__ s2,
                          int* __restrict__ p2, int* __restrict__ e2) {
    int e = blockIdx.x * blockDim.x + threadIdx.x;
    if (e < E1) {
        int p = atomicAdd(&p1[d1[e]], 1);
        e1[p] = s1[e];
    } else if (e < E1 + E2) {
        int q = e - E1;
        int p = atomicAdd(&p2[d2[q]], 1);
        e2[p] = s2[q];
    }
}

// ---------------- gather (fp32 src) + fp16 split, dynamic rows ---------------
#define GROWS 16
__global__ void gather_split(const float* __restrict__ X,
                             const int* __restrict__ esrc,
                             const int* __restrict__ rowptr, int nrows,
                             __half* __restrict__ Ah, __half* __restrict__ Al) {
    __shared__ int cur;
    if (threadIdx.x == 0) cur = 0;
    __syncthreads();
    const int base = blockIdx.x * GROWS;
    const int lane = threadIdx.x & 31;
    for (;;) {
        int r = 0;
        if (lane == 0) r = atomicAdd(&cur, 1);
        r = __shfl_sync(0xFFFFFFFFu, r, 0);
        if (r >= GROWS) break;
        int row = base + r;
        if (row >= nrows) break;
        const int beg = rowptr[row], end = rowptr[row + 1];
        float4 a0 = make_float4(0.f, 0.f, 0.f, 0.f), a1 = a0, a2 = a0, a3 = a0;
        float4 b0 = a0, b1 = a0, b2 = a0, b3 = a0;
        int i = beg;
        for (; i + 2 <= end; i += 2) {
            const float4* r0 = (const float4*)(X + (size_t)__ldg(&esrc[i]) * FH);
            const float4* r1 = (const float4*)(X + (size_t)__ldg(&esrc[i + 1]) * FH);
            float4 u0 = r0[lane], u1 = r0[lane + 32], u2 = r0[lane + 64], u3 = r0[lane + 96];
            float4 w0 = r1[lane], w1 = r1[lane + 32], w2 = r1[lane + 64], w3 = r1[lane + 96];
            a0.x += u0.x; a0.y += u0.y; a0.z += u0.z; a0.w += u0.w;
            a1.x += u1.x; a1.y += u1.y; a1.z += u1.z; a1.w += u1.w;
            a2.x += u2.x; a2.y += u2.y; a2.z += u2.z; a2.w += u2.w;
            a3.x += u3.x; a3.y += u3.y; a3.z += u3.z; a3.w += u3.w;
            b0.x += w0.x; b0.y += w0.y; b0.z += w0.z; b0.w += w0.w;
            b1.x += w1.x; b1.y += w1.y; b1.z += w1.z; b1.w += w1.w;
            b2.x += w2.x; b2.y += w2.y; b2.z += w2.z; b2.w += w2.w;
            b3.x += w3.x; b3.y += w3.y; b3.z += w3.z; b3.w += w3.w;
        }
        if (i < end) {
            const float4* r0 = (const float4*)(X + (size_t)__ldg(&esrc[i]) * FH);
            float4 u0 = r0[lane], u1 = r0[lane + 32], u2 = r0[lane + 64], u3 = r0[lane + 96];
            a0.x += u0.x; a0.y += u0.y; a0.z += u0.z; a0.w += u0.w;
            a1.x += u1.x; a1.y += u1.y; a1.z += u1.z; a1.w += u1.w;
            a2.x += u2.x; a2.y += u2.y; a2.z += u2.z; a2.w += u2.w;
            a3.x += u3.x; a3.y += u3.y; a3.z += u3.z; a3.w += u3.w;
        }
        a0.x += b0.x; a0.y += b0.y; a0.z += b0.z; a0.w += b0.w;
        a1.x += b1.x; a1.y += b1.y; a1.z += b1.z; a1.w += b1.w;
        a2.x += b2.x; a2.y += b2.y; a2.z += b2.z; a2.w += b2.w;
        a3.x += b3.x; a3.y += b3.y; a3.z += b3.z; a3.w += b3.w;
        float4 acc[4] = {a0, a1, a2, a3};
#pragma unroll
        for (int q = 0; q < 4; ++q) {
            __half h0, h1, h2, h3, l0, l1, l2, l3;
            split1(acc[q].x, h0, l0); split1(acc[q].y, h1, l1);
            split1(acc[q].z, h2, l2); split1(acc[q].w, h3, l3);
            size_t o = (size_t)row * FH + 4 * (lane + 32 * q);
            *(uint2*)(Ah + o) = make_uint2(pack2(h0, h1), pack2(h2, h3));
            *(uint2*)(Al + o) = make_uint2(pack2(l0, l1), pack2(l2, l3));
        }
    }
}

// ---------------- gather (fp16 hi/lo src) + fp16 split, dynamic rows ---------
__global__ void gather_f16_split(const __half* __restrict__ Xh,
                                 const __half* __restrict__ Xl,
                                 const int* __restrict__ esrc,
                                 const int* __restrict__ rowptr, int nrows,
                                 __half* __restrict__ Ah, __half* __restrict__ Al) {
    __shared__ int cur;
    if (threadIdx.x == 0) cur = 0;
    __syncthreads();
    const int base = blockIdx.x * GROWS;
    const int lane = threadIdx.x & 31;
    for (;;) {
        int r = 0;
        if (lane == 0) r = atomicAdd(&cur, 1);
        r = __shfl_sync(0xFFFFFFFFu, r, 0);
        if (r >= GROWS) break;
        int row = base + r;
        if (row >= nrows) break;
        const int beg = rowptr[row], end = rowptr[row + 1];
        float acc[16];
#pragma unroll
        for (int j = 0; j < 16; ++j) acc[j] = 0.f;
        for (int i = beg; i < end; ++i) {
            size_t b = (size_t)__ldg(&esrc[i]) * FH + lane * 16;
            uint4 H0 = *(const uint4*)(Xh + b);
            uint4 H1 = *(const uint4*)(Xh + b + 8);
            uint4 L0 = *(const uint4*)(Xl + b);
            uint4 L1 = *(const uint4*)(Xl + b + 8);
            uint32_t hw[8] = {H0.x, H0.y, H0.z, H0.w, H1.x, H1.y, H1.z, H1.w};
            uint32_t lw[8] = {L0.x, L0.y, L0.z, L0.w, L1.x, L1.y, L1.z, L1.w};
#pragma unroll
            for (int j = 0; j < 8; ++j) {
                float2 hh = h2f(hw[j]), ll = h2f(lw[j]);
                acc[2 * j]     += hh.x + ll.x;
                acc[2 * j + 1] += hh.y + ll.y;
            }
        }
        uint32_t hp[8], lp[8];
#pragma unroll
        for (int j = 0; j < 8; ++j) {
            __half h0, h1, l0, l1;
            split1(acc[2 * j], h0, l0);
            split1(acc[2 * j + 1], h1, l1);
            hp[j] = pack2(h0, h1);
            lp[j] = pack2(l0, l1);
        }
        size_t o = (size_t)row * FH + lane * 16;
        *(uint4*)(Ah + o)     = make_uint4(hp[0], hp[1], hp[2], hp[3]);
        *(uint4*)(Ah + o + 8) = make_uint4(hp[4], hp[5], hp[6], hp[7]);
        *(uint4*)(Al + o)     = make_uint4(lp[0], lp[1], lp[2], lp[3]);
        *(uint4*)(Al + o + 8) = make_uint4(lp[4], lp[5], lp[6], lp[7]);
    }
}

// ---------------- fp32 -> fp16 hi/lo split -----------------------------------
__global__ void split_f32(const float4* __restrict__ in,
                          uint2* __restrict__ hi, uint2* __restrict__ lo, int n4) {
    int i = blockIdx.x * blockDim.x + threadIdx.x;
    if (i >= n4) return;
    float4 v = in[i];
    __half h0, h1, h2, h3, l0, l1, l2, l3;
    split1(v.x, h0, l0); split1(v.y, h1, l1);
    split1(v.z, h2, l2); split1(v.w, h3, l3);
    hi[i] = make_uint2(pack2(h0, h1), pack2(h2, h3));
    lo[i] = make_uint2(pack2(l0, l1), pack2(l2, l3));
}

// ---------------- weight transpose + split (fused over 4 weights) ------------
__global__ void transpose_split4(const float* __restrict__ W0,
                                 const float* __restrict__ W1,
                                 const float* __restrict__ W2,
                                 const float* __restrict__ W3,
                                 __half* __restrict__ Wt) {
    __shared__ float t[32][33];
    const float* W = (blockIdx.z == 0) ? W0 : (blockIdx.z == 1) ? W1
                   : (blockIdx.z == 2) ? W2 : W3;
    __half* Bh = Wt + (size_t)(2 * blockIdx.z) * FH * FH;
    __half* Bl = Bh + (size_t)FH * FH;
    int n0 = blockIdx.x * 32, k0 = blockIdx.y * 32;
    int tx = threadIdx.x, ty = threadIdx.y;
    for (int yy = ty; yy < 32; yy += 8)
        t[yy][tx] = W[(size_t)(k0 + yy) * FH + n0 + tx];
    __syncthreads();
    for (int yy = ty; yy < 32; yy += 8) {
        float v = t[tx][yy];
        size_t o = (size_t)(n0 + yy) * FH + k0 + tx;
        __half h, l;
        split1(v, h, l);
        Bh[o] = h; Bl[o] = l;
    }
}

// ---------------- head fold + head ------------------------------------------
__global__ void wcomb_kernel(const float* __restrict__ Wlin,
                             const float* __restrict__ Whead,
                             const float* __restrict__ blin,
                             const float* __restrict__ bhead,
                             float* __restrict__ Wcomb, float* __restrict__ bcomb) {
    int k = blockIdx.x;
    int lane = threadIdx.x;
    const float* rowv = (k < FH) ? (Wlin + (size_t)k * FH) : blin;
    float acc[C_OUT];
#pragma unroll
    for (int c = 0; c < C_OUT; ++c) acc[c] = 0.f;
    for (int j = lane; j < FH; j += 32) {
        float v = rowv[j];
        const float* w = Whead + (size_t)j * C_OUT;
#pragma unroll
        for (int c = 0; c < C_OUT; ++c) acc[c] += v * w[c];
    }
#pragma unroll
    for (int off = 16; off > 0; off >>= 1)
#pragma unroll
        for (int c = 0; c < C_OUT; ++c)
            acc[c] += __shfl_down_sync(0xFFFFFFFFu, acc[c], off);
    if (lane == 0) {
        if (k < FH) {
#pragma unroll
            for (int c = 0; c < C_OUT; ++c) Wcomb[(size_t)k * C_OUT + c] = acc[c];
        } else {
#pragma unroll
            for (int c = 0; c < C_OUT; ++c) bcomb[c] = acc[c] + bhead[c];
        }
    }
}

__global__ void head_kernel(const float* __restrict__ h2,
                            const float* __restrict__ Wcomb,
                            const float* __restrict__ bcomb,
                            float* __restrict__ out) {
    int r = blockIdx.x;
    int lane = threadIdx.x;
    float acc[C_OUT];
#pragma unroll
    for (int c = 0; c < C_OUT; ++c) acc[c] = 0.f;
    const float* trow = h2 + (size_t)r * FH;
    for (int k = lane; k < FH; k += 32) {
        float t = trow[k];
        const float* w = Wcomb + (size_t)k * C_OUT;
#pragma unroll
        for (int c = 0; c < C_OUT; ++c) acc[c] += t * w[c];
    }
#pragma unroll
    for (int off = 16; off > 0; off >>= 1)
#pragma unroll
        for (int c = 0; c < C_OUT; ++c)
            acc[c] += __shfl_down_sync(0xFFFFFFFFu, acc[c], off);
    if (lane == 0) {
#pragma unroll
        for (int c = 0; c < C_OUT; ++c) out[(size_t)r * C_OUT + c] = acc[c] + bcomb[c];
    }
}

// ---------------- HMMA fp16-split dual-source GEMM ---------------------------
// NC=2: C = AhBh + AlBh (fp16 2-term, err ~2^-12)
// NC=3: C = AhBh + AlBh + AhBl (err ~2^-22)
#define SA 40

template <bool RELU, bool SPLIT, bool WF32, int NC>
__global__ __launch_bounds__(256) void gemm_mma(
    const __half* __restrict__ A0h, const __half* __restrict__ A0l,
    const __half* __restrict__ A1h, const __half* __restrict__ A1l,
    const __half* __restrict__ B0h, const __half* __restrict__ B0l,
    const __half* __restrict__ B1h, const __half* __restrict__ B1l,
    const float* __restrict__ bias, float* __restrict__ Cout,
    __half* __restrict__ Ch, __half* __restrict__ Cl, int M) {
    extern __shared__ __half sm[];
    constexpr int NT = (NC == 3) ? 4 : 3;  // tiles per stage
    const int tid = threadIdx.x;
    const int lane = tid & 31;
    const int wid = tid >> 5;
    const int wm = wid & 3;
    const int wn = wid >> 2;
    const int m0 = blockIdx.y * 128;
    const int n0 = blockIdx.x * 128;

    const __half* APs[2][2] = {{A0h, A0l}, {A1h, A1l}};
    const __half* BPs[2][2] = {{B0h, B0l}, {B1h, B1l}};

    float acc[2][8][4];
#pragma unroll
    for (int i = 0; i < 2; ++i)
#pragma unroll
        for (int j = 0; j < 8; ++j)
#pragma unroll
            for (int q = 0; q < 4; ++q) acc[i][j][q] = 0.f;

    const int r0 = tid >> 2;
    const int c8 = (tid & 3) * 8;

    auto tile_off = [&](int buf, int t, int row, int col) -> uint32_t {
        return (uint32_t)((((buf * NT + t) * 128 + row) * SA + col) * 2);
    };
    const uint32_t smb = smem_u32(sm);

    constexpr int NST = 32;
    auto issue = [&](int buf, int s) {
        const int src = s >> 4;
        const int k0 = (s & 15) * 32;
#pragma unroll
        for (int t = 0; t < NT; ++t) {
            const __half* P = (t < 2) ? APs[src][t] : BPs[src][t - 2];
#pragma unroll
            for (int i = 0; i < 2; ++i) {
                int row = r0 + i * 64;
                int sz = 16;
                int gr;
                if (t < 2) { gr = m0 + row; if (gr >= M) sz = 0; }
                else       { gr = n0 + row; }
                cp_async16(smb + tile_off(buf, t, row, c8),
                           P + (size_t)gr * FH + k0 + c8, sz);
            }
        }
        cp_commit();
    };

    issue(0, 0);

    const int lrow = lane & 15;
    const int lcol = (lane >> 4) << 3;
    const int fr = lane >> 2;
    const int fc = (lane & 3) * 2;

#pragma unroll 1
    for (int s = 0; s < NST; ++s) {
        cp_wait0();
        __syncthreads();
        if (s + 1 < NST) issue((s + 1) & 1, s + 1);
        const int buf = s & 1;
#pragma unroll
        for (int kk = 0; kk < 32; kk += 16) {
            uint32_t ah[2][4], al[2][4], bb[4][4];
#pragma unroll
            for (int mi = 0; mi < 2; ++mi) {
                int rb = wm * 32 + mi * 16 + lrow;
                LDX4(ah[mi], smb + tile_off(buf, 0, rb, kk + lcol));
                LDX4(al[mi], smb + tile_off(buf, 1, rb, kk + lcol));
            }
#pragma unroll
            for (int np = 0; np < 4; ++np) {
                int nb = wn * 64 + np * 16 + lrow;
                LDX4(bb[np], smb + tile_off(buf, 2, nb, kk + lcol));
            }
#pragma unroll
            for (int np = 0; np < 4; ++np) {
#pragma unroll
                for (int mi = 0; mi < 2; ++mi) {
                    mma16816(acc[mi][2 * np],     ah[mi], bb[np][0], bb[np][2]);
                    mma16816(acc[mi][2 * np + 1], ah[mi], bb[np][1], bb[np][3]);
                    mma16816(acc[mi][2 * np],     al[mi], bb[np][0], bb[np][2]);
                    mma16816(acc[mi][2 * np + 1], al[mi], bb[np][1], bb[np][3]);
                }
            }
            if (NC == 3) {
#pragma unroll
                for (int np = 0; np < 4; ++np) {
                    int nb = wn * 64 + np * 16 + lrow;
                    LDX4(bb[np], smb + tile_off(buf, 3, nb, kk + lcol));
                }
#pragma unroll
                for (int np = 0; np < 4; ++np) {
#pragma unroll
                    for (int mi = 0; mi < 2; ++mi) {
                        mma16816(acc[mi][2 * np],     ah[mi], bb[np][0], bb[np][2]);
                        mma16816(acc[mi][2 * np + 1], ah[mi], bb[np][1], bb[np][3]);
                    }
                }
            }
        }
        __syncthreads();
    }

    // -------- epilogue --------
#pragma unroll
    for (int mi = 0; mi < 2; ++mi) {
#pragma unroll
        for (int half = 0; half < 2; ++half) {
            int row = m0 + wm * 32 + mi * 16 + fr + half * 8;
            if (row >= M) continue;
#pragma unroll
            for (int ni = 0; ni < 8; ++ni) {
                int col = n0 + wn * 64 + ni * 8 + fc;
                float v0 = acc[mi][ni][half * 2 + 0] + bias[col];
                float v1 = acc[mi][ni][half * 2 + 1] + bias[col + 1];
                if (RELU) { v0 = fmaxf(v0, 0.f); v1 = fmaxf(v1, 0.f); }
                if (WF32)
                    *(float2*)(Cout + (size_t)row * FH + col) = make_float2(v0, v1);
                if (SPLIT) {
                    __half h0, h1, l0, l1;
                    split1(v0, h0, l0); split1(v1, h1, l1);
                    *(uint32_t*)(Ch + (size_t)row * FH + col) = pack2(h0, h1);
                    *(uint32_t*)(Cl + (size_t)row * FH + col) = pack2(l0, l1);
                }
            }
        }
    }
}

// ---------------------------------------------------------------------------
extern "C" void kernel_launch(void* const* d_in, const int* in_sizes, int n_in,
                              void* d_out, int out_size) {
    const float* x     = (const float*)d_in[0];
    const int*   src1  = (const int*)  d_in[1];
    const int*   dst1  = (const int*)  d_in[2];
    const int*   src2  = (const int*)  d_in[3];
    const int*   dst2  = (const int*)  d_in[4];
    const float* Wrel1 = (const float*)d_in[5];
    const float* brel1 = (const float*)d_in[6];
    const float* Wroot1= (const float*)d_in[7];
    const float* Wrel2 = (const float*)d_in[8];
    const float* brel2 = (const float*)d_in[9];
    const float* Wroot2= (const float*)d_in[10];
    const float* Wlin  = (const float*)d_in[11];
    const float* blin  = (const float*)d_in[12];
    const float* Whead = (const float*)d_in[13];
    const float* bhead = (const float*)d_in[14];
    float* out = (float*)d_out;

    float *h2, *Wcomb, *bcomb;
    __half *A1h, *A1l, *A2h, *A2l, *Hh, *Hl, *G2h, *G2l, *Wt;
    int *cnt1, *rp1, *pos1, *esrc1, *cnt2, *rp2, *pos2, *esrc2;
    cudaGetSymbolAddress((void**)&h2,   g_h2);
    cudaGetSymbolAddress((void**)&A1h,  g_A1h);
    cudaGetSymbolAddress((void**)&A1l,  g_A1l);
    cudaGetSymbolAddress((void**)&A2h,  g_A2h);
    cudaGetSymbolAddress((void**)&A2l,  g_A2l);
    cudaGetSymbolAddress((void**)&Hh,   g_Hh);
    cudaGetSymbolAddress((void**)&Hl,   g_Hl);
    cudaGetSymbolAddress((void**)&G2h,  g_G2h);
    cudaGetSymbolAddress((void**)&G2l,  g_G2l);
    cudaGetSymbolAddress((void**)&Wt,   g_Wt);
    cudaGetSymbolAddress((void**)&Wcomb, g_Wcomb);
    cudaGetSymbolAddress((void**)&bcomb, g_bcomb);
    cudaGetSymbolAddress((void**)&cnt1, g_cnt1);
    cudaGetSymbolAddress((void**)&rp1,  g_rp1);
    cudaGetSymbolAddress((void**)&pos1, g_pos1);
    cudaGetSymbolAddress((void**)&esrc1, g_esrc1);
    cudaGetSymbolAddress((void**)&cnt2, g_cnt2);
    cudaGetSymbolAddress((void**)&rp2,  g_rp2);
    cudaGetSymbolAddress((void**)&pos2, g_pos2);
    cudaGetSymbolAddress((void**)&esrc2, g_esrc2);
    __half* WtP[8];
    for (int i = 0; i < 8; ++i) WtP[i] = Wt + (size_t)i * FH * FH;

    constexpr int GSMEM2 = 2 * 3 * 128 * SA * 2;  // 61440 B (NC=2)
    constexpr int GSMEM3 = 2 * 4 * 128 * SA * 2;  // 81920 B (NC=3)
    cudaFuncSetAttribute(gemm_mma<true, true, false, 2>,
                         cudaFuncAttributeMaxDynamicSharedMemorySize, GSMEM2);
    cudaFuncSetAttribute(gemm_mma<false, false, true, 3>,
                         cudaFuncAttributeMaxDynamicSharedMemorySize, GSMEM3);

    // ---- CSR build (fused) ----
    zero_both<<<(N1 + N2 + 255) / 256, 256>>>(cnt1, cnt2);
    hist_both<<<(E1 + E2 + 255) / 256, 256>>>(dst1, dst2, cnt1, cnt2);
    scan_both<<<2, 1024>>>(cnt1, rp1, pos1, cnt2, rp2, pos2);
    fill_both<<<(E1 + E2 + 255) / 256, 256>>>(dst1, src1, pos1, esrc1,
                                              dst2, src2, pos2, esrc2);

    // ---- splits / weight prep ----
    {
        int n4 = (N1 * FH) / 4;
        split_f32<<<(n4 + 255) / 256, 256>>>((const float4*)x, (uint2*)A2h, (uint2*)A2l, n4);
        dim3 g(16, 16, 4), b(32, 8);
        transpose_split4<<<g, b>>>(Wrel1, Wroot1, Wrel2, Wroot2, Wt);
        wcomb_kernel<<<FH + 1, 32>>>(Wlin, Whead, blin, bhead, Wcomb, bcomb);
    }

    // ---- layer 1 ----
    gather_split<<<(N1 + GROWS - 1) / GROWS, 256>>>(x, esrc1, rp1, N1, A1h, A1l);
    {
        dim3 grid(FH / 128, (N1 + 127) / 128);
        gemm_mma<true, true, false, 2><<<grid, 256, GSMEM2>>>(
            A1h, A1l, A2h, A2l, WtP[0], WtP[1], WtP[2], WtP[3],
            brel1, nullptr, Hh, Hl, N1);
    }

    // ---- layer 2 ----
    gather_f16_split<<<(N2 + GROWS - 1) / GROWS, 256>>>(Hh, Hl, esrc2, rp2, N2, G2h, G2l);
    {
        dim3 grid(FH / 128, (N2 + 127) / 128);
        gemm_mma<false, false, true, 3><<<grid, 256, GSMEM3>>>(
            G2h, G2l, Hh, Hl, WtP[4], WtP[5], WtP[6], WtP[7],
            brel2, h2, nullptr, nullptr, N2);
    }

    // ---- head ----
    head_kernel<<<N2, 32>>>(h2, Wcomb, bcomb, out);

    (void)in_sizes; (void)n_in; (void)out_size;
}

// round 8
// speedup vs baseline: 4.2209x; 1.1803x over previous
#include <cuda_runtime.h>
#include <cuda_fp16.h>
#include <cstdint>

#define N0 100000
#define N1 20000
#define N2 4000
#define E1 500000
#define E2 100000
#define FH 512
#define C_OUT 10

// ---------------- scratch ---------------------------------------------------
__device__ float g_h2[(size_t)N2 * FH];

__device__ __half g_Xh [(size_t)N0 * FH];                         // fp16 hi of x (all rows)
__device__ __half g_A2l[(size_t)N1 * FH];                         // fp16 lo of x[:N1]
__device__ __half g_A1h[(size_t)N1 * FH];                         // agg1 (fp16)
__device__ __half g_Hh [(size_t)N1 * FH], g_Hl [(size_t)N1 * FH]; // h split
__device__ __half g_G2h[(size_t)N2 * FH], g_G2l[(size_t)N2 * FH]; // agg2 split
__device__ __half g_Wt[8][(size_t)FH * FH];
__device__ float g_Wcomb[(size_t)FH * C_OUT];
__device__ float g_bcomb[C_OUT];

// CSR scratch
__device__ int g_cnt1[N1], g_rp1[N1 + 1], g_pos1[N1], g_esrc1[E1];
__device__ int g_cnt2[N2], g_rp2[N2 + 1], g_pos2[N2], g_esrc2[E2];

// ---------------- helpers ---------------------------------------------------
__device__ __forceinline__ uint32_t smem_u32(const void* p) {
    uint32_t a;
    asm("{ .reg .u64 t; cvta.to.shared.u64 t, %1; cvt.u32.u64 %0, t; }"
        : "=r"(a) : "l"(p));
    return a;
}
__device__ __forceinline__ void cp_async16(uint32_t dst, const void* src, int sz) {
    asm volatile("cp.async.cg.shared.global [%0], [%1], 16, %2;"
                 :: "r"(dst), "l"(src), "r"(sz) : "memory");
}
__device__ __forceinline__ void cp_commit() {
    asm volatile("cp.async.commit_group;" ::: "memory");
}
__device__ __forceinline__ void cp_wait0() {
    asm volatile("cp.async.wait_group 0;" ::: "memory");
}
__device__ __forceinline__ void split1(float v, __half& h, __half& l) {
    h = __float2half_rn(v);
    l = __float2half_rn(v - __half2float(h));
}
__device__ __forceinline__ uint32_t pack2(__half a, __half b) {
    __half2 t = __halves2half2(a, b);
    return *reinterpret_cast<uint32_t*>(&t);
}
__device__ __forceinline__ float2 h2f(uint32_t w) {
    __half2 t = *reinterpret_cast<__half2*>(&w);
    return __half22float2(t);
}
__device__ __forceinline__ void mma16816(float* c, const uint32_t* a,
                                         uint32_t b0, uint32_t b1) {
    asm("mma.sync.aligned.m16n8k16.row.col.f32.f16.f16.f32 "
        "{%0,%1,%2,%3}, {%4,%5,%6,%7}, {%8,%9}, {%0,%1,%2,%3};"
        : "+f"(c[0]), "+f"(c[1]), "+f"(c[2]), "+f"(c[3])
        : "r"(a[0]), "r"(a[1]), "r"(a[2]), "r"(a[3]), "r"(b0), "r"(b1));
}
#define LDX4(r, addr) \
    asm volatile("ldmatrix.sync.aligned.m8n8.x4.shared.b16 {%0,%1,%2,%3}, [%4];" \
                 : "=r"((r)[0]), "=r"((r)[1]), "=r"((r)[2]), "=r"((r)[3])        \
                 : "r"(addr))

// ---------------- CSR build (fused across both layers) -----------------------
__global__ void zero_both(int* __restrict__ c1, int* __restrict__ c2) {
    int i = blockIdx.x * blockDim.x + threadIdx.x;
    if (i < N1) c1[i] = 0;
    else if (i < N1 + N2) c2[i - N1] = 0;
}
__global__ void hist_both(const int* __restrict__ d1, const int* __restrict__ d2,
                          int* __restrict__ c1, int* __restrict__ c2) {
    int e = blockIdx.x * blockDim.x + threadIdx.x;
    if (e < E1) atomicAdd(&c1[d1[e]], 1);
    else if (e < E1 + E2) atomicAdd(&c2[d2[e - E1]], 1);
}
__global__ __launch_bounds__(1024) void scan_both(
    const int* __restrict__ c1, int* __restrict__ r1, int* __restrict__ p1,
    const int* __restrict__ c2, int* __restrict__ r2, int* __restrict__ p2) {
    const int n = blockIdx.x ? N2 : N1;
    const int* cnt = blockIdx.x ? c2 : c1;
    int* rowptr = blockIdx.x ? r2 : r1;
    int* pos    = blockIdx.x ? p2 : p1;
    __shared__ int ts[1024];
    const int t = threadIdx.x;
    const int C = (n + 1023) >> 10;
    int local[20];
    int s = 0;
    for (int j = 0; j < C; ++j) {
        int idx = t * C + j;
        int v = (idx < n) ? cnt[idx] : 0;
        local[j] = s; s += v;
    }
    ts[t] = s;
    __syncthreads();
    for (int off = 1; off < 1024; off <<= 1) {
        int v = (t >= off) ? ts[t - off] : 0;
        __syncthreads();
        ts[t] += v;
        __syncthreads();
    }
    int base = (t > 0) ? ts[t - 1] : 0;
    for (int j = 0; j < C; ++j) {
        int idx = t * C + j;
        if (idx < n) { int r = base + local[j]; rowptr[idx] = r; pos[idx] = r; }
    }
    if (t == 1023) rowptr[n] = ts[1023];
}
__global__ void fill_both(const int* __restrict__ d1, const int* __restrict__ s1,
                          int* __restrict__ p1, int* __restrict__ e1,
                          const int* __restrict__ d2, const int* __restrict__ s2,
                          int* __restrict__ p2, int* __restrict__ e2) {
    int e = blockIdx.x * blockDim.x + threadIdx.x;
    if (e < E1) {
        int p = atomicAdd(&p1[d1[e]], 1);
        e1[p] = s1[e];
    } else if (e < E1 + E2) {
        int q = e - E1;
        int p = atomicAdd(&p2[d2[q]], 1);
        e2[p] = s2[q];
    }
}

// ---------------- x -> fp16 conversion (hi for all, lo for first N1 rows) ----
__global__ void convert_x(const float4* __restrict__ x4,
                          uint4* __restrict__ Xh4, uint4* __restrict__ Xl4) {
    int i = blockIdx.x * blockDim.x + threadIdx.x;   // 8-float chunk index
    if (i >= (N0 * FH) / 8) return;
    float4 v0 = x4[2 * i], v1 = x4[2 * i + 1];
    __half h[8], l[8];
    split1(v0.x, h[0], l[0]); split1(v0.y, h[1], l[1]);
    split1(v0.z, h[2], l[2]); split1(v0.w, h[3], l[3]);
    split1(v1.x, h[4], l[4]); split1(v1.y, h[5], l[5]);
    split1(v1.z, h[6], l[6]); split1(v1.w, h[7], l[7]);
    Xh4[i] = make_uint4(pack2(h[0], h[1]), pack2(h[2], h[3]),
                        pack2(h[4], h[5]), pack2(h[6], h[7]));
    if (i < (N1 * FH) / 8)
        Xl4[i] = make_uint4(pack2(l[0], l[1]), pack2(l[2], l[3]),
                            pack2(l[4], l[5]), pack2(l[6], l[7]));
}

// ---------------- gather (fp16 hi src) -> fp16 agg, dynamic rows -------------
#define GROWS 16
__global__ void gather_hi(const __half* __restrict__ Xh,
                          const int* __restrict__ esrc,
                          const int* __restrict__ rowptr, int nrows,
                          __half* __restrict__ Ah) {
    __shared__ int cur;
    if (threadIdx.x == 0) cur = 0;
    __syncthreads();
    const int base = blockIdx.x * GROWS;
    const int lane = threadIdx.x & 31;
    for (;;) {
        int r = 0;
        if (lane == 0) r = atomicAdd(&cur, 1);
        r = __shfl_sync(0xFFFFFFFFu, r, 0);
        if (r >= GROWS) break;
        int row = base + r;
        if (row >= nrows) break;
        const int beg = rowptr[row], end = rowptr[row + 1];
        float acc[16];
#pragma unroll
        for (int j = 0; j < 16; ++j) acc[j] = 0.f;
        int i = beg;
        for (; i + 2 <= end; i += 2) {
            size_t b0 = (size_t)__ldg(&esrc[i]) * FH + lane * 16;
            size_t b1 = (size_t)__ldg(&esrc[i + 1]) * FH + lane * 16;
            uint4 U0 = *(const uint4*)(Xh + b0);
            uint4 U1 = *(const uint4*)(Xh + b0 + 8);
            uint4 V0 = *(const uint4*)(Xh + b1);
            uint4 V1 = *(const uint4*)(Xh + b1 + 8);
            uint32_t uw[8] = {U0.x, U0.y, U0.z, U0.w, U1.x, U1.y, U1.z, U1.w};
            uint32_t vw[8] = {V0.x, V0.y, V0.z, V0.w, V1.x, V1.y, V1.z, V1.w};
#pragma unroll
            for (int j = 0; j < 8; ++j) {
                float2 a = h2f(uw[j]), b = h2f(vw[j]);
                acc[2 * j]     += a.x + b.x;
                acc[2 * j + 1] += a.y + b.y;
            }
        }
        if (i < end) {
            size_t b0 = (size_t)__ldg(&esrc[i]) * FH + lane * 16;
            uint4 U0 = *(const uint4*)(Xh + b0);
            uint4 U1 = *(const uint4*)(Xh + b0 + 8);
            uint32_t uw[8] = {U0.x, U0.y, U0.z, U0.w, U1.x, U1.y, U1.z, U1.w};
#pragma unroll
            for (int j = 0; j < 8; ++j) {
                float2 a = h2f(uw[j]);
                acc[2 * j]     += a.x;
                acc[2 * j + 1] += a.y;
            }
        }
        uint32_t hp[8];
#pragma unroll
        for (int j = 0; j < 8; ++j)
            hp[j] = pack2(__float2half_rn(acc[2 * j]), __float2half_rn(acc[2 * j + 1]));
        size_t o = (size_t)row * FH + lane * 16;
        *(uint4*)(Ah + o)     = make_uint4(hp[0], hp[1], hp[2], hp[3]);
        *(uint4*)(Ah + o + 8) = make_uint4(hp[4], hp[5], hp[6], hp[7]);
    }
}

// ---------------- gather (fp16 hi/lo src) + fp16 split, dynamic rows ---------
__global__ void gather_f16_split(const __half* __restrict__ Xh,
                                 const __half* __restrict__ Xl,
                                 const int* __restrict__ esrc,
                                 const int* __restrict__ rowptr, int nrows,
                                 __half* __restrict__ Ah, __half* __restrict__ Al) {
    __shared__ int cur;
    if (threadIdx.x == 0) cur = 0;
    __syncthreads();
    const int base = blockIdx.x * GROWS;
    const int lane = threadIdx.x & 31;
    for (;;) {
        int r = 0;
        if (lane == 0) r = atomicAdd(&cur, 1);
        r = __shfl_sync(0xFFFFFFFFu, r, 0);
        if (r >= GROWS) break;
        int row = base + r;
        if (row >= nrows) break;
        const int beg = rowptr[row], end = rowptr[row + 1];
        float acc[16];
#pragma unroll
        for (int j = 0; j < 16; ++j) acc[j] = 0.f;
        for (int i = beg; i < end; ++i) {
            size_t b = (size_t)__ldg(&esrc[i]) * FH + lane * 16;
            uint4 H0 = *(const uint4*)(Xh + b);
            uint4 H1 = *(const uint4*)(Xh + b + 8);
            uint4 L0 = *(const uint4*)(Xl + b);
            uint4 L1 = *(const uint4*)(Xl + b + 8);
            uint32_t hw[8] = {H0.x, H0.y, H0.z, H0.w, H1.x, H1.y, H1.z, H1.w};
            uint32_t lw[8] = {L0.x, L0.y, L0.z, L0.w, L1.x, L1.y, L1.z, L1.w};
#pragma unroll
            for (int j = 0; j < 8; ++j) {
                float2 hh = h2f(hw[j]), ll = h2f(lw[j]);
                acc[2 * j]     += hh.x + ll.x;
                acc[2 * j + 1] += hh.y + ll.y;
            }
        }
        uint32_t hp[8], lp[8];
#pragma unroll
        for (int j = 0; j < 8; ++j) {
            __half h0, h1, l0, l1;
            split1(acc[2 * j], h0, l0);
            split1(acc[2 * j + 1], h1, l1);
            hp[j] = pack2(h0, h1);
            lp[j] = pack2(l0, l1);
        }
        size_t o = (size_t)row * FH + lane * 16;
        *(uint4*)(Ah + o)     = make_uint4(hp[0], hp[1], hp[2], hp[3]);
        *(uint4*)(Ah + o + 8) = make_uint4(hp[4], hp[5], hp[6], hp[7]);
        *(uint4*)(Al + o)     = make_uint4(lp[0], lp[1], lp[2], lp[3]);
        *(uint4*)(Al + o + 8) = make_uint4(lp[4], lp[5], lp[6], lp[7]);
    }
}

// ---------------- weight transpose + split (fused over 4 weights) ------------
__global__ void transpose_split4(const float* __restrict__ W0,
                                 const float* __restrict__ W1,
                                 const float* __restrict__ W2,
                                 const float* __restrict__ W3,
                                 __half* __restrict__ Wt) {
    __shared__ float t[32][33];
    const float* W = (blockIdx.z == 0) ? W0 : (blockIdx.z == 1) ? W1
                   : (blockIdx.z == 2) ? W2 : W3;
    __half* Bh = Wt + (size_t)(2 * blockIdx.z) * FH * FH;
    __half* Bl = Bh + (size_t)FH * FH;
    int n0 = blockIdx.x * 32, k0 = blockIdx.y * 32;
    int tx = threadIdx.x, ty = threadIdx.y;
    for (int yy = ty; yy < 32; yy += 8)
        t[yy][tx] = W[(size_t)(k0 + yy) * FH + n0 + tx];
    __syncthreads();
    for (int yy = ty; yy < 32; yy += 8) {
        float v = t[tx][yy];
        size_t o = (size_t)(n0 + yy) * FH + k0 + tx;
        __half h, l;
        split1(v, h, l);
        Bh[o] = h; Bl[o] = l;
    }
}

// ---------------- head fold + head ------------------------------------------
__global__ void wcomb_kernel(const float* __restrict__ Wlin,
                             const float* __restrict__ Whead,
                             const float* __restrict__ blin,
                             const float* __restrict__ bhead,
                             float* __restrict__ Wcomb, float* __restrict__ bcomb) {
    int k = blockIdx.x;
    int lane = threadIdx.x;
    const float* rowv = (k < FH) ? (Wlin + (size_t)k * FH) : blin;
    float acc[C_OUT];
#pragma unroll
    for (int c = 0; c < C_OUT; ++c) acc[c] = 0.f;
    for (int j = lane; j < FH; j += 32) {
        float v = rowv[j];
        const float* w = Whead + (size_t)j * C_OUT;
#pragma unroll
        for (int c = 0; c < C_OUT; ++c) acc[c] += v * w[c];
    }
#pragma unroll
    for (int off = 16; off > 0; off >>= 1)
#pragma unroll
        for (int c = 0; c < C_OUT; ++c)
            acc[c] += __shfl_down_sync(0xFFFFFFFFu, acc[c], off);
    if (lane == 0) {
        if (k < FH) {
#pragma unroll
            for (int c = 0; c < C_OUT; ++c) Wcomb[(size_t)k * C_OUT + c] = acc[c];
        } else {
#pragma unroll
            for (int c = 0; c < C_OUT; ++c) bcomb[c] = acc[c] + bhead[c];
        }
    }
}

__global__ void head_kernel(const float* __restrict__ h2,
                            const float* __restrict__ Wcomb,
                            const float* __restrict__ bcomb,
                            float* __restrict__ out) {
    int r = blockIdx.x;
    int lane = threadIdx.x;
    float acc[C_OUT];
#pragma unroll
    for (int c = 0; c < C_OUT; ++c) acc[c] = 0.f;
    const float* trow = h2 + (size_t)r * FH;
    for (int k = lane; k < FH; k += 32) {
        float t = trow[k];
        const float* w = Wcomb + (size_t)k * C_OUT;
#pragma unroll
        for (int c = 0; c < C_OUT; ++c) acc[c] += t * w[c];
    }
#pragma unroll
    for (int off = 16; off > 0; off >>= 1)
#pragma unroll
        for (int c = 0; c < C_OUT; ++c)
            acc[c] += __shfl_down_sync(0xFFFFFFFFu, acc[c], off);
    if (lane == 0) {
#pragma unroll
        for (int c = 0; c < C_OUT; ++c) out[(size_t)r * C_OUT + c] = acc[c] + bcomb[c];
    }
}

// ---------------- layer-1 asymmetric GEMM ------------------------------------
// h = relu( Aagg@B0h  +  (Axh+Axl)@B1h  + bias ), epilogue emits fp16 split.
// src0 (agg): 1 combo; src1 (root): 2 combos.
#define SA 40

__global__ __launch_bounds__(256) void gemm1_asym(
    const __half* __restrict__ Aagg, const __half* __restrict__ B0h,
    const __half* __restrict__ Axh,  const __half* __restrict__ Axl,
    const __half* __restrict__ B1h,
    const float* __restrict__ bias,
    __half* __restrict__ Ch, __half* __restrict__ Cl, int M) {
    extern __shared__ __half sm[];
    constexpr int NT = 3;   // tile 0 = A hi, 1 = A lo (src1 only), 2 = B hi
    const int tid = threadIdx.x;
    const int lane = tid & 31;
    const int wid = tid >> 5;
    const int wm = wid & 3;
    const int wn = wid >> 2;
    const int m0 = blockIdx.y * 128;
    const int n0 = blockIdx.x * 128;

    float acc[2][8][4];
#pragma unroll
    for (int i = 0; i < 2; ++i)
#pragma unroll
        for (int j = 0; j < 8; ++j)
#pragma unroll
            for (int q = 0; q < 4; ++q) acc[i][j][q] = 0.f;

    const int r0 = tid >> 2;
    const int c8 = (tid & 3) * 8;

    auto tile_off = [&](int buf, int t, int row, int col) -> uint32_t {
        return (uint32_t)((((buf * NT + t) * 128 + row) * SA + col) * 2);
    };
    const uint32_t smb = smem_u32(sm);

    constexpr int NST = 32;
    auto issue = [&](int buf, int s) {
        const int src = s >> 4;
        const int k0 = (s & 15) * 32;
        const __half* A = src ? Axh : Aagg;
        const __half* B = src ? B1h : B0h;
#pragma unroll
        for (int i = 0; i < 2; ++i) {
            int row = r0 + i * 64;
            int gm = m0 + row;
            cp_async16(smb + tile_off(buf, 0, row, c8),
                       A + (size_t)gm * FH + k0 + c8, gm < M ? 16 : 0);
            cp_async16(smb + tile_off(buf, 2, row, c8),
                       B + (size_t)(n0 + row) * FH + k0 + c8, 16);
        }
        if (src) {
#pragma unroll
            for (int i = 0; i < 2; ++i) {
                int row = r0 + i * 64;
                int gm = m0 + row;
                cp_async16(smb + tile_off(buf, 1, row, c8),
                           Axl + (size_t)gm * FH + k0 + c8, gm < M ? 16 : 0);
            }
        }
        cp_commit();
    };

    issue(0, 0);

    const int lrow = lane & 15;
    const int lcol = (lane >> 4) << 3;
    const int fr = lane >> 2;
    const int fc = (lane & 3) * 2;

#pragma unroll 1
    for (int s = 0; s < NST; ++s) {
        cp_wait0();
        __syncthreads();
        if (s + 1 < NST) issue((s + 1) & 1, s + 1);
        const int buf = s & 1;
        const int src = s >> 4;
#pragma unroll
        for (int kk = 0; kk < 32; kk += 16) {
            uint32_t ah[2][4], bb[4][4];
#pragma unroll
            for (int mi = 0; mi < 2; ++mi) {
                int rb = wm * 32 + mi * 16 + lrow;
                LDX4(ah[mi], smb + tile_off(buf, 0, rb, kk + lcol));
            }
#pragma unroll
            for (int np = 0; np < 4; ++np) {
                int nb = wn * 64 + np * 16 + lrow;
                LDX4(bb[np], smb + tile_off(buf, 2, nb, kk + lcol));
            }
#pragma unroll
            for (int np = 0; np < 4; ++np) {
#pragma unroll
                for (int mi = 0; mi < 2; ++mi) {
                    mma16816(acc[mi][2 * np],     ah[mi], bb[np][0], bb[np][2]);
                    mma16816(acc[mi][2 * np + 1], ah[mi], bb[np][1], bb[np][3]);
                }
            }
            if (src) {
                uint32_t al[2][4];
#pragma unroll
                for (int mi = 0; mi < 2; ++mi) {
                    int rb = wm * 32 + mi * 16 + lrow;
                    LDX4(al[mi], smb + tile_off(buf, 1, rb, kk + lcol));
                }
#pragma unroll
                for (int np = 0; np < 4; ++np) {
#pragma unroll
                    for (int mi = 0; mi < 2; ++mi) {
                        mma16816(acc[mi][2 * np],     al[mi], bb[np][0], bb[np][2]);
                        mma16816(acc[mi][2 * np + 1], al[mi], bb[np][1], bb[np][3]);
                    }
                }
            }
        }
        __syncthreads();
    }

    // -------- epilogue: relu + fp16 split --------
#pragma unroll
    for (int mi = 0; mi < 2; ++mi) {
#pragma unroll
        for (int half = 0; half < 2; ++half) {
            int row = m0 + wm * 32 + mi * 16 + fr + half * 8;
            if (row >= M) continue;
#pragma unroll
            for (int ni = 0; ni < 8; ++ni) {
                int col = n0 + wn * 64 + ni * 8 + fc;
                float v0 = fmaxf(acc[mi][ni][half * 2 + 0] + bias[col], 0.f);
                float v1 = fmaxf(acc[mi][ni][half * 2 + 1] + bias[col + 1], 0.f);
                __half h0, h1, l0, l1;
                split1(v0, h0, l0); split1(v1, h1, l1);
                *(uint32_t*)(Ch + (size_t)row * FH + col) = pack2(h0, h1);
                *(uint32_t*)(Cl + (size_t)row * FH + col) = pack2(l0, l1);
            }
        }
    }
}

// ---------------- layer-2 GEMM (3-term, dual source, f32 out) ----------------
__global__ __launch_bounds__(256) void gemm2_mma(
    const __half* __restrict__ A0h, const __half* __restrict__ A0l,
    const __half* __restrict__ A1h, const __half* __restrict__ A1l,
    const __half* __restrict__ B0h, const __half* __restrict__ B0l,
    const __half* __restrict__ B1h, const __half* __restrict__ B1l,
    const float* __restrict__ bias, float* __restrict__ Cout, int M) {
    extern __shared__ __half sm[];
    constexpr int NT = 4;
    const int tid = threadIdx.x;
    const int lane = tid & 31;
    const int wid = tid >> 5;
    const int wm = wid & 3;
    const int wn = wid >> 2;
    const int m0 = blockIdx.y * 128;
    const int n0 = blockIdx.x * 128;

    const __half* APs[2][2] = {{A0h, A0l}, {A1h, A1l}};
    const __half* BPs[2][2] = {{B0h, B0l}, {B1h, B1l}};

    float acc[2][8][4];
#pragma unroll
    for (int i = 0; i < 2; ++i)
#pragma unroll
        for (int j = 0; j < 8; ++j)
#pragma unroll
            for (int q = 0; q < 4; ++q) acc[i][j][q] = 0.f;

    const int r0 = tid >> 2;
    const int c8 = (tid & 3) * 8;

    auto tile_off = [&](int buf, int t, int row, int col) -> uint32_t {
        return (uint32_t)((((buf * NT + t) * 128 + row) * SA + col) * 2);
    };
    const uint32_t smb = smem_u32(sm);

    constexpr int NST = 32;
    auto issue = [&](int buf, int s) {
        const int src = s >> 4;
        const int k0 = (s & 15) * 32;
#pragma unroll
        for (int t = 0; t < NT; ++t) {
            const __half* P = (t < 2) ? APs[src][t] : BPs[src][t - 2];
#pragma unroll
            for (int i = 0; i < 2; ++i) {
                int row = r0 + i * 64;
                int sz = 16;
                int gr;
                if (t < 2) { gr = m0 + row; if (gr >= M) sz = 0; }
                else       { gr = n0 + row; }
                cp_async16(smb + tile_off(buf, t, row, c8),
                           P + (size_t)gr * FH + k0 + c8, sz);
            }
        }
        cp_commit();
    };

    issue(0, 0);

    const int lrow = lane & 15;
    const int lcol = (lane >> 4) << 3;
    const int fr = lane >> 2;
    const int fc = (lane & 3) * 2;

#pragma unroll 1
    for (int s = 0; s < NST; ++s) {
        cp_wait0();
        __syncthreads();
        if (s + 1 < NST) issue((s + 1) & 1, s + 1);
        const int buf = s & 1;
#pragma unroll
        for (int kk = 0; kk < 32; kk += 16) {
            uint32_t ah[2][4], al[2][4], bb[4][4];
#pragma unroll
            for (int mi = 0; mi < 2; ++mi) {
                int rb = wm * 32 + mi * 16 + lrow;
                LDX4(ah[mi], smb + tile_off(buf, 0, rb, kk + lcol));
                LDX4(al[mi], smb + tile_off(buf, 1, rb, kk + lcol));
            }
#pragma unroll
            for (int np = 0; np < 4; ++np) {
                int nb = wn * 64 + np * 16 + lrow;
                LDX4(bb[np], smb + tile_off(buf, 2, nb, kk + lcol));
            }
#pragma unroll
            for (int np = 0; np < 4; ++np) {
#pragma unroll
                for (int mi = 0; mi < 2; ++mi) {
                    mma16816(acc[mi][2 * np],     ah[mi], bb[np][0], bb[np][2]);
                    mma16816(acc[mi][2 * np + 1], ah[mi], bb[np][1], bb[np][3]);
                    mma16816(acc[mi][2 * np],     al[mi], bb[np][0], bb[np][2]);
                    mma16816(acc[mi][2 * np + 1], al[mi], bb[np][1], bb[np][3]);
                }
            }
#pragma unroll
            for (int np = 0; np < 4; ++np) {
                int nb = wn * 64 + np * 16 + lrow;
                LDX4(bb[np], smb + tile_off(buf, 3, nb, kk + lcol));
            }
#pragma unroll
            for (int np = 0; np < 4; ++np) {
#pragma unroll
                for (int mi = 0; mi < 2; ++mi) {
                    mma16816(acc[mi][2 * np],     ah[mi], bb[np][0], bb[np][2]);
                    mma16816(acc[mi][2 * np + 1], ah[mi], bb[np][1], bb[np][3]);
                }
            }
        }
        __syncthreads();
    }

#pragma unroll
    for (int mi = 0; mi < 2; ++mi) {
#pragma unroll
        for (int half = 0; half < 2; ++half) {
            int row = m0 + wm * 32 + mi * 16 + fr + half * 8;
            if (row >= M) continue;
#pragma unroll
            for (int ni = 0; ni < 8; ++ni) {
                int col = n0 + wn * 64 + ni * 8 + fc;
                float v0 = acc[mi][ni][half * 2 + 0] + bias[col];
                float v1 = acc[mi][ni][half * 2 + 1] + bias[col + 1];
                *(float2*)(Cout + (size_t)row * FH + col) = make_float2(v0, v1);
            }
        }
    }
}

// ---------------------------------------------------------------------------
extern "C" void kernel_launch(void* const* d_in, const int* in_sizes, int n_in,
                              void* d_out, int out_size) {
    const float* x     = (const float*)d_in[0];
    const int*   src1  = (const int*)  d_in[1];
    const int*   dst1  = (const int*)  d_in[2];
    const int*   src2  = (const int*)  d_in[3];
    const int*   dst2  = (const int*)  d_in[4];
    const float* Wrel1 = (const float*)d_in[5];
    const float* brel1 = (const float*)d_in[6];
    const float* Wroot1= (const float*)d_in[7];
    const float* Wrel2 = (const float*)d_in[8];
    const float* brel2 = (const float*)d_in[9];
    const float* Wroot2= (const float*)d_in[10];
    const float* Wlin  = (const float*)d_in[11];
    const float* blin  = (const float*)d_in[12];
    const float* Whead = (const float*)d_in[13];
    const float* bhead = (const float*)d_in[14];
    float* out = (float*)d_out;

    float *h2, *Wcomb, *bcomb;
    __half *Xh, *A2l, *A1h, *Hh, *Hl, *G2h, *G2l, *Wt;
    int *cnt1, *rp1, *pos1, *esrc1, *cnt2, *rp2, *pos2, *esrc2;
    cudaGetSymbolAddress((void**)&h2,   g_h2);
    cudaGetSymbolAddress((void**)&Xh,   g_Xh);
    cudaGetSymbolAddress((void**)&A2l,  g_A2l);
    cudaGetSymbolAddress((void**)&A1h,  g_A1h);
    cudaGetSymbolAddress((void**)&Hh,   g_Hh);
    cudaGetSymbolAddress((void**)&Hl,   g_Hl);
    cudaGetSymbolAddress((void**)&G2h,  g_G2h);
    cudaGetSymbolAddress((void**)&G2l,  g_G2l);
    cudaGetSymbolAddress((void**)&Wt,   g_Wt);
    cudaGetSymbolAddress((void**)&Wcomb, g_Wcomb);
    cudaGetSymbolAddress((void**)&bcomb, g_bcomb);
    cudaGetSymbolAddress((void**)&cnt1, g_cnt1);
    cudaGetSymbolAddress((void**)&rp1,  g_rp1);
    cudaGetSymbolAddress((void**)&pos1, g_pos1);
    cudaGetSymbolAddress((void**)&esrc1, g_esrc1);
    cudaGetSymbolAddress((void**)&cnt2, g_cnt2);
    cudaGetSymbolAddress((void**)&rp2,  g_rp2);
    cudaGetSymbolAddress((void**)&pos2, g_pos2);
    cudaGetSymbolAddress((void**)&esrc2, g_esrc2);
    __half* WtP[8];
    for (int i = 0; i < 8; ++i) WtP[i] = Wt + (size_t)i * FH * FH;

    constexpr int GSMEM1 = 2 * 3 * 128 * SA * 2;  // 61440 B
    constexpr int GSMEM2 = 2 * 4 * 128 * SA * 2;  // 81920 B
    cudaFuncSetAttribute(gemm1_asym,
                         cudaFuncAttributeMaxDynamicSharedMemorySize, GSMEM1);
    cudaFuncSetAttribute(gemm2_mma,
                         cudaFuncAttributeMaxDynamicSharedMemorySize, GSMEM2);

    // ---- CSR build (fused) ----
    zero_both<<<(N1 + N2 + 255) / 256, 256>>>(cnt1, cnt2);
    hist_both<<<(E1 + E2 + 255) / 256, 256>>>(dst1, dst2, cnt1, cnt2);
    scan_both<<<2, 1024>>>(cnt1, rp1, pos1, cnt2, rp2, pos2);
    fill_both<<<(E1 + E2 + 255) / 256, 256>>>(dst1, src1, pos1, esrc1,
                                              dst2, src2, pos2, esrc2);

    // ---- x conversion + weight prep ----
    {
        int nch = (N0 * FH) / 8;
        convert_x<<<(nch + 255) / 256, 256>>>((const float4*)x, (uint4*)Xh, (uint4*)A2l);
        dim3 g(16, 16, 4), b(32, 8);
        transpose_split4<<<g, b>>>(Wrel1, Wroot1, Wrel2, Wroot2, Wt);
        wcomb_kernel<<<FH + 1, 32>>>(Wlin, Whead, blin, bhead, Wcomb, bcomb);
    }

    // ---- layer 1 ----
    gather_hi<<<(N1 + GROWS - 1) / GROWS, 256>>>(Xh, esrc1, rp1, N1, A1h);
    {
        dim3 grid(FH / 128, (N1 + 127) / 128);
        gemm1_asym<<<grid, 256, GSMEM1>>>(
            A1h, WtP[0], Xh, A2l, WtP[2], brel1, Hh, Hl, N1);
    }

    // ---- layer 2 ----
    gather_f16_split<<<(N2 + GROWS - 1) / GROWS, 256>>>(Hh, Hl, esrc2, rp2, N2, G2h, G2l);
    {
        dim3 grid(FH / 128, (N2 + 127) / 128);
        gemm2_mma<<<grid, 256, GSMEM2>>>(
            G2h, G2l, Hh, Hl, WtP[4], WtP[5], WtP[6], WtP[7],
            brel2, h2, N2);
    }

    // ---- head ----
    head_kernel<<<N2, 32>>>(h2, Wcomb, bcomb, out);

    (void)in_sizes; (void)n_in; (void)out_size;
}

// round 9
// speedup vs baseline: 4.6947x; 1.1123x over previous
#include <cuda_runtime.h>
#include <cuda_fp16.h>
#include <cstdint>

#define N0 100000
#define N1 20000
#define N2 4000
#define E1 500000
#define E2 100000
#define FH 512
#define C_OUT 10

// ---------------- scratch ---------------------------------------------------
__device__ float g_h2[(size_t)N2 * FH];

__device__ __half g_Xh [(size_t)N0 * FH];                         // fp16 of x (all rows)
__device__ __half g_A1h[(size_t)N1 * FH];                         // agg1 (fp16)
__device__ __half g_Hh [(size_t)N1 * FH], g_Hl [(size_t)N1 * FH]; // h split
__device__ __half g_G2h[(size_t)N2 * FH], g_G2l[(size_t)N2 * FH]; // agg2 split
__device__ __half g_Wt[8][(size_t)FH * FH];
__device__ float g_Wcomb[(size_t)FH * C_OUT];
__device__ float g_bcomb[C_OUT];

// CSR scratch
__device__ int g_cnt1[N1], g_rp1[N1 + 1], g_pos1[N1], g_esrc1[E1];
__device__ int g_cnt2[N2], g_rp2[N2 + 1], g_pos2[N2], g_esrc2[E2];

// ---------------- helpers ---------------------------------------------------
__device__ __forceinline__ uint32_t smem_u32(const void* p) {
    uint32_t a;
    asm("{ .reg .u64 t; cvta.to.shared.u64 t, %1; cvt.u32.u64 %0, t; }"
        : "=r"(a) : "l"(p));
    return a;
}
__device__ __forceinline__ void cp_async16(uint32_t dst, const void* src, int sz) {
    asm volatile("cp.async.cg.shared.global [%0], [%1], 16, %2;"
                 :: "r"(dst), "l"(src), "r"(sz) : "memory");
}
__device__ __forceinline__ void cp_commit() {
    asm volatile("cp.async.commit_group;" ::: "memory");
}
__device__ __forceinline__ void cp_wait0() {
    asm volatile("cp.async.wait_group 0;" ::: "memory");
}
__device__ __forceinline__ void split1(float v, __half& h, __half& l) {
    h = __float2half_rn(v);
    l = __float2half_rn(v - __half2float(h));
}
__device__ __forceinline__ uint32_t pack2(__half a, __half b) {
    __half2 t = __halves2half2(a, b);
    return *reinterpret_cast<uint32_t*>(&t);
}
__device__ __forceinline__ float2 h2f(uint32_t w) {
    __half2 t = *reinterpret_cast<__half2*>(&w);
    return __half22float2(t);
}
__device__ __forceinline__ void mma16816(float* c, const uint32_t* a,
                                         uint32_t b0, uint32_t b1) {
    asm("mma.sync.aligned.m16n8k16.row.col.f32.f16.f16.f32 "
        "{%0,%1,%2,%3}, {%4,%5,%6,%7}, {%8,%9}, {%0,%1,%2,%3};"
        : "+f"(c[0]), "+f"(c[1]), "+f"(c[2]), "+f"(c[3])
        : "r"(a[0]), "r"(a[1]), "r"(a[2]), "r"(a[3]), "r"(b0), "r"(b1));
}
#define LDX4(r, addr) \
    asm volatile("ldmatrix.sync.aligned.m8n8.x4.shared.b16 {%0,%1,%2,%3}, [%4];" \
                 : "=r"((r)[0]), "=r"((r)[1]), "=r"((r)[2]), "=r"((r)[3])        \
                 : "r"(addr))

// ---------------- x -> fp16 chunk converter (8 floats per chunk) -------------
#define NCH_TOTAL ((N0 * FH) / 8)
__device__ __forceinline__ void conv_chunk(const float4* __restrict__ x4,
                                           uint4* __restrict__ Xh4, int i) {
    float4 v0 = x4[2 * i], v1 = x4[2 * i + 1];
    Xh4[i] = make_uint4(
        pack2(__float2half_rn(v0.x), __float2half_rn(v0.y)),
        pack2(__float2half_rn(v0.z), __float2half_rn(v0.w)),
        pack2(__float2half_rn(v1.x), __float2half_rn(v1.y)),
        pack2(__float2half_rn(v1.z), __float2half_rn(v1.w)));
}

// ---------------- CSR build, each launch co-scheduled with a conv slice ------
__global__ void zero_conv(int* __restrict__ c1, int* __restrict__ c2,
                          int baseBlocks,
                          const float4* __restrict__ x4, uint4* __restrict__ Xh4,
                          int convStart, int convEnd) {
    if ((int)blockIdx.x < baseBlocks) {
        int i = blockIdx.x * blockDim.x + threadIdx.x;
        if (i < N1) c1[i] = 0;
        else if (i < N1 + N2) c2[i - N1] = 0;
    } else {
        int i = convStart + (blockIdx.x - baseBlocks) * blockDim.x + threadIdx.x;
        if (i < convEnd) conv_chunk(x4, Xh4, i);
    }
}
__global__ void hist_conv(const int* __restrict__ d1, const int* __restrict__ d2,
                          int* __restrict__ c1, int* __restrict__ c2,
                          int baseBlocks,
                          const float4* __restrict__ x4, uint4* __restrict__ Xh4,
                          int convStart, int convEnd) {
    if ((int)blockIdx.x < baseBlocks) {
        int e = blockIdx.x * blockDim.x + threadIdx.x;
        if (e < E1) atomicAdd(&c1[d1[e]], 1);
        else if (e < E1 + E2) atomicAdd(&c2[d2[e - E1]], 1);
    } else {
        int i = convStart + (blockIdx.x - baseBlocks) * blockDim.x + threadIdx.x;
        if (i < convEnd) conv_chunk(x4, Xh4, i);
    }
}
__global__ __launch_bounds__(1024) void scan_both(
    const int* __restrict__ c1, int* __restrict__ r1, int* __restrict__ p1,
    const int* __restrict__ c2, int* __restrict__ r2, int* __restrict__ p2) {
    const int n = blockIdx.x ? N2 : N1;
    const int* cnt = blockIdx.x ? c2 : c1;
    int* rowptr = blockIdx.x ? r2 : r1;
    int* pos    = blockIdx.x ? p2 : p1;
    __shared__ int ts[1024];
    const int t = threadIdx.x;
    const int C = (n + 1023) >> 10;
    int local[20];
    int s = 0;
    for (int j = 0; j < C; ++j) {
        int idx = t * C + j;
        int v = (idx < n) ? cnt[idx] : 0;
        local[j] = s; s += v;
    }
    ts[t] = s;
    __syncthreads();
    for (int off = 1; off < 1024; off <<= 1) {
        int v = (t >= off) ? ts[t - off] : 0;
        __syncthreads();
        ts[t] += v;
        __syncthreads();
    }
    int base = (t > 0) ? ts[t - 1] : 0;
    for (int j = 0; j < C; ++j) {
        int idx = t * C + j;
        if (idx < n) { int r = base + local[j]; rowptr[idx] = r; pos[idx] = r; }
    }
    if (t == 1023) rowptr[n] = ts[1023];
}
__global__ void fill_conv(const int* __restrict__ d1, const int* __restrict__ s1,
                          int* __restrict__ p1, int* __restrict__ e1,
                          const int* __restrict__ d2, const int* __restrict__ s2,
                          int* __restrict__ p2, int* __restrict__ e2,
                          int baseBlocks,
                          const float4* __restrict__ x4, uint4* __restrict__ Xh4,
                          int convStart, int convEnd) {
    if ((int)blockIdx.x < baseBlocks) {
        int e = blockIdx.x * blockDim.x + threadIdx.x;
        if (e < E1) {
            int p = atomicAdd(&p1[d1[e]], 1);
            e1[p] = s1[e];
        } else if (e < E1 + E2) {
            int q = e - E1;
            int p = atomicAdd(&p2[d2[q]], 1);
            e2[p] = s2[q];
        }
    } else {
        int i = convStart + (blockIdx.x - baseBlocks) * blockDim.x + threadIdx.x;
        if (i < convEnd) conv_chunk(x4, Xh4, i);
    }
}

// ---------------- gather (fp16 src) -> fp16 agg, dynamic rows ----------------
#define GROWS 16
__global__ void gather_hi(const __half* __restrict__ Xh,
                          const int* __restrict__ esrc,
                          const int* __restrict__ rowptr, int nrows,
                          __half* __restrict__ Ah) {
    __shared__ int cur;
    if (threadIdx.x == 0) cur = 0;
    __syncthreads();
    const int base = blockIdx.x * GROWS;
    const int lane = threadIdx.x & 31;
    for (;;) {
        int r = 0;
        if (lane == 0) r = atomicAdd(&cur, 1);
        r = __shfl_sync(0xFFFFFFFFu, r, 0);
        if (r >= GROWS) break;
        int row = base + r;
        if (row >= nrows) break;
        const int beg = rowptr[row], end = rowptr[row + 1];
        float acc[16];
#pragma unroll
        for (int j = 0; j < 16; ++j) acc[j] = 0.f;
        int i = beg;
        for (; i + 2 <= end; i += 2) {
            size_t b0 = (size_t)__ldg(&esrc[i]) * FH + lane * 16;
            size_t b1 = (size_t)__ldg(&esrc[i + 1]) * FH + lane * 16;
            uint4 U0 = *(const uint4*)(Xh + b0);
            uint4 U1 = *(const uint4*)(Xh + b0 + 8);
            uint4 V0 = *(const uint4*)(Xh + b1);
            uint4 V1 = *(const uint4*)(Xh + b1 + 8);
            uint32_t uw[8] = {U0.x, U0.y, U0.z, U0.w, U1.x, U1.y, U1.z, U1.w};
            uint32_t vw[8] = {V0.x, V0.y, V0.z, V0.w, V1.x, V1.y, V1.z, V1.w};
#pragma unroll
            for (int j = 0; j < 8; ++j) {
                float2 a = h2f(uw[j]), b = h2f(vw[j]);
                acc[2 * j]     += a.x + b.x;
                acc[2 * j + 1] += a.y + b.y;
            }
        }
        if (i < end) {
            size_t b0 = (size_t)__ldg(&esrc[i]) * FH + lane * 16;
            uint4 U0 = *(const uint4*)(Xh + b0);
            uint4 U1 = *(const uint4*)(Xh + b0 + 8);
            uint32_t uw[8] = {U0.x, U0.y, U0.z, U0.w, U1.x, U1.y, U1.z, U1.w};
#pragma unroll
            for (int j = 0; j < 8; ++j) {
                float2 a = h2f(uw[j]);
                acc[2 * j]     += a.x;
                acc[2 * j + 1] += a.y;
            }
        }
        uint32_t hp[8];
#pragma unroll
        for (int j = 0; j < 8; ++j)
            hp[j] = pack2(__float2half_rn(acc[2 * j]), __float2half_rn(acc[2 * j + 1]));
        size_t o = (size_t)row * FH + lane * 16;
        *(uint4*)(Ah + o)     = make_uint4(hp[0], hp[1], hp[2], hp[3]);
        *(uint4*)(Ah + o + 8) = make_uint4(hp[4], hp[5], hp[6], hp[7]);
    }
}

// ---------------- gather (fp16 hi/lo src) + fp16 split, dynamic rows ---------
__global__ void gather_f16_split(const __half* __restrict__ Xh,
                                 const __half* __restrict__ Xl,
                                 const int* __restrict__ esrc,
                                 const int* __restrict__ rowptr, int nrows,
                                 __half* __restrict__ Ah, __half* __restrict__ Al) {
    __shared__ int cur;
    if (threadIdx.x == 0) cur = 0;
    __syncthreads();
    const int base = blockIdx.x * GROWS;
    const int lane = threadIdx.x & 31;
    for (;;) {
        int r = 0;
        if (lane == 0) r = atomicAdd(&cur, 1);
        r = __shfl_sync(0xFFFFFFFFu, r, 0);
        if (r >= GROWS) break;
        int row = base + r;
        if (row >= nrows) break;
        const int beg = rowptr[row], end = rowptr[row + 1];
        float acc[16];
#pragma unroll
        for (int j = 0; j < 16; ++j) acc[j] = 0.f;
        for (int i = beg; i < end; ++i) {
            size_t b = (size_t)__ldg(&esrc[i]) * FH + lane * 16;
            uint4 H0 = *(const uint4*)(Xh + b);
            uint4 H1 = *(const uint4*)(Xh + b + 8);
            uint4 L0 = *(const uint4*)(Xl + b);
            uint4 L1 = *(const uint4*)(Xl + b + 8);
            uint32_t hw[8] = {H0.x, H0.y, H0.z, H0.w, H1.x, H1.y, H1.z, H1.w};
            uint32_t lw[8] = {L0.x, L0.y, L0.z, L0.w, L1.x, L1.y, L1.z, L1.w};
#pragma unroll
            for (int j = 0; j < 8; ++j) {
                float2 hh = h2f(hw[j]), ll = h2f(lw[j]);
                acc[2 * j]     += hh.x + ll.x;
                acc[2 * j + 1] += hh.y + ll.y;
            }
        }
        uint32_t hp[8], lp[8];
#pragma unroll
        for (int j = 0; j < 8; ++j) {
            __half h0, h1, l0, l1;
            split1(acc[2 * j], h0, l0);
            split1(acc[2 * j + 1], h1, l1);
            hp[j] = pack2(h0, h1);
            lp[j] = pack2(l0, l1);
        }
        size_t o = (size_t)row * FH + lane * 16;
        *(uint4*)(Ah + o)     = make_uint4(hp[0], hp[1], hp[2], hp[3]);
        *(uint4*)(Ah + o + 8) = make_uint4(hp[4], hp[5], hp[6], hp[7]);
        *(uint4*)(Al + o)     = make_uint4(lp[0], lp[1], lp[2], lp[3]);
        *(uint4*)(Al + o + 8) = make_uint4(lp[4], lp[5], lp[6], lp[7]);
    }
}

// ---------------- weight transpose + split (fused over 4 weights) ------------
__global__ void transpose_split4(const float* __restrict__ W0,
                                 const float* __restrict__ W1,
                                 const float* __restrict__ W2,
                                 const float* __restrict__ W3,
                                 __half* __restrict__ Wt) {
    __shared__ float t[32][33];
    const float* W = (blockIdx.z == 0) ? W0 : (blockIdx.z == 1) ? W1
                   : (blockIdx.z == 2) ? W2 : W3;
    __half* Bh = Wt + (size_t)(2 * blockIdx.z) * FH * FH;
    __half* Bl = Bh + (size_t)FH * FH;
    int n0 = blockIdx.x * 32, k0 = blockIdx.y * 32;
    int tx = threadIdx.x, ty = threadIdx.y;
    for (int yy = ty; yy < 32; yy += 8)
        t[yy][tx] = W[(size_t)(k0 + yy) * FH + n0 + tx];
    __syncthreads();
    for (int yy = ty; yy < 32; yy += 8) {
        float v = t[tx][yy];
        size_t o = (size_t)(n0 + yy) * FH + k0 + tx;
        __half h, l;
        split1(v, h, l);
        Bh[o] = h; Bl[o] = l;
    }
}

// ---------------- head fold + head ------------------------------------------
__global__ void wcomb_kernel(const float* __restrict__ Wlin,
                             const float* __restrict__ Whead,
                             const float* __restrict__ blin,
                             const float* __restrict__ bhead,
                             float* __restrict__ Wcomb, float* __restrict__ bcomb) {
    int k = blockIdx.x;
    int lane = threadIdx.x;
    const float* rowv = (k < FH) ? (Wlin + (size_t)k * FH) : blin;
    float acc[C_OUT];
#pragma unroll
    for (int c = 0; c < C_OUT; ++c) acc[c] = 0.f;
    for (int j = lane; j < FH; j += 32) {
        float v = rowv[j];
        const float* w = Whead + (size_t)j * C_OUT;
#pragma unroll
        for (int c = 0; c < C_OUT; ++c) acc[c] += v * w[c];
    }
#pragma unroll
    for (int off = 16; off > 0; off >>= 1)
#pragma unroll
        for (int c = 0; c < C_OUT; ++c)
            acc[c] += __shfl_down_sync(0xFFFFFFFFu, acc[c], off);
    if (lane == 0) {
        if (k < FH) {
#pragma unroll
            for (int c = 0; c < C_OUT; ++c) Wcomb[(size_t)k * C_OUT + c] = acc[c];
        } else {
#pragma unroll
            for (int c = 0; c < C_OUT; ++c) bcomb[c] = acc[c] + bhead[c];
        }
    }
}

__global__ void head_kernel(const float* __restrict__ h2,
                            const float* __restrict__ Wcomb,
                            const float* __restrict__ bcomb,
                            float* __restrict__ out) {
    int r = blockIdx.x;
    int lane = threadIdx.x;
    float acc[C_OUT];
#pragma unroll
    for (int c = 0; c < C_OUT; ++c) acc[c] = 0.f;
    const float* trow = h2 + (size_t)r * FH;
    for (int k = lane; k < FH; k += 32) {
        float t = trow[k];
        const float* w = Wcomb + (size_t)k * C_OUT;
#pragma unroll
        for (int c = 0; c < C_OUT; ++c) acc[c] += t * w[c];
    }
#pragma unroll
    for (int off = 16; off > 0; off >>= 1)
#pragma unroll
        for (int c = 0; c < C_OUT; ++c)
            acc[c] += __shfl_down_sync(0xFFFFFFFFu, acc[c], off);
    if (lane == 0) {
#pragma unroll
        for (int c = 0; c < C_OUT; ++c) out[(size_t)r * C_OUT + c] = acc[c] + bcomb[c];
    }
}

// ---------------- layer-1 GEMM (hi-only, 2 sources) --------------------------
// h = relu( Aagg@B0h + Xh@B1h + bias ); epilogue emits fp16 split of h.
#define SA 40

__global__ __launch_bounds__(256) void gemm1_hi(
    const __half* __restrict__ Aagg, const __half* __restrict__ B0h,
    const __half* __restrict__ Axh,  const __half* __restrict__ B1h,
    const float* __restrict__ bias,
    __half* __restrict__ Ch, __half* __restrict__ Cl, int M) {
    extern __shared__ __half sm[];
    constexpr int NT = 2;   // tile 0 = A, 1 = B
    const int tid = threadIdx.x;
    const int lane = tid & 31;
    const int wid = tid >> 5;
    const int wm = wid & 3;
    const int wn = wid >> 2;
    const int m0 = blockIdx.y * 128;
    const int n0 = blockIdx.x * 128;

    float acc[2][8][4];
#pragma unroll
    for (int i = 0; i < 2; ++i)
#pragma unroll
        for (int j = 0; j < 8; ++j)
#pragma unroll
            for (int q = 0; q < 4; ++q) acc[i][j][q] = 0.f;

    const int r0 = tid >> 2;
    const int c8 = (tid & 3) * 8;

    auto tile_off = [&](int buf, int t, int row, int col) -> uint32_t {
        return (uint32_t)((((buf * NT + t) * 128 + row) * SA + col) * 2);
    };
    const uint32_t smb = smem_u32(sm);

    constexpr int NST = 32;
    auto issue = [&](int buf, int s) {
        const int src = s >> 4;
        const int k0 = (s & 15) * 32;
        const __half* A = src ? Axh : Aagg;
        const __half* B = src ? B1h : B0h;
#pragma unroll
        for (int i = 0; i < 2; ++i) {
            int row = r0 + i * 64;
            int gm = m0 + row;
            cp_async16(smb + tile_off(buf, 0, row, c8),
                       A + (size_t)gm * FH + k0 + c8, gm < M ? 16 : 0);
            cp_async16(smb + tile_off(buf, 1, row, c8),
                       B + (size_t)(n0 + row) * FH + k0 + c8, 16);
        }
        cp_commit();
    };

    issue(0, 0);

    const int lrow = lane & 15;
    const int lcol = (lane >> 4) << 3;
    const int fr = lane >> 2;
    const int fc = (lane & 3) * 2;

#pragma unroll 1
    for (int s = 0; s < NST; ++s) {
        cp_wait0();
        __syncthreads();
        if (s + 1 < NST) issue((s + 1) & 1, s + 1);
        const int buf = s & 1;
#pragma unroll
        for (int kk = 0; kk < 32; kk += 16) {
            uint32_t ah[2][4], bb[4][4];
#pragma unroll
            for (int mi = 0; mi < 2; ++mi) {
                int rb = wm * 32 + mi * 16 + lrow;
                LDX4(ah[mi], smb + tile_off(buf, 0, rb, kk + lcol));
            }
#pragma unroll
            for (int np = 0; np < 4; ++np) {
                int nb = wn * 64 + np * 16 + lrow;
                LDX4(bb[np], smb + tile_off(buf, 1, nb, kk + lcol));
            }
#pragma unroll
            for (int np = 0; np < 4; ++np) {
#pragma unroll
                for (int mi = 0; mi < 2; ++mi) {
                    mma16816(acc[mi][2 * np],     ah[mi], bb[np][0], bb[np][2]);
                    mma16816(acc[mi][2 * np + 1], ah[mi], bb[np][1], bb[np][3]);
                }
            }
        }
        __syncthreads();
    }

    // -------- epilogue: relu + fp16 split --------
#pragma unroll
    for (int mi = 0; mi < 2; ++mi) {
#pragma unroll
        for (int half = 0; half < 2; ++half) {
            int row = m0 + wm * 32 + mi * 16 + fr + half * 8;
            if (row >= M) continue;
#pragma unroll
            for (int ni = 0; ni < 8; ++ni) {
                int col = n0 + wn * 64 + ni * 8 + fc;
                float v0 = fmaxf(acc[mi][ni][half * 2 + 0] + bias[col], 0.f);
                float v1 = fmaxf(acc[mi][ni][half * 2 + 1] + bias[col + 1], 0.f);
                __half h0, h1, l0, l1;
                split1(v0, h0, l0); split1(v1, h1, l1);
                *(uint32_t*)(Ch + (size_t)row * FH + col) = pack2(h0, h1);
                *(uint32_t*)(Cl + (size_t)row * FH + col) = pack2(l0, l1);
            }
        }
    }
}

// ---------------- layer-2 GEMM (3-term, dual source, f32 out) ----------------
__global__ __launch_bounds__(256) void gemm2_mma(
    const __half* __restrict__ A0h, const __half* __restrict__ A0l,
    const __half* __restrict__ A1h, const __half* __restrict__ A1l,
    const __half* __restrict__ B0h, const __half* __restrict__ B0l,
    const __half* __restrict__ B1h, const __half* __restrict__ B1l,
    const float* __restrict__ bias, float* __restrict__ Cout, int M) {
    extern __shared__ __half sm[];
    constexpr int NT = 4;
    const int tid = threadIdx.x;
    const int lane = tid & 31;
    const int wid = tid >> 5;
    const int wm = wid & 3;
    const int wn = wid >> 2;
    const int m0 = blockIdx.y * 128;
    const int n0 = blockIdx.x * 128;

    const __half* APs[2][2] = {{A0h, A0l}, {A1h, A1l}};
    const __half* BPs[2][2] = {{B0h, B0l}, {B1h, B1l}};

    float acc[2][8][4];
#pragma unroll
    for (int i = 0; i < 2; ++i)
#pragma unroll
        for (int j = 0; j < 8; ++j)
#pragma unroll
            for (int q = 0; q < 4; ++q) acc[i][j][q] = 0.f;

    const int r0 = tid >> 2;
    const int c8 = (tid & 3) * 8;

    auto tile_off = [&](int buf, int t, int row, int col) -> uint32_t {
        return (uint32_t)((((buf * NT + t) * 128 + row) * SA + col) * 2);
    };
    const uint32_t smb = smem_u32(sm);

    constexpr int NST = 32;
    auto issue = [&](int buf, int s) {
        const int src = s >> 4;
        const int k0 = (s & 15) * 32;
#pragma unroll
        for (int t = 0; t < NT; ++t) {
            const __half* P = (t < 2) ? APs[src][t] : BPs[src][t - 2];
#pragma unroll
            for (int i = 0; i < 2; ++i) {
                int row = r0 + i * 64;
                int sz = 16;
                int gr;
                if (t < 2) { gr = m0 + row; if (gr >= M) sz = 0; }
                else       { gr = n0 + row; }
                cp_async16(smb + tile_off(buf, t, row, c8),
                           P + (size_t)gr * FH + k0 + c8, sz);
            }
        }
        cp_commit();
    };

    issue(0, 0);

    const int lrow = lane & 15;
    const int lcol = (lane >> 4) << 3;
    const int fr = lane >> 2;
    const int fc = (lane & 3) * 2;

#pragma unroll 1
    for (int s = 0; s < NST; ++s) {
        cp_wait0();
        __syncthreads();
        if (s + 1 < NST) issue((s + 1) & 1, s + 1);
        const int buf = s & 1;
#pragma unroll
        for (int kk = 0; kk < 32; kk += 16) {
            uint32_t ah[2][4], al[2][4], bb[4][4];
#pragma unroll
            for (int mi = 0; mi < 2; ++mi) {
                int rb = wm * 32 + mi * 16 + lrow;
                LDX4(ah[mi], smb + tile_off(buf, 0, rb, kk + lcol));
                LDX4(al[mi], smb + tile_off(buf, 1, rb, kk + lcol));
            }
#pragma unroll
            for (int np = 0; np < 4; ++np) {
                int nb = wn * 64 + np * 16 + lrow;
                LDX4(bb[np], smb + tile_off(buf, 2, nb, kk + lcol));
            }
#pragma unroll
            for (int np = 0; np < 4; ++np) {
#pragma unroll
                for (int mi = 0; mi < 2; ++mi) {
                    mma16816(acc[mi][2 * np],     ah[mi], bb[np][0], bb[np][2]);
                    mma16816(acc[mi][2 * np + 1], ah[mi], bb[np][1], bb[np][3]);
                    mma16816(acc[mi][2 * np],     al[mi], bb[np][0], bb[np][2]);
                    mma16816(acc[mi][2 * np + 1], al[mi], bb[np][1], bb[np][3]);
                }
            }
#pragma unroll
            for (int np = 0; np < 4; ++np) {
                int nb = wn * 64 + np * 16 + lrow;
                LDX4(bb[np], smb + tile_off(buf, 3, nb, kk + lcol));
            }
#pragma unroll
            for (int np = 0; np < 4; ++np) {
#pragma unroll
                for (int mi = 0; mi < 2; ++mi) {
                    mma16816(acc[mi][2 * np],     ah[mi], bb[np][0], bb[np][2]);
                    mma16816(acc[mi][2 * np + 1], ah[mi], bb[np][1], bb[np][3]);
                }
            }
        }
        __syncthreads();
    }

#pragma unroll
    for (int mi = 0; mi < 2; ++mi) {
#pragma unroll
        for (int half = 0; half < 2; ++half) {
            int row = m0 + wm * 32 + mi * 16 + fr + half * 8;
            if (row >= M) continue;
#pragma unroll
            for (int ni = 0; ni < 8; ++ni) {
                int col = n0 + wn * 64 + ni * 8 + fc;
                float v0 = acc[mi][ni][half * 2 + 0] + bias[col];
                float v1 = acc[mi][ni][half * 2 + 1] + bias[col + 1];
                *(float2*)(Cout + (size_t)row * FH + col) = make_float2(v0, v1);
            }
        }
    }
}

// ---------------------------------------------------------------------------
extern "C" void kernel_launch(void* const* d_in, const int* in_sizes, int n_in,
                              void* d_out, int out_size) {
    const float* x     = (const float*)d_in[0];
    const int*   src1  = (const int*)  d_in[1];
    const int*   dst1  = (const int*)  d_in[2];
    const int*   src2  = (const int*)  d_in[3];
    const int*   dst2  = (const int*)  d_in[4];
    const float* Wrel1 = (const float*)d_in[5];
    const float* brel1 = (const float*)d_in[6];
    const float* Wroot1= (const float*)d_in[7];
    const float* Wrel2 = (const float*)d_in[8];
    const float* brel2 = (const float*)d_in[9];
    const float* Wroot2= (const float*)d_in[10];
    const float* Wlin  = (const float*)d_in[11];
    const float* blin  = (const float*)d_in[12];
    const float* Whead = (const float*)d_in[13];
    const float* bhead = (const float*)d_in[14];
    float* out = (float*)d_out;

    float *h2, *Wcomb, *bcomb;
    __half *Xh, *A1h, *Hh, *Hl, *G2h, *G2l, *Wt;
    int *cnt1, *rp1, *pos1, *esrc1, *cnt2, *rp2, *pos2, *esrc2;
    cudaGetSymbolAddress((void**)&h2,   g_h2);
    cudaGetSymbolAddress((void**)&Xh,   g_Xh);
    cudaGetSymbolAddress((void**)&A1h,  g_A1h);
    cudaGetSymbolAddress((void**)&Hh,   g_Hh);
    cudaGetSymbolAddress((void**)&Hl,   g_Hl);
    cudaGetSymbolAddress((void**)&G2h,  g_G2h);
    cudaGetSymbolAddress((void**)&G2l,  g_G2l);
    cudaGetSymbolAddress((void**)&Wt,   g_Wt);
    cudaGetSymbolAddress((void**)&Wcomb, g_Wcomb);
    cudaGetSymbolAddress((void**)&bcomb, g_bcomb);
    cudaGetSymbolAddress((void**)&cnt1, g_cnt1);
    cudaGetSymbolAddress((void**)&rp1,  g_rp1);
    cudaGetSymbolAddress((void**)&pos1, g_pos1);
    cudaGetSymbolAddress((void**)&esrc1, g_esrc1);
    cudaGetSymbolAddress((void**)&cnt2, g_cnt2);
    cudaGetSymbolAddress((void**)&rp2,  g_rp2);
    cudaGetSymbolAddress((void**)&pos2, g_pos2);
    cudaGetSymbolAddress((void**)&esrc2, g_esrc2);
    __half* WtP[8];
    for (int i = 0; i < 8; ++i) WtP[i] = Wt + (size_t)i * FH * FH;

    constexpr int GSMEM1 = 2 * 2 * 128 * SA * 2;  // 40960 B
    constexpr int GSMEM2 = 2 * 4 * 128 * SA * 2;  // 81920 B
    cudaFuncSetAttribute(gemm1_hi,
                         cudaFuncAttributeMaxDynamicSharedMemorySize, GSMEM1);
    cudaFuncSetAttribute(gemm2_mma,
                         cudaFuncAttributeMaxDynamicSharedMemorySize, GSMEM2);

    // conv slice partition: 40% / 30% / 30% across zero/hist/fill launches
    const int convA = (NCH_TOTAL * 2) / 5;
    const int convB = convA + (NCH_TOTAL * 3) / 10;

    // ---- CSR build + x conversion, co-scheduled ----
    {
        int zb = (N1 + N2 + 255) / 256;
        int cb = (convA + 255) / 256;
        zero_conv<<<zb + cb, 256>>>(cnt1, cnt2, zb, (const float4*)x, (uint4*)Xh,
                                    0, convA);
        int hb = (E1 + E2 + 255) / 256;
        int cb2 = (convB - convA + 255) / 256;
        hist_conv<<<hb + cb2, 256>>>(dst1, dst2, cnt1, cnt2, hb,
                                     (const float4*)x, (uint4*)Xh, convA, convB);
        scan_both<<<2, 1024>>>(cnt1, rp1, pos1, cnt2, rp2, pos2);
        int cb3 = (NCH_TOTAL - convB + 255) / 256;
        fill_conv<<<hb + cb3, 256>>>(dst1, src1, pos1, esrc1,
                                     dst2, src2, pos2, esrc2, hb,
                                     (const float4*)x, (uint4*)Xh, convB, NCH_TOTAL);
    }

    // ---- weight prep ----
    {
        dim3 g(16, 16, 4), b(32, 8);
        transpose_split4<<<g, b>>>(Wrel1, Wroot1, Wrel2, Wroot2, Wt);
        wcomb_kernel<<<FH + 1, 32>>>(Wlin, Whead, blin, bhead, Wcomb, bcomb);
    }

    // ---- layer 1 ----
    gather_hi<<<(N1 + GROWS - 1) / GROWS, 256>>>(Xh, esrc1, rp1, N1, A1h);
    {
        dim3 grid(FH / 128, (N1 + 127) / 128);
        gemm1_hi<<<grid, 256, GSMEM1>>>(
            A1h, WtP[0], Xh, WtP[2], brel1, Hh, Hl, N1);
    }

    // ---- layer 2 ----
    gather_f16_split<<<(N2 + GROWS - 1) / GROWS, 256>>>(Hh, Hl, esrc2, rp2, N2, G2h, G2l);
    {
        dim3 grid(FH / 128, (N2 + 127) / 128);
        gemm2_mma<<<grid, 256, GSMEM2>>>(
            G2h, G2l, Hh, Hl, WtP[4], WtP[5], WtP[6], WtP[7],
            brel2, h2, N2);
    }

    // ---- head ----
    head_kernel<<<N2, 32>>>(h2, Wcomb, bcomb, out);

    (void)in_sizes; (void)n_in; (void)out_size;
}

// round 10
// speedup vs baseline: 5.4905x; 1.1695x over previous
#include <cuda_runtime.h>
#include <cuda_fp16.h>
#include <cstdint>

#define N0 100000
#define N1 20000
#define N2 4000
#define E1 500000
#define E2 100000
#define FH 512
#define C_OUT 10

// ---------------- scratch ---------------------------------------------------
__device__ float g_h2[(size_t)N2 * FH];

__device__ __half g_Xh [(size_t)N0 * FH];    // fp16 of x (all rows)
__device__ __half g_A1h[(size_t)N1 * FH];    // agg1 (fp16)
__device__ __half g_Hh [(size_t)N1 * FH];    // h (fp16)
__device__ __half g_G2h[(size_t)N2 * FH];    // agg2 (fp16)
__device__ __half g_Wt[8][(size_t)FH * FH];  // 0 rel1, 2 root1, 4 rel2, 6 root2 (hi slots used)
__device__ float g_Wcomb[(size_t)FH * C_OUT];
__device__ float g_bcomb[C_OUT];

// CSR scratch
__device__ int g_cnt1[N1], g_rp1[N1 + 1], g_pos1[N1], g_esrc1[E1];
__device__ int g_cnt2[N2], g_rp2[N2 + 1], g_pos2[N2], g_esrc2[E2];

// ---------------- helpers ---------------------------------------------------
__device__ __forceinline__ uint32_t smem_u32(const void* p) {
    uint32_t a;
    asm("{ .reg .u64 t; cvta.to.shared.u64 t, %1; cvt.u32.u64 %0, t; }"
        : "=r"(a) : "l"(p));
    return a;
}
__device__ __forceinline__ void cp_async16(uint32_t dst, const void* src, int sz) {
    asm volatile("cp.async.cg.shared.global [%0], [%1], 16, %2;"
                 :: "r"(dst), "l"(src), "r"(sz) : "memory");
}
__device__ __forceinline__ void cp_commit() {
    asm volatile("cp.async.commit_group;" ::: "memory");
}
__device__ __forceinline__ void cp_wait1() {
    asm volatile("cp.async.wait_group 1;" ::: "memory");
}
__device__ __forceinline__ uint32_t pack2(__half a, __half b) {
    __half2 t = __halves2half2(a, b);
    return *reinterpret_cast<uint32_t*>(&t);
}
__device__ __forceinline__ float2 h2f(uint32_t w) {
    __half2 t = *reinterpret_cast<__half2*>(&w);
    return __half22float2(t);
}
__device__ __forceinline__ void mma16816(float* c, const uint32_t* a,
                                         uint32_t b0, uint32_t b1) {
    asm("mma.sync.aligned.m16n8k16.row.col.f32.f16.f16.f32 "
        "{%0,%1,%2,%3}, {%4,%5,%6,%7}, {%8,%9}, {%0,%1,%2,%3};"
        : "+f"(c[0]), "+f"(c[1]), "+f"(c[2]), "+f"(c[3])
        : "r"(a[0]), "r"(a[1]), "r"(a[2]), "r"(a[3]), "r"(b0), "r"(b1));
}
#define LDX4(r, addr) \
    asm volatile("ldmatrix.sync.aligned.m8n8.x4.shared.b16 {%0,%1,%2,%3}, [%4];" \
                 : "=r"((r)[0]), "=r"((r)[1]), "=r"((r)[2]), "=r"((r)[3])        \
                 : "r"(addr))

// ---------------- x -> fp16 chunk converter (8 floats per chunk) -------------
#define NCH_TOTAL ((N0 * FH) / 8)
__device__ __forceinline__ void conv_chunk(const float4* __restrict__ x4,
                                           uint4* __restrict__ Xh4, int i) {
    float4 v0 = x4[2 * i], v1 = x4[2 * i + 1];
    Xh4[i] = make_uint4(
        pack2(__float2half_rn(v0.x), __float2half_rn(v0.y)),
        pack2(__float2half_rn(v0.z), __float2half_rn(v0.w)),
        pack2(__float2half_rn(v1.x), __float2half_rn(v1.y)),
        pack2(__float2half_rn(v1.z), __float2half_rn(v1.w)));
}

// ---------------- device bodies for folded prep work --------------------------
__device__ __forceinline__ void transpose_body(
    const float* __restrict__ W, __half* __restrict__ Bh,
    int bx, int by, int tx, int ty, float (*t)[33]) {
    int n0 = bx * 32, k0 = by * 32;
    for (int yy = ty; yy < 32; yy += 8)
        t[yy][tx] = W[(size_t)(k0 + yy) * FH + n0 + tx];
    __syncthreads();
    for (int yy = ty; yy < 32; yy += 8)
        Bh[(size_t)(n0 + yy) * FH + k0 + tx] = __float2half_rn(t[tx][yy]);
}

__device__ __forceinline__ void wcomb_body(
    int k, int lane,
    const float* __restrict__ Wlin, const float* __restrict__ Whead,
    const float* __restrict__ blin, const float* __restrict__ bhead,
    float* __restrict__ Wcomb, float* __restrict__ bcomb) {
    const float* rowv = (k < FH) ? (Wlin + (size_t)k * FH) : blin;
    float acc[C_OUT];
#pragma unroll
    for (int c = 0; c < C_OUT; ++c) acc[c] = 0.f;
    for (int j = lane; j < FH; j += 32) {
        float v = rowv[j];
        const float* w = Whead + (size_t)j * C_OUT;
#pragma unroll
        for (int c = 0; c < C_OUT; ++c) acc[c] += v * w[c];
    }
#pragma unroll
    for (int off = 16; off > 0; off >>= 1)
#pragma unroll
        for (int c = 0; c < C_OUT; ++c)
            acc[c] += __shfl_down_sync(0xFFFFFFFFu, acc[c], off);
    if (lane == 0) {
        if (k < FH) {
#pragma unroll
            for (int c = 0; c < C_OUT; ++c) Wcomb[(size_t)k * C_OUT + c] = acc[c];
        } else {
#pragma unroll
            for (int c = 0; c < C_OUT; ++c) bcomb[c] = acc[c] + bhead[c];
        }
    }
}

// ---------------- launch 1: zero counters + conv slice + weight transpose ----
__global__ void zero_conv_tr(int* __restrict__ c1, int* __restrict__ c2,
                             int zb, int cb,
                             const float4* __restrict__ x4, uint4* __restrict__ Xh4,
                             int convStart, int convEnd,
                             const float* __restrict__ W0, const float* __restrict__ W1,
                             const float* __restrict__ W2, const float* __restrict__ W3,
                             __half* __restrict__ Wt) {
    int bid = blockIdx.x;
    if (bid < zb) {
        int i = bid * blockDim.x + threadIdx.x;
        if (i < N1) c1[i] = 0;
        else if (i < N1 + N2) c2[i - N1] = 0;
    } else if (bid < zb + cb) {
        int i = convStart + (bid - zb) * blockDim.x + threadIdx.x;
        if (i < convEnd) conv_chunk(x4, Xh4, i);
    } else {
        __shared__ float t[32][33];
        int idx = bid - zb - cb;           // 0..1023
        int z = idx >> 8;
        int rem = idx & 255;
        const float* W = (z == 0) ? W0 : (z == 1) ? W1 : (z == 2) ? W2 : W3;
        __half* Bh = Wt + (size_t)(2 * z) * FH * FH;
        transpose_body(W, Bh, rem & 15, rem >> 4,
                       threadIdx.x & 31, threadIdx.x >> 5, t);
    }
}

// ---------------- launch 2: hist + conv slice + wcomb -------------------------
__global__ void hist_conv_wc(const int* __restrict__ d1, const int* __restrict__ d2,
                             int* __restrict__ c1, int* __restrict__ c2,
                             int hb, int cb,
                             const float4* __restrict__ x4, uint4* __restrict__ Xh4,
                             int convStart, int convEnd,
                             const float* __restrict__ Wlin, const float* __restrict__ Whead,
                             const float* __restrict__ blin, const float* __restrict__ bhead,
                             float* __restrict__ Wcomb, float* __restrict__ bcomb) {
    int bid = blockIdx.x;
    if (bid < hb) {
        int e = bid * blockDim.x + threadIdx.x;
        if (e < E1) atomicAdd(&c1[d1[e]], 1);
        else if (e < E1 + E2) atomicAdd(&c2[d2[e - E1]], 1);
    } else if (bid < hb + cb) {
        int i = convStart + (bid - hb) * blockDim.x + threadIdx.x;
        if (i < convEnd) conv_chunk(x4, Xh4, i);
    } else {
        int k = (bid - hb - cb) * 8 + (threadIdx.x >> 5);
        if (k <= FH)
            wcomb_body(k, threadIdx.x & 31, Wlin, Whead, blin, bhead, Wcomb, bcomb);
    }
}

// ---------------- scan ---------------------------------------------------------
__global__ __launch_bounds__(1024) void scan_both(
    const int* __restrict__ c1, int* __restrict__ r1, int* __restrict__ p1,
    const int* __restrict__ c2, int* __restrict__ r2, int* __restrict__ p2) {
    const int n = blockIdx.x ? N2 : N1;
    const int* cnt = blockIdx.x ? c2 : c1;
    int* rowptr = blockIdx.x ? r2 : r1;
    int* pos    = blockIdx.x ? p2 : p1;
    __shared__ int ts[1024];
    const int t = threadIdx.x;
    const int C = (n + 1023) >> 10;
    int local[20];
    int s = 0;
    for (int j = 0; j < C; ++j) {
        int idx = t * C + j;
        int v = (idx < n) ? cnt[idx] : 0;
        local[j] = s; s += v;
    }
    ts[t] = s;
    __syncthreads();
    for (int off = 1; off < 1024; off <<= 1) {
        int v = (t >= off) ? ts[t - off] : 0;
        __syncthreads();
        ts[t] += v;
        __syncthreads();
    }
    int base = (t > 0) ? ts[t - 1] : 0;
    for (int j = 0; j < C; ++j) {
        int idx = t * C + j;
        if (idx < n) { int r = base + local[j]; rowptr[idx] = r; pos[idx] = r; }
    }
    if (t == 1023) rowptr[n] = ts[1023];
}

// ---------------- launch 3: fill + conv slice ---------------------------------
__global__ void fill_conv(const int* __restrict__ d1, const int* __restrict__ s1,
                          int* __restrict__ p1, int* __restrict__ e1,
                          const int* __restrict__ d2, const int* __restrict__ s2,
                          int* __restrict__ p2, int* __restrict__ e2,
                          int baseBlocks,
                          const float4* __restrict__ x4, uint4* __restrict__ Xh4,
                          int convStart, int convEnd) {
    if ((int)blockIdx.x < baseBlocks) {
        int e = blockIdx.x * blockDim.x + threadIdx.x;
        if (e < E1) {
            int p = atomicAdd(&p1[d1[e]], 1);
            e1[p] = s1[e];
        } else if (e < E1 + E2) {
            int q = e - E1;
            int p = atomicAdd(&p2[d2[q]], 1);
            e2[p] = s2[q];
        }
    } else {
        int i = convStart + (blockIdx.x - baseBlocks) * blockDim.x + threadIdx.x;
        if (i < convEnd) conv_chunk(x4, Xh4, i);
    }
}

// ---------------- gather (fp16 src) -> fp16 agg, dynamic rows ----------------
#define GROWS 16
__global__ void gather_hi(const __half* __restrict__ Xh,
                          const int* __restrict__ esrc,
                          const int* __restrict__ rowptr, int nrows,
                          __half* __restrict__ Ah) {
    __shared__ int cur;
    if (threadIdx.x == 0) cur = 0;
    __syncthreads();
    const int base = blockIdx.x * GROWS;
    const int lane = threadIdx.x & 31;
    for (;;) {
        int r = 0;
        if (lane == 0) r = atomicAdd(&cur, 1);
        r = __shfl_sync(0xFFFFFFFFu, r, 0);
        if (r >= GROWS) break;
        int row = base + r;
        if (row >= nrows) break;
        const int beg = rowptr[row], end = rowptr[row + 1];
        float acc[16];
#pragma unroll
        for (int j = 0; j < 16; ++j) acc[j] = 0.f;
        int i = beg;
        for (; i + 2 <= end; i += 2) {
            size_t b0 = (size_t)__ldg(&esrc[i]) * FH + lane * 16;
            size_t b1 = (size_t)__ldg(&esrc[i + 1]) * FH + lane * 16;
            uint4 U0 = *(const uint4*)(Xh + b0);
            uint4 U1 = *(const uint4*)(Xh + b0 + 8);
            uint4 V0 = *(const uint4*)(Xh + b1);
            uint4 V1 = *(const uint4*)(Xh + b1 + 8);
            uint32_t uw[8] = {U0.x, U0.y, U0.z, U0.w, U1.x, U1.y, U1.z, U1.w};
            uint32_t vw[8] = {V0.x, V0.y, V0.z, V0.w, V1.x, V1.y, V1.z, V1.w};
#pragma unroll
            for (int j = 0; j < 8; ++j) {
                float2 a = h2f(uw[j]), b = h2f(vw[j]);
                acc[2 * j]     += a.x + b.x;
                acc[2 * j + 1] += a.y + b.y;
            }
        }
        if (i < end) {
            size_t b0 = (size_t)__ldg(&esrc[i]) * FH + lane * 16;
            uint4 U0 = *(const uint4*)(Xh + b0);
            uint4 U1 = *(const uint4*)(Xh + b0 + 8);
            uint32_t uw[8] = {U0.x, U0.y, U0.z, U0.w, U1.x, U1.y, U1.z, U1.w};
#pragma unroll
            for (int j = 0; j < 8; ++j) {
                float2 a = h2f(uw[j]);
                acc[2 * j]     += a.x;
                acc[2 * j + 1] += a.y;
            }
        }
        uint32_t hp[8];
#pragma unroll
        for (int j = 0; j < 8; ++j)
            hp[j] = pack2(__float2half_rn(acc[2 * j]), __float2half_rn(acc[2 * j + 1]));
        size_t o = (size_t)row * FH + lane * 16;
        *(uint4*)(Ah + o)     = make_uint4(hp[0], hp[1], hp[2], hp[3]);
        *(uint4*)(Ah + o + 8) = make_uint4(hp[4], hp[5], hp[6], hp[7]);
    }
}

// ---------------- head -------------------------------------------------------
__global__ void head_kernel(const float* __restrict__ h2,
                            const float* __restrict__ Wcomb,
                            const float* __restrict__ bcomb,
                            float* __restrict__ out) {
    int r = blockIdx.x;
    int lane = threadIdx.x;
    float acc[C_OUT];
#pragma unroll
    for (int c = 0; c < C_OUT; ++c) acc[c] = 0.f;
    const float* trow = h2 + (size_t)r * FH;
    for (int k = lane; k < FH; k += 32) {
        float t = trow[k];
        const float* w = Wcomb + (size_t)k * C_OUT;
#pragma unroll
        for (int c = 0; c < C_OUT; ++c) acc[c] += t * w[c];
    }
#pragma unroll
    for (int off = 16; off > 0; off >>= 1)
#pragma unroll
        for (int c = 0; c < C_OUT; ++c)
            acc[c] += __shfl_down_sync(0xFFFFFFFFu, acc[c], off);
    if (lane == 0) {
#pragma unroll
        for (int c = 0; c < C_OUT; ++c) out[(size_t)r * C_OUT + c] = acc[c] + bcomb[c];
    }
}

// ---------------- unified fp16 dual-source GEMM (hi-only, 3-stage pipe) ------
// C = act( A0@B0 + A1@B1 + bias );  F16OUT: fp16 out (+relu), else f32 out.
#define SA 40
#define NBUF 3

template <bool RELU, bool F16OUT>
__global__ __launch_bounds__(256) void gemm_hi(
    const __half* __restrict__ A0, const __half* __restrict__ B0,
    const __half* __restrict__ A1, const __half* __restrict__ B1,
    const float* __restrict__ bias,
    __half* __restrict__ Ch, float* __restrict__ Cf, int M) {
    extern __shared__ __half sm[];
    const int tid = threadIdx.x;
    const int lane = tid & 31;
    const int wid = tid >> 5;
    const int wm = wid & 3;
    const int wn = wid >> 2;
    const int m0 = blockIdx.y * 128;
    const int n0 = blockIdx.x * 128;

    float acc[2][8][4];
#pragma unroll
    for (int i = 0; i < 2; ++i)
#pragma unroll
        for (int j = 0; j < 8; ++j)
#pragma unroll
            for (int q = 0; q < 4; ++q) acc[i][j][q] = 0.f;

    const int r0 = tid >> 2;
    const int c8 = (tid & 3) * 8;

    auto tile_off = [&](int buf, int t, int row, int col) -> uint32_t {
        return (uint32_t)((((buf * 2 + t) * 128 + row) * SA + col) * 2);
    };
    const uint32_t smb = smem_u32(sm);

    constexpr int NST = 32;
    auto issue = [&](int buf, int s) {
        const int src = s >> 4;
        const int k0 = (s & 15) * 32;
        const __half* A = src ? A1 : A0;
        const __half* B = src ? B1 : B0;
#pragma unroll
        for (int i = 0; i < 2; ++i) {
            int row = r0 + i * 64;
            int gm = m0 + row;
            cp_async16(smb + tile_off(buf, 0, row, c8),
                       A + (size_t)gm * FH + k0 + c8, gm < M ? 16 : 0);
            cp_async16(smb + tile_off(buf, 1, row, c8),
                       B + (size_t)(n0 + row) * FH + k0 + c8, 16);
        }
        cp_commit();
    };

    issue(0, 0);
    issue(1, 1);

    const int lrow = lane & 15;
    const int lcol = (lane >> 4) << 3;
    const int fr = lane >> 2;
    const int fc = (lane & 3) * 2;

#pragma unroll 1
    for (int s = 0; s < NST; ++s) {
        cp_wait1();                 // stage s data resident (s+1 may pend)
        __syncthreads();            // also guards buffer reuse from prev compute
        if (s + 2 < NST) issue((s + 2) % NBUF, s + 2);
        else cp_commit();           // keep group accounting aligned at tail
        const int buf = s % NBUF;
#pragma unroll
        for (int kk = 0; kk < 32; kk += 16) {
            uint32_t ah[2][4], bb[4][4];
#pragma unroll
            for (int mi = 0; mi < 2; ++mi) {
                int rb = wm * 32 + mi * 16 + lrow;
                LDX4(ah[mi], smb + tile_off(buf, 0, rb, kk + lcol));
            }
#pragma unroll
            for (int np = 0; np < 4; ++np) {
                int nb = wn * 64 + np * 16 + lrow;
                LDX4(bb[np], smb + tile_off(buf, 1, nb, kk + lcol));
            }
#pragma unroll
            for (int np = 0; np < 4; ++np) {
#pragma unroll
                for (int mi = 0; mi < 2; ++mi) {
                    mma16816(acc[mi][2 * np],     ah[mi], bb[np][0], bb[np][2]);
                    mma16816(acc[mi][2 * np + 1], ah[mi], bb[np][1], bb[np][3]);
                }
            }
        }
    }

    // -------- epilogue --------
#pragma unroll
    for (int mi = 0; mi < 2; ++mi) {
#pragma unroll
        for (int half = 0; half < 2; ++half) {
            int row = m0 + wm * 32 + mi * 16 + fr + half * 8;
            if (row >= M) continue;
#pragma unroll
            for (int ni = 0; ni < 8; ++ni) {
                int col = n0 + wn * 64 + ni * 8 + fc;
                float v0 = acc[mi][ni][half * 2 + 0] + bias[col];
                float v1 = acc[mi][ni][half * 2 + 1] + bias[col + 1];
                if (RELU) { v0 = fmaxf(v0, 0.f); v1 = fmaxf(v1, 0.f); }
                if (F16OUT) {
                    *(uint32_t*)(Ch + (size_t)row * FH + col) =
                        pack2(__float2half_rn(v0), __float2half_rn(v1));
                } else {
                    *(float2*)(Cf + (size_t)row * FH + col) = make_float2(v0, v1);
                }
            }
        }
    }
}

// ---------------------------------------------------------------------------
extern "C" void kernel_launch(void* const* d_in, const int* in_sizes, int n_in,
                              void* d_out, int out_size) {
    const float* x     = (const float*)d_in[0];
    const int*   src1  = (const int*)  d_in[1];
    const int*   dst1  = (const int*)  d_in[2];
    const int*   src2  = (const int*)  d_in[3];
    const int*   dst2  = (const int*)  d_in[4];
    const float* Wrel1 = (const float*)d_in[5];
    const float* brel1 = (const float*)d_in[6];
    const float* Wroot1= (const float*)d_in[7];
    const float* Wrel2 = (const float*)d_in[8];
    const float* brel2 = (const float*)d_in[9];
    const float* Wroot2= (const float*)d_in[10];
    const float* Wlin  = (const float*)d_in[11];
    const float* blin  = (const float*)d_in[12];
    const float* Whead = (const float*)d_in[13];
    const float* bhead = (const float*)d_in[14];
    float* out = (float*)d_out;

    float *h2, *Wcomb, *bcomb;
    __half *Xh, *A1h, *Hh, *G2h, *Wt;
    int *cnt1, *rp1, *pos1, *esrc1, *cnt2, *rp2, *pos2, *esrc2;
    cudaGetSymbolAddress((void**)&h2,   g_h2);
    cudaGetSymbolAddress((void**)&Xh,   g_Xh);
    cudaGetSymbolAddress((void**)&A1h,  g_A1h);
    cudaGetSymbolAddress((void**)&Hh,   g_Hh);
    cudaGetSymbolAddress((void**)&G2h,  g_G2h);
    cudaGetSymbolAddress((void**)&Wt,   g_Wt);
    cudaGetSymbolAddress((void**)&Wcomb, g_Wcomb);
    cudaGetSymbolAddress((void**)&bcomb, g_bcomb);
    cudaGetSymbolAddress((void**)&cnt1, g_cnt1);
    cudaGetSymbolAddress((void**)&rp1,  g_rp1);
    cudaGetSymbolAddress((void**)&pos1, g_pos1);
    cudaGetSymbolAddress((void**)&esrc1, g_esrc1);
    cudaGetSymbolAddress((void**)&cnt2, g_cnt2);
    cudaGetSymbolAddress((void**)&rp2,  g_rp2);
    cudaGetSymbolAddress((void**)&pos2, g_pos2);
    cudaGetSymbolAddress((void**)&esrc2, g_esrc2);
    __half* WtP[8];
    for (int i = 0; i < 8; ++i) WtP[i] = Wt + (size_t)i * FH * FH;

    constexpr int GSMEM = NBUF * 2 * 128 * SA * 2;  // 61440 B
    cudaFuncSetAttribute(gemm_hi<true, true>,
                         cudaFuncAttributeMaxDynamicSharedMemorySize, GSMEM);
    cudaFuncSetAttribute(gemm_hi<false, false>,
                         cudaFuncAttributeMaxDynamicSharedMemorySize, GSMEM);

    // conv slice partition across the three CSR launches
    const int convA = (NCH_TOTAL * 2) / 5;
    const int convB = convA + (NCH_TOTAL * 3) / 10;

    // ---- launch 1: zero + conv + transposes ----
    {
        int zb = (N1 + N2 + 255) / 256;
        int cb = (convA + 255) / 256;
        zero_conv_tr<<<zb + cb + 1024, 256>>>(
            cnt1, cnt2, zb, cb, (const float4*)x, (uint4*)Xh, 0, convA,
            Wrel1, Wroot1, Wrel2, Wroot2, Wt);
    }
    // ---- launch 2: hist + conv + wcomb ----
    {
        int hb = (E1 + E2 + 255) / 256;
        int cb = (convB - convA + 255) / 256;
        int wb = (FH + 1 + 7) / 8;   // 65 blocks, warp per k-row
        hist_conv_wc<<<hb + cb + wb, 256>>>(
            dst1, dst2, cnt1, cnt2, hb, cb,
            (const float4*)x, (uint4*)Xh, convA, convB,
            Wlin, Whead, blin, bhead, Wcomb, bcomb);
    }
    scan_both<<<2, 1024>>>(cnt1, rp1, pos1, cnt2, rp2, pos2);
    // ---- launch 3: fill + conv ----
    {
        int hb = (E1 + E2 + 255) / 256;
        int cb = (NCH_TOTAL - convB + 255) / 256;
        fill_conv<<<hb + cb, 256>>>(dst1, src1, pos1, esrc1,
                                    dst2, src2, pos2, esrc2, hb,
                                    (const float4*)x, (uint4*)Xh, convB, NCH_TOTAL);
    }

    // ---- layer 1 ----
    gather_hi<<<(N1 + GROWS - 1) / GROWS, 256>>>(Xh, esrc1, rp1, N1, A1h);
    {
        dim3 grid(FH / 128, (N1 + 127) / 128);
        gemm_hi<true, true><<<grid, 256, GSMEM>>>(
            A1h, WtP[0], Xh, WtP[2], brel1, Hh, nullptr, N1);
    }

    // ---- layer 2 ----
    gather_hi<<<(N2 + GROWS - 1) / GROWS, 256>>>(Hh, esrc2, rp2, N2, G2h);
    {
        dim3 grid(FH / 128, (N2 + 127) / 128);
        gemm_hi<false, false><<<grid, 256, GSMEM>>>(
            G2h, WtP[4], Hh, WtP[6], brel2, nullptr, h2, N2);
    }

    // ---- head ----
    head_kernel<<<N2, 32>>>(h2, Wcomb, bcomb, out);

    (void)in_sizes; (void)n_in; (void)out_size;
}

// round 11
// speedup vs baseline: 5.9651x; 1.0864x over previous
#include <cuda_runtime.h>
#include <cuda_fp16.h>
#include <cstdint>

#define N0 100000
#define N1 20000
#define N2 4000
#define E1 500000
#define E2 100000
#define FH 512
#define C_OUT 10

// ---------------- scratch ---------------------------------------------------
__device__ __half g_Xh [(size_t)N0 * FH];    // fp16 of x (all rows)
__device__ __half g_A1h[(size_t)N1 * FH];    // agg1 (fp16)
__device__ __half g_Hh [(size_t)N1 * FH];    // h (fp16)
__device__ __half g_Wt[4][(size_t)FH * FH];  // 0 rel1, 2 root1 (transposed fp16)
__device__ float g_Wcomb[(size_t)FH * C_OUT];
__device__ float g_bcomb[C_OUT];
// folded layer-2 weights: [2][256 pairs][21] (pair-padded, conflict-free LDS)
#define WC2_PITCH 21
#define WC2_MAT (256 * WC2_PITCH)     // 5376 floats per matrix
__device__ float g_Wc2[2 * WC2_MAT];
__device__ float g_bc2[C_OUT];

// CSR scratch
__device__ int g_cnt1[N1], g_rp1[N1 + 1], g_pos1[N1], g_esrc1[E1];
__device__ int g_cnt2[N2], g_rp2[N2 + 1], g_pos2[N2], g_esrc2[E2];

// ---------------- helpers ---------------------------------------------------
__device__ __forceinline__ uint32_t smem_u32(const void* p) {
    uint32_t a;
    asm("{ .reg .u64 t; cvta.to.shared.u64 t, %1; cvt.u32.u64 %0, t; }"
        : "=r"(a) : "l"(p));
    return a;
}
__device__ __forceinline__ void cp_async16(uint32_t dst, const void* src, int sz) {
    asm volatile("cp.async.cg.shared.global [%0], [%1], 16, %2;"
                 :: "r"(dst), "l"(src), "r"(sz) : "memory");
}
__device__ __forceinline__ void cp_commit() {
    asm volatile("cp.async.commit_group;" ::: "memory");
}
__device__ __forceinline__ void cp_wait1() {
    asm volatile("cp.async.wait_group 1;" ::: "memory");
}
__device__ __forceinline__ uint32_t pack2(__half a, __half b) {
    __half2 t = __halves2half2(a, b);
    return *reinterpret_cast<uint32_t*>(&t);
}
__device__ __forceinline__ float2 h2f(uint32_t w) {
    __half2 t = *reinterpret_cast<__half2*>(&w);
    return __half22float2(t);
}
__device__ __forceinline__ void mma16816(float* c, const uint32_t* a,
                                         uint32_t b0, uint32_t b1) {
    asm("mma.sync.aligned.m16n8k16.row.col.f32.f16.f16.f32 "
        "{%0,%1,%2,%3}, {%4,%5,%6,%7}, {%8,%9}, {%0,%1,%2,%3};"
        : "+f"(c[0]), "+f"(c[1]), "+f"(c[2]), "+f"(c[3])
        : "r"(a[0]), "r"(a[1]), "r"(a[2]), "r"(a[3]), "r"(b0), "r"(b1));
}
#define LDX4(r, addr) \
    asm volatile("ldmatrix.sync.aligned.m8n8.x4.shared.b16 {%0,%1,%2,%3}, [%4];" \
                 : "=r"((r)[0]), "=r"((r)[1]), "=r"((r)[2]), "=r"((r)[3])        \
                 : "r"(addr))

// ---------------- x -> fp16 chunk converter ----------------------------------
#define NCH_TOTAL ((N0 * FH) / 8)
__device__ __forceinline__ void conv_chunk(const float4* __restrict__ x4,
                                           uint4* __restrict__ Xh4, int i) {
    float4 v0 = x4[2 * i], v1 = x4[2 * i + 1];
    Xh4[i] = make_uint4(
        pack2(__float2half_rn(v0.x), __float2half_rn(v0.y)),
        pack2(__float2half_rn(v0.z), __float2half_rn(v0.w)),
        pack2(__float2half_rn(v1.x), __float2half_rn(v1.y)),
        pack2(__float2half_rn(v1.z), __float2half_rn(v1.w)));
}

// ---------------- folded prep bodies ------------------------------------------
__device__ __forceinline__ void transpose_body(
    const float* __restrict__ W, __half* __restrict__ Bh,
    int bx, int by, int tx, int ty, float (*t)[33]) {
    int n0 = bx * 32, k0 = by * 32;
    for (int yy = ty; yy < 32; yy += 8)
        t[yy][tx] = W[(size_t)(k0 + yy) * FH + n0 + tx];
    __syncthreads();
    for (int yy = ty; yy < 32; yy += 8)
        Bh[(size_t)(n0 + yy) * FH + k0 + tx] = __float2half_rn(t[tx][yy]);
}

__device__ __forceinline__ void wcomb_body(
    int k, int lane,
    const float* __restrict__ Wlin, const float* __restrict__ Whead,
    const float* __restrict__ blin, const float* __restrict__ bhead,
    float* __restrict__ Wcomb, float* __restrict__ bcomb) {
    const float* rowv = (k < FH) ? (Wlin + (size_t)k * FH) : blin;
    float acc[C_OUT];
#pragma unroll
    for (int c = 0; c < C_OUT; ++c) acc[c] = 0.f;
    for (int j = lane; j < FH; j += 32) {
        float v = rowv[j];
        const float* w = Whead + (size_t)j * C_OUT;
#pragma unroll
        for (int c = 0; c < C_OUT; ++c) acc[c] += v * w[c];
    }
#pragma unroll
    for (int off = 16; off > 0; off >>= 1)
#pragma unroll
        for (int c = 0; c < C_OUT; ++c)
            acc[c] += __shfl_down_sync(0xFFFFFFFFu, acc[c], off);
    if (lane == 0) {
        if (k < FH) {
#pragma unroll
            for (int c = 0; c < C_OUT; ++c) Wcomb[(size_t)k * C_OUT + c] = acc[c];
        } else {
#pragma unroll
            for (int c = 0; c < C_OUT; ++c) bcomb[c] = acc[c] + bhead[c];
        }
    }
}

// fold layer-2: Wc2[m] = (m? Wroot2 : Wrel2) @ Wcomb; bc2 = brel2@Wcomb + bcomb
__device__ __forceinline__ void wfold_body(
    int idx, int lane,
    const float* __restrict__ Wrel2, const float* __restrict__ Wroot2,
    const float* __restrict__ brel2,
    const float* __restrict__ Wcomb, const float* __restrict__ bcomb,
    float* __restrict__ Wc2, float* __restrict__ bc2) {
    float acc[C_OUT];
#pragma unroll
    for (int c = 0; c < C_OUT; ++c) acc[c] = 0.f;
    if (idx < 2 * FH) {
        int m = idx >> 9, k = idx & (FH - 1);
        const float* W = m ? Wroot2 : Wrel2;
        for (int j = lane; j < FH; j += 32) {
            float v = W[(size_t)k * FH + j];
            const float* wc = Wcomb + (size_t)j * C_OUT;
#pragma unroll
            for (int c = 0; c < C_OUT; ++c) acc[c] += v * wc[c];
        }
#pragma unroll
        for (int off = 16; off > 0; off >>= 1)
#pragma unroll
            for (int c = 0; c < C_OUT; ++c)
                acc[c] += __shfl_down_sync(0xFFFFFFFFu, acc[c], off);
        if (lane == 0) {
            int p = k >> 1, dd = k & 1;
            float* dst = Wc2 + (size_t)m * WC2_MAT + p * WC2_PITCH + dd * C_OUT;
#pragma unroll
            for (int c = 0; c < C_OUT; ++c) dst[c] = acc[c];
        }
    } else if (idx == 2 * FH) {
        for (int j = lane; j < FH; j += 32) {
            float v = brel2[j];
            const float* wc = Wcomb + (size_t)j * C_OUT;
#pragma unroll
            for (int c = 0; c < C_OUT; ++c) acc[c] += v * wc[c];
        }
#pragma unroll
        for (int off = 16; off > 0; off >>= 1)
#pragma unroll
            for (int c = 0; c < C_OUT; ++c)
                acc[c] += __shfl_down_sync(0xFFFFFFFFu, acc[c], off);
        if (lane == 0) {
#pragma unroll
            for (int c = 0; c < C_OUT; ++c) bc2[c] = acc[c] + bcomb[c];
        }
    }
}

// ---------------- launch 1: zero counters + conv slice + transposes ----------
__global__ void zero_conv_tr(int* __restrict__ c1, int* __restrict__ c2,
                             int zb, int cb,
                             const float4* __restrict__ x4, uint4* __restrict__ Xh4,
                             int convStart, int convEnd,
                             const float* __restrict__ W0, const float* __restrict__ W1,
                             __half* __restrict__ Wt) {
    int bid = blockIdx.x;
    if (bid < zb) {
        int i = bid * blockDim.x + threadIdx.x;
        if (i < N1) c1[i] = 0;
        else if (i < N1 + N2) c2[i - N1] = 0;
    } else if (bid < zb + cb) {
        int i = convStart + (bid - zb) * blockDim.x + threadIdx.x;
        if (i < convEnd) conv_chunk(x4, Xh4, i);
    } else {
        __shared__ float t[32][33];
        int idx = bid - zb - cb;           // 0..511
        int z = idx >> 8;                  // 0 rel1, 1 root1
        int rem = idx & 255;
        const float* W = z ? W1 : W0;
        __half* Bh = Wt + (size_t)(2 * z) * FH * FH;
        transpose_body(W, Bh, rem & 15, rem >> 4,
                       threadIdx.x & 31, threadIdx.x >> 5, t);
    }
}

// ---------------- launch 2: hist + conv slice + wcomb -------------------------
__global__ void hist_conv_wc(const int* __restrict__ d1, const int* __restrict__ d2,
                             int* __restrict__ c1, int* __restrict__ c2,
                             int hb, int cb,
                             const float4* __restrict__ x4, uint4* __restrict__ Xh4,
                             int convStart, int convEnd,
                             const float* __restrict__ Wlin, const float* __restrict__ Whead,
                             const float* __restrict__ blin, const float* __restrict__ bhead,
                             float* __restrict__ Wcomb, float* __restrict__ bcomb) {
    int bid = blockIdx.x;
    if (bid < hb) {
        int e = bid * blockDim.x + threadIdx.x;
        if (e < E1) atomicAdd(&c1[d1[e]], 1);
        else if (e < E1 + E2) atomicAdd(&c2[d2[e - E1]], 1);
    } else if (bid < hb + cb) {
        int i = convStart + (bid - hb) * blockDim.x + threadIdx.x;
        if (i < convEnd) conv_chunk(x4, Xh4, i);
    } else {
        int k = (bid - hb - cb) * 8 + (threadIdx.x >> 5);
        if (k <= FH)
            wcomb_body(k, threadIdx.x & 31, Wlin, Whead, blin, bhead, Wcomb, bcomb);
    }
}

// ---------------- scan ---------------------------------------------------------
__global__ __launch_bounds__(1024) void scan_both(
    const int* __restrict__ c1, int* __restrict__ r1, int* __restrict__ p1,
    const int* __restrict__ c2, int* __restrict__ r2, int* __restrict__ p2) {
    const int n = blockIdx.x ? N2 : N1;
    const int* cnt = blockIdx.x ? c2 : c1;
    int* rowptr = blockIdx.x ? r2 : r1;
    int* pos    = blockIdx.x ? p2 : p1;
    __shared__ int ts[1024];
    const int t = threadIdx.x;
    const int C = (n + 1023) >> 10;
    int local[20];
    int s = 0;
    for (int j = 0; j < C; ++j) {
        int idx = t * C + j;
        int v = (idx < n) ? cnt[idx] : 0;
        local[j] = s; s += v;
    }
    ts[t] = s;
    __syncthreads();
    for (int off = 1; off < 1024; off <<= 1) {
        int v = (t >= off) ? ts[t - off] : 0;
        __syncthreads();
        ts[t] += v;
        __syncthreads();
    }
    int base = (t > 0) ? ts[t - 1] : 0;
    for (int j = 0; j < C; ++j) {
        int idx = t * C + j;
        if (idx < n) { int r = base + local[j]; rowptr[idx] = r; pos[idx] = r; }
    }
    if (t == 1023) rowptr[n] = ts[1023];
}

// ---------------- launch 3: fill + conv slice + wfold --------------------------
__global__ void fill_conv_wf(const int* __restrict__ d1, const int* __restrict__ s1,
                             int* __restrict__ p1, int* __restrict__ e1,
                             const int* __restrict__ d2, const int* __restrict__ s2,
                             int* __restrict__ p2, int* __restrict__ e2,
                             int fb, int cb,
                             const float4* __restrict__ x4, uint4* __restrict__ Xh4,
                             int convStart, int convEnd,
                             const float* __restrict__ Wrel2, const float* __restrict__ Wroot2,
                             const float* __restrict__ brel2,
                             const float* __restrict__ Wcomb, const float* __restrict__ bcomb,
                             float* __restrict__ Wc2, float* __restrict__ bc2) {
    int bid = blockIdx.x;
    if (bid < fb) {
        int e = bid * blockDim.x + threadIdx.x;
        if (e < E1) {
            int p = atomicAdd(&p1[d1[e]], 1);
            e1[p] = s1[e];
        } else if (e < E1 + E2) {
            int q = e - E1;
            int p = atomicAdd(&p2[d2[q]], 1);
            e2[p] = s2[q];
        }
    } else if (bid < fb + cb) {
        int i = convStart + (bid - fb) * blockDim.x + threadIdx.x;
        if (i < convEnd) conv_chunk(x4, Xh4, i);
    } else {
        int idx = (bid - fb - cb) * 8 + (threadIdx.x >> 5);
        wfold_body(idx, threadIdx.x & 31, Wrel2, Wroot2, brel2, Wcomb, bcomb,
                   Wc2, bc2);
    }
}

// ---------------- gather (fp16 src) -> fp16 agg, dynamic rows ----------------
#define GROWS 16
__global__ void gather_hi(const __half* __restrict__ Xh,
                          const int* __restrict__ esrc,
                          const int* __restrict__ rowptr, int nrows,
                          __half* __restrict__ Ah) {
    __shared__ int cur;
    if (threadIdx.x == 0) cur = 0;
    __syncthreads();
    const int base = blockIdx.x * GROWS;
    const int lane = threadIdx.x & 31;
    for (;;) {
        int r = 0;
        if (lane == 0) r = atomicAdd(&cur, 1);
        r = __shfl_sync(0xFFFFFFFFu, r, 0);
        if (r >= GROWS) break;
        int row = base + r;
        if (row >= nrows) break;
        const int beg = rowptr[row], end = rowptr[row + 1];
        float acc[16];
#pragma unroll
        for (int j = 0; j < 16; ++j) acc[j] = 0.f;
        int i = beg;
        for (; i + 2 <= end; i += 2) {
            size_t b0 = (size_t)__ldg(&esrc[i]) * FH + lane * 16;
            size_t b1 = (size_t)__ldg(&esrc[i + 1]) * FH + lane * 16;
            uint4 U0 = *(const uint4*)(Xh + b0);
            uint4 U1 = *(const uint4*)(Xh + b0 + 8);
            uint4 V0 = *(const uint4*)(Xh + b1);
            uint4 V1 = *(const uint4*)(Xh + b1 + 8);
            uint32_t uw[8] = {U0.x, U0.y, U0.z, U0.w, U1.x, U1.y, U1.z, U1.w};
            uint32_t vw[8] = {V0.x, V0.y, V0.z, V0.w, V1.x, V1.y, V1.z, V1.w};
#pragma unroll
            for (int j = 0; j < 8; ++j) {
                float2 a = h2f(uw[j]), b = h2f(vw[j]);
                acc[2 * j]     += a.x + b.x;
                acc[2 * j + 1] += a.y + b.y;
            }
        }
        if (i < end) {
            size_t b0 = (size_t)__ldg(&esrc[i]) * FH + lane * 16;
            uint4 U0 = *(const uint4*)(Xh + b0);
            uint4 U1 = *(const uint4*)(Xh + b0 + 8);
            uint32_t uw[8] = {U0.x, U0.y, U0.z, U0.w, U1.x, U1.y, U1.z, U1.w};
#pragma unroll
            for (int j = 0; j < 8; ++j) {
                float2 a = h2f(uw[j]);
                acc[2 * j]     += a.x;
                acc[2 * j + 1] += a.y;
            }
        }
        uint32_t hp[8];
#pragma unroll
        for (int j = 0; j < 8; ++j)
            hp[j] = pack2(__float2half_rn(acc[2 * j]), __float2half_rn(acc[2 * j + 1]));
        size_t o = (size_t)row * FH + lane * 16;
        *(uint4*)(Ah + o)     = make_uint4(hp[0], hp[1], hp[2], hp[3]);
        *(uint4*)(Ah + o + 8) = make_uint4(hp[4], hp[5], hp[6], hp[7]);
    }
}

// ---------------- layer-1 GEMM (hi-only, 3-stage pipeline) -------------------
#define SA 40
#define NBUF 3

__global__ __launch_bounds__(256) void gemm1_hi(
    const __half* __restrict__ A0, const __half* __restrict__ B0,
    const __half* __restrict__ A1, const __half* __restrict__ B1,
    const float* __restrict__ bias,
    __half* __restrict__ Ch, int M) {
    extern __shared__ __half sm[];
    const int tid = threadIdx.x;
    const int lane = tid & 31;
    const int wid = tid >> 5;
    const int wm = wid & 3;
    const int wn = wid >> 2;
    const int m0 = blockIdx.y * 128;
    const int n0 = blockIdx.x * 128;

    float acc[2][8][4];
#pragma unroll
    for (int i = 0; i < 2; ++i)
#pragma unroll
        for (int j = 0; j < 8; ++j)
#pragma unroll
            for (int q = 0; q < 4; ++q) acc[i][j][q] = 0.f;

    const int r0 = tid >> 2;
    const int c8 = (tid & 3) * 8;

    auto tile_off = [&](int buf, int t, int row, int col) -> uint32_t {
        return (uint32_t)((((buf * 2 + t) * 128 + row) * SA + col) * 2);
    };
    const uint32_t smb = smem_u32(sm);

    constexpr int NST = 32;
    auto issue = [&](int buf, int s) {
        const int src = s >> 4;
        const int k0 = (s & 15) * 32;
        const __half* A = src ? A1 : A0;
        const __half* B = src ? B1 : B0;
#pragma unroll
        for (int i = 0; i < 2; ++i) {
            int row = r0 + i * 64;
            int gm = m0 + row;
            cp_async16(smb + tile_off(buf, 0, row, c8),
                       A + (size_t)gm * FH + k0 + c8, gm < M ? 16 : 0);
            cp_async16(smb + tile_off(buf, 1, row, c8),
                       B + (size_t)(n0 + row) * FH + k0 + c8, 16);
        }
        cp_commit();
    };

    issue(0, 0);
    issue(1, 1);

    const int lrow = lane & 15;
    const int lcol = (lane >> 4) << 3;
    const int fr = lane >> 2;
    const int fc = (lane & 3) * 2;

#pragma unroll 1
    for (int s = 0; s < NST; ++s) {
        cp_wait1();
        __syncthreads();
        if (s + 2 < NST) issue((s + 2) % NBUF, s + 2);
        else cp_commit();
        const int buf = s % NBUF;
#pragma unroll
        for (int kk = 0; kk < 32; kk += 16) {
            uint32_t ah[2][4], bb[4][4];
#pragma unroll
            for (int mi = 0; mi < 2; ++mi) {
                int rb = wm * 32 + mi * 16 + lrow;
                LDX4(ah[mi], smb + tile_off(buf, 0, rb, kk + lcol));
            }
#pragma unroll
            for (int np = 0; np < 4; ++np) {
                int nb = wn * 64 + np * 16 + lrow;
                LDX4(bb[np], smb + tile_off(buf, 1, nb, kk + lcol));
            }
#pragma unroll
            for (int np = 0; np < 4; ++np) {
#pragma unroll
                for (int mi = 0; mi < 2; ++mi) {
                    mma16816(acc[mi][2 * np],     ah[mi], bb[np][0], bb[np][2]);
                    mma16816(acc[mi][2 * np + 1], ah[mi], bb[np][1], bb[np][3]);
                }
            }
        }
    }

    // epilogue: relu + fp16
#pragma unroll
    for (int mi = 0; mi < 2; ++mi) {
#pragma unroll
        for (int half = 0; half < 2; ++half) {
            int row = m0 + wm * 32 + mi * 16 + fr + half * 8;
            if (row >= M) continue;
#pragma unroll
            for (int ni = 0; ni < 8; ++ni) {
                int col = n0 + wn * 64 + ni * 8 + fc;
                float v0 = fmaxf(acc[mi][ni][half * 2 + 0] + bias[col], 0.f);
                float v1 = fmaxf(acc[mi][ni][half * 2 + 1] + bias[col + 1], 0.f);
                *(uint32_t*)(Ch + (size_t)row * FH + col) =
                    pack2(__float2half_rn(v0), __float2half_rn(v1));
            }
        }
    }
}

// ---------------- fused layer 2 + head ---------------------------------------
// out[r,:] = (sum_e h[src_e]) @ Wc2rel + h[r] @ Wc2root + bc2   (all fp32)
__global__ __launch_bounds__(256) void layer2_fused(
    const uint32_t* __restrict__ Hh32,       // h as packed half2, 256 u32/row
    const int* __restrict__ esrc, const int* __restrict__ rowptr,
    const float* __restrict__ Wc2, const float* __restrict__ bc2,
    float* __restrict__ out) {
    __shared__ float ws[2 * WC2_MAT];        // 43008 B
    __shared__ float bs[C_OUT];
    for (int i = threadIdx.x; i < 2 * WC2_MAT; i += 256) ws[i] = Wc2[i];
    if (threadIdx.x < C_OUT) bs[threadIdx.x] = bc2[threadIdx.x];
    __syncthreads();

    const int lane = threadIdx.x & 31;
    int row = blockIdx.x * 8 + (threadIdx.x >> 5);
    if (row >= N2) return;
    const int beg = rowptr[row], end = rowptr[row + 1];

    // gather agg row (strided pairs: pair index p = lane + 32q)
    float agg[16];
#pragma unroll
    for (int j = 0; j < 16; ++j) agg[j] = 0.f;
    for (int i = beg; i < end; ++i) {
        const uint32_t* hrow = Hh32 + (size_t)__ldg(&esrc[i]) * 256;
#pragma unroll
        for (int q = 0; q < 8; ++q) {
            float2 f = h2f(hrow[lane + 32 * q]);
            agg[2 * q]     += f.x;
            agg[2 * q + 1] += f.y;
        }
    }
    // root row
    float hr[16];
    {
        const uint32_t* rrow = Hh32 + (size_t)row * 256;
#pragma unroll
        for (int q = 0; q < 8; ++q) {
            float2 f = h2f(rrow[lane + 32 * q]);
            hr[2 * q]     = f.x;
            hr[2 * q + 1] = f.y;
        }
    }
    // contract against folded weights
    float res[C_OUT];
#pragma unroll
    for (int c = 0; c < C_OUT; ++c) res[c] = 0.f;
    const float* wrel  = ws;
    const float* wroot = ws + WC2_MAT;
#pragma unroll
    for (int q = 0; q < 8; ++q) {
        int p = lane + 32 * q;
        const float* w0 = wrel  + p * WC2_PITCH;
        const float* w1 = wroot + p * WC2_PITCH;
#pragma unroll
        for (int c = 0; c < C_OUT; ++c) {
            res[c] += agg[2 * q]     * w0[c]
                    + agg[2 * q + 1] * w0[C_OUT + c]
                    + hr[2 * q]      * w1[c]
                    + hr[2 * q + 1]  * w1[C_OUT + c];
        }
    }
#pragma unroll
    for (int off = 16; off > 0; off >>= 1)
#pragma unroll
        for (int c = 0; c < C_OUT; ++c)
            res[c] += __shfl_down_sync(0xFFFFFFFFu, res[c], off);
    if (lane == 0) {
#pragma unroll
        for (int c = 0; c < C_OUT; ++c)
            out[(size_t)row * C_OUT + c] = res[c] + bs[c];
    }
}

// ---------------------------------------------------------------------------
extern "C" void kernel_launch(void* const* d_in, const int* in_sizes, int n_in,
                              void* d_out, int out_size) {
    const float* x     = (const float*)d_in[0];
    const int*   src1  = (const int*)  d_in[1];
    const int*   dst1  = (const int*)  d_in[2];
    const int*   src2  = (const int*)  d_in[3];
    const int*   dst2  = (const int*)  d_in[4];
    const float* Wrel1 = (const float*)d_in[5];
    const float* brel1 = (const float*)d_in[6];
    const float* Wroot1= (const float*)d_in[7];
    const float* Wrel2 = (const float*)d_in[8];
    const float* brel2 = (const float*)d_in[9];
    const float* Wroot2= (const float*)d_in[10];
    const float* Wlin  = (const float*)d_in[11];
    const float* blin  = (const float*)d_in[12];
    const float* Whead = (const float*)d_in[13];
    const float* bhead = (const float*)d_in[14];
    float* out = (float*)d_out;

    float *Wcomb, *bcomb, *Wc2, *bc2;
    __half *Xh, *A1h, *Hh, *Wt;
    int *cnt1, *rp1, *pos1, *esrc1, *cnt2, *rp2, *pos2, *esrc2;
    cudaGetSymbolAddress((void**)&Xh,   g_Xh);
    cudaGetSymbolAddress((void**)&A1h,  g_A1h);
    cudaGetSymbolAddress((void**)&Hh,   g_Hh);
    cudaGetSymbolAddress((void**)&Wt,   g_Wt);
    cudaGetSymbolAddress((void**)&Wcomb, g_Wcomb);
    cudaGetSymbolAddress((void**)&bcomb, g_bcomb);
    cudaGetSymbolAddress((void**)&Wc2,  g_Wc2);
    cudaGetSymbolAddress((void**)&bc2,  g_bc2);
    cudaGetSymbolAddress((void**)&cnt1, g_cnt1);
    cudaGetSymbolAddress((void**)&rp1,  g_rp1);
    cudaGetSymbolAddress((void**)&pos1, g_pos1);
    cudaGetSymbolAddress((void**)&esrc1, g_esrc1);
    cudaGetSymbolAddress((void**)&cnt2, g_cnt2);
    cudaGetSymbolAddress((void**)&rp2,  g_rp2);
    cudaGetSymbolAddress((void**)&pos2, g_pos2);
    cudaGetSymbolAddress((void**)&esrc2, g_esrc2);
    __half* Wrel1T = Wt;
    __half* Wroot1T = Wt + (size_t)2 * FH * FH;

    constexpr int GSMEM = NBUF * 2 * 128 * SA * 2;  // 61440 B
    cudaFuncSetAttribute(gemm1_hi,
                         cudaFuncAttributeMaxDynamicSharedMemorySize, GSMEM);

    const int convA = (NCH_TOTAL * 2) / 5;
    const int convB = convA + (NCH_TOTAL * 3) / 10;

    // ---- launch 1: zero + conv + transposes (rel1, root1) ----
    {
        int zb = (N1 + N2 + 255) / 256;
        int cb = (convA + 255) / 256;
        zero_conv_tr<<<zb + cb + 512, 256>>>(
            cnt1, cnt2, zb, cb, (const float4*)x, (uint4*)Xh, 0, convA,
            Wrel1, Wroot1, Wt);
    }
    // ---- launch 2: hist + conv + wcomb ----
    {
        int hb = (E1 + E2 + 255) / 256;
        int cb = (convB - convA + 255) / 256;
        int wb = (FH + 1 + 7) / 8;
        hist_conv_wc<<<hb + cb + wb, 256>>>(
            dst1, dst2, cnt1, cnt2, hb, cb,
            (const float4*)x, (uint4*)Xh, convA, convB,
            Wlin, Whead, blin, bhead, Wcomb, bcomb);
    }
    scan_both<<<2, 1024>>>(cnt1, rp1, pos1, cnt2, rp2, pos2);
    // ---- launch 3: fill + conv + layer-2 weight fold ----
    {
        int fb = (E1 + E2 + 255) / 256;
        int cb = (NCH_TOTAL - convB + 255) / 256;
        int wb = (2 * FH + 1 + 7) / 8;   // 129 blocks
        fill_conv_wf<<<fb + cb + wb, 256>>>(
            dst1, src1, pos1, esrc1, dst2, src2, pos2, esrc2, fb, cb,
            (const float4*)x, (uint4*)Xh, convB, NCH_TOTAL,
            Wrel2, Wroot2, brel2, Wcomb, bcomb, Wc2, bc2);
    }

    // ---- layer 1 ----
    gather_hi<<<(N1 + GROWS - 1) / GROWS, 256>>>(Xh, esrc1, rp1, N1, A1h);
    {
        dim3 grid(FH / 128, (N1 + 127) / 128);
        gemm1_hi<<<grid, 256, GSMEM>>>(
            A1h, Wrel1T, Xh, Wroot1T, brel1, Hh, N1);
    }

    // ---- fused layer 2 + head ----
    layer2_fused<<<(N2 + 7) / 8, 256>>>(
        (const uint32_t*)Hh, esrc2, rp2, Wc2, bc2, out);

    (void)in_sizes; (void)n_in; (void)out_size;
}